// round 1
// baseline (speedup 1.0000x reference)
#include <cuda_runtime.h>
#include <math.h>

#define T_SEQ   1024
#define D_MODEL 1024
#define NLAYER  4
#define NHEAD   16
#define DHEAD   64
#define FF_DIM  4096
#define VOCAB   32000
#define BT      2048            // B * T
#define ATT_SCALE 0.125f        // DHEAD^-0.5

// ---------------- scratch (device globals; no runtime allocation) ----------
__device__ float g_h   [BT * D_MODEL];
__device__ float g_n   [BT * D_MODEL];
__device__ float g_qkv [BT * 3 * D_MODEL];
__device__ float g_pred[BT * D_MODEL];
__device__ float g_corr[BT * D_MODEL];
__device__ float g_diff[BT * D_MODEL];
__device__ float g_cat [BT * 2 * D_MODEL];
__device__ float g_gate[BT * D_MODEL];
__device__ float g_ff  [BT * FF_DIM];

// ---------------- embedding ------------------------------------------------
__global__ void embed_kernel(const int* __restrict__ x, const float* __restrict__ emb,
                             const float* __restrict__ pos, float* __restrict__ h) {
    int row = blockIdx.x;                 // b*T + t
    int t   = row & (T_SEQ - 1);
    int tok = x[row];
    const float* e = emb + (size_t)tok * D_MODEL;
    const float* p = pos + (size_t)t   * D_MODEL;
    float* o = h + (size_t)row * D_MODEL;
    for (int d = threadIdx.x; d < D_MODEL; d += blockDim.x)
        o[d] = e[d] + p[d];
}

// ---------------- layernorm (one block per row, 256 threads) ---------------
__global__ void ln_kernel(const float* __restrict__ in, const float* __restrict__ g,
                          const float* __restrict__ b, float* __restrict__ out) {
    int row = blockIdx.x;
    const float* x = in + (size_t)row * D_MODEL;
    float* o = out + (size_t)row * D_MODEL;
    int tid = threadIdx.x;
    float s = 0.f, ss = 0.f;
    for (int d = tid; d < D_MODEL; d += 256) { float v = x[d]; s += v; ss += v * v; }
    #pragma unroll
    for (int off = 16; off; off >>= 1) {
        s  += __shfl_xor_sync(0xffffffffu, s,  off);
        ss += __shfl_xor_sync(0xffffffffu, ss, off);
    }
    __shared__ float shs[8], shss[8];
    if ((tid & 31) == 0) { shs[tid >> 5] = s; shss[tid >> 5] = ss; }
    __syncthreads();
    float tots = 0.f, totss = 0.f;
    #pragma unroll
    for (int i = 0; i < 8; i++) { tots += shs[i]; totss += shss[i]; }
    float mean = tots * (1.f / D_MODEL);
    float var  = totss * (1.f / D_MODEL) - mean * mean;
    float rstd = rsqrtf(var + 1e-5f);
    for (int d = tid; d < D_MODEL; d += 256)
        o[d] = (x[d] - mean) * rstd * g[d] + b[d];
}

// ---------------- SGEMM: C[M,N] = A[M,K] @ W[N,K]^T + bias (+ epilogue) ----
// 128x128 tile, BK=8, 256 threads, 8x8 microtile per thread.
// epi: 0 none, 1 add residual, 2 exact gelu, 3 sigmoid
__global__ __launch_bounds__(256, 2) void gemm128(
    const float* __restrict__ A, const float* __restrict__ W,
    const float* __restrict__ bias, const float* __restrict__ res,
    float* __restrict__ C, int M, int N, int K, int epi) {
    __shared__ __align__(16) float As[8][132];
    __shared__ __align__(16) float Ws[8][132];
    int tid = threadIdx.x;
    int bm = blockIdx.y * 128, bn = blockIdx.x * 128;
    int tx = tid & 15, ty = tid >> 4;
    int lrow = tid >> 1, lk = (tid & 1) * 4;
    const float* aptr = A + (size_t)(bm + lrow) * K + lk;
    const float* wptr = W + (size_t)(bn + lrow) * K + lk;
    float acc[8][8];
    #pragma unroll
    for (int i = 0; i < 8; i++)
        #pragma unroll
        for (int j = 0; j < 8; j++) acc[i][j] = 0.f;

    for (int k0 = 0; k0 < K; k0 += 8) {
        float4 av = *(const float4*)(aptr + k0);
        float4 wv = *(const float4*)(wptr + k0);
        __syncthreads();
        As[lk+0][lrow] = av.x; As[lk+1][lrow] = av.y; As[lk+2][lrow] = av.z; As[lk+3][lrow] = av.w;
        Ws[lk+0][lrow] = wv.x; Ws[lk+1][lrow] = wv.y; Ws[lk+2][lrow] = wv.z; Ws[lk+3][lrow] = wv.w;
        __syncthreads();
        #pragma unroll
        for (int k = 0; k < 8; k++) {
            float4 a0 = *(const float4*)&As[k][ty*8];
            float4 a1 = *(const float4*)&As[k][ty*8+4];
            float4 b0 = *(const float4*)&Ws[k][tx*8];
            float4 b1 = *(const float4*)&Ws[k][tx*8+4];
            float a[8]  = {a0.x,a0.y,a0.z,a0.w,a1.x,a1.y,a1.z,a1.w};
            float bb[8] = {b0.x,b0.y,b0.z,b0.w,b1.x,b1.y,b1.z,b1.w};
            #pragma unroll
            for (int i = 0; i < 8; i++)
                #pragma unroll
                for (int j = 0; j < 8; j++)
                    acc[i][j] += a[i] * bb[j];
        }
    }

    #pragma unroll
    for (int i = 0; i < 8; i++) {
        int m = bm + ty*8 + i;
        #pragma unroll
        for (int j = 0; j < 8; j++) {
            int n = bn + tx*8 + j;
            float v = acc[i][j];
            if (bias) v += bias[n];
            if (epi == 1)      v += res[(size_t)m * N + n];
            else if (epi == 2) v = 0.5f * v * (1.f + erff(v * 0.70710678118f));
            else if (epi == 3) v = 1.f / (1.f + __expf(-v));
            C[(size_t)m * N + n] = v;
        }
    }
}

// ---------------- fused causal attention (flash-style) ---------------------
// grid: (T/64, H, B). block: 256 threads. Q tile 64, K/V tile 32.
// qkv layout per token: [3, H, DH] flattened (stride 3072 floats per token).
__global__ __launch_bounds__(256) void attn_kernel(const float* __restrict__ qkv,
                                                   float* __restrict__ out) {
    int qt = blockIdx.x, hh = blockIdx.y, b = blockIdx.z;
    __shared__ __align__(16) float Qs[64][68];
    __shared__ __align__(16) float Ks[32][68];
    __shared__ __align__(16) float Vs[32][68];
    __shared__ float Ps[64][36];
    int tid = threadIdx.x;
    int tx = tid & 15, ty = tid >> 4;
    const float* base = qkv + (size_t)b * T_SEQ * 3072 + hh * 64;

    for (int i = tid; i < 64 * 64; i += 256) {
        int r = i >> 6, d = i & 63;
        Qs[r][d] = base[(size_t)(qt * 64 + r) * 3072 + d];
    }
    float m_i[4], l_i[4], O[4][4];
    #pragma unroll
    for (int i = 0; i < 4; i++) {
        m_i[i] = -1e30f; l_i[i] = 0.f;
        #pragma unroll
        for (int j = 0; j < 4; j++) O[i][j] = 0.f;
    }

    int ntiles = (qt * 64 + 63) / 32 + 1;
    for (int kt = 0; kt < ntiles; kt++) {
        __syncthreads();
        for (int i = tid; i < 32 * 64; i += 256) {
            int r = i >> 6, d = i & 63;
            const float* kb = base + (size_t)(kt * 32 + r) * 3072 + d;
            Ks[r][d] = kb[1024];
            Vs[r][d] = kb[2048];
        }
        __syncthreads();

        float s[4][2];
        #pragma unroll
        for (int i = 0; i < 4; i++) { s[i][0] = 0.f; s[i][1] = 0.f; }
        #pragma unroll
        for (int kk = 0; kk < 64; kk += 4) {
            float4 kv0 = *(const float4*)&Ks[tx*2+0][kk];
            float4 kv1 = *(const float4*)&Ks[tx*2+1][kk];
            #pragma unroll
            for (int i = 0; i < 4; i++) {
                float4 qv = *(const float4*)&Qs[ty*4+i][kk];
                s[i][0] += qv.x*kv0.x + qv.y*kv0.y + qv.z*kv0.z + qv.w*kv0.w;
                s[i][1] += qv.x*kv1.x + qv.y*kv1.y + qv.z*kv1.z + qv.w*kv1.w;
            }
        }

        #pragma unroll
        for (int i = 0; i < 4; i++) {
            int q = qt * 64 + ty * 4 + i;
            float s0 = (kt*32 + tx*2 + 0 <= q) ? s[i][0] * ATT_SCALE : -1e30f;
            float s1 = (kt*32 + tx*2 + 1 <= q) ? s[i][1] * ATT_SCALE : -1e30f;
            float mx = fmaxf(s0, s1);
            #pragma unroll
            for (int off = 8; off; off >>= 1)
                mx = fmaxf(mx, __shfl_xor_sync(0xffffffffu, mx, off));
            float mnew  = fmaxf(m_i[i], mx);
            float alpha = __expf(m_i[i] - mnew);
            float p0 = __expf(s0 - mnew);
            float p1 = __expf(s1 - mnew);
            float psum = p0 + p1;
            #pragma unroll
            for (int off = 8; off; off >>= 1)
                psum += __shfl_xor_sync(0xffffffffu, psum, off);
            l_i[i] = l_i[i] * alpha + psum;
            m_i[i] = mnew;
            #pragma unroll
            for (int j = 0; j < 4; j++) O[i][j] *= alpha;
            Ps[ty*4+i][tx*2+0] = p0;
            Ps[ty*4+i][tx*2+1] = p1;
        }
        __syncthreads();

        #pragma unroll 8
        for (int k = 0; k < 32; k++) {
            float4 vv = *(const float4*)&Vs[k][tx*4];
            #pragma unroll
            for (int i = 0; i < 4; i++) {
                float p = Ps[ty*4+i][k];
                O[i][0] += p * vv.x; O[i][1] += p * vv.y;
                O[i][2] += p * vv.z; O[i][3] += p * vv.w;
            }
        }
    }

    #pragma unroll
    for (int i = 0; i < 4; i++) {
        float inv = 1.f / l_i[i];
        int r = qt * 64 + ty * 4 + i;
        float* op = out + (size_t)(b * T_SEQ + r) * D_MODEL + hh * 64 + tx * 4;
        op[0] = O[i][0]*inv; op[1] = O[i][1]*inv; op[2] = O[i][2]*inv; op[3] = O[i][3]*inv;
    }
}

// ---------------- elementwise helpers --------------------------------------
__global__ void sub_kernel(const float* __restrict__ a, const float* __restrict__ b,
                           float* __restrict__ c, int n) {
    int i = blockIdx.x * blockDim.x + threadIdx.x;
    if (i < n) c[i] = a[i] - b[i];
}
__global__ void combine_kernel(const float* __restrict__ pred, const float* __restrict__ gate,
                               const float* __restrict__ corr, float* __restrict__ o, int n) {
    int i = blockIdx.x * blockDim.x + threadIdx.x;
    if (i < n) o[i] = pred[i] + gate[i] * corr[i];
}
__global__ void cat_kernel(const float* __restrict__ a, const float* __restrict__ b,
                           float* __restrict__ o) {
    int i = blockIdx.x * blockDim.x + threadIdx.x;
    if (i < BT * 2 * D_MODEL) {
        int m = i >> 11, n = i & 2047;
        o[i] = (n < D_MODEL) ? a[m * D_MODEL + n] : b[m * D_MODEL + (n - D_MODEL)];
    }
}

// ---------------- driver ----------------------------------------------------
extern "C" void kernel_launch(void* const* d_in, const int* in_sizes, int n_in,
                              void* d_out, int out_size) {
    const int*   x      = (const int*)  d_in[0];
    const float* embed  = (const float*)d_in[1];
    const float* pos    = (const float*)d_in[2];
    const float* Wqkv   = (const float*)d_in[3];
    const float* bqkv   = (const float*)d_in[4];
    const float* Wo     = (const float*)d_in[5];
    const float* bo     = (const float*)d_in[6];
    const float* Wg     = (const float*)d_in[7];
    const float* bg     = (const float*)d_in[8];
    const float* ln1_g  = (const float*)d_in[9];
    const float* ln1_b  = (const float*)d_in[10];
    const float* W1     = (const float*)d_in[11];
    const float* b1     = (const float*)d_in[12];
    const float* W2     = (const float*)d_in[13];
    const float* b2     = (const float*)d_in[14];
    const float* ln2_g  = (const float*)d_in[15];
    const float* ln2_b  = (const float*)d_in[16];
    const float* lnf_g  = (const float*)d_in[17];
    const float* lnf_b  = (const float*)d_in[18];
    float* out = (float*)d_out;

    float *h, *n, *qkv, *pred, *corr, *diff, *cat, *gate, *ff;
    cudaGetSymbolAddress((void**)&h,    g_h);
    cudaGetSymbolAddress((void**)&n,    g_n);
    cudaGetSymbolAddress((void**)&qkv,  g_qkv);
    cudaGetSymbolAddress((void**)&pred, g_pred);
    cudaGetSymbolAddress((void**)&corr, g_corr);
    cudaGetSymbolAddress((void**)&diff, g_diff);
    cudaGetSymbolAddress((void**)&cat,  g_cat);
    cudaGetSymbolAddress((void**)&gate, g_gate);
    cudaGetSymbolAddress((void**)&ff,   g_ff);

    const int NE = BT * D_MODEL;                 // 2,097,152
    dim3 ew((NE + 255) / 256), ewb(256);
    dim3 ew2((BT * 2 * D_MODEL + 255) / 256);
    dim3 agrid(T_SEQ / 64, NHEAD, 2);

    embed_kernel<<<BT, 256>>>(x, embed, pos, h);

    for (int l = 0; l < NLAYER; l++) {
        // n1 = ln(h)
        ln_kernel<<<BT, 256>>>(h, ln1_g + l * D_MODEL, ln1_b + l * D_MODEL, n);
        // attend #1 -> pred
        gemm128<<<dim3(3072/128, BT/128), 256>>>(n, Wqkv + (size_t)(l*2+0)*3072*D_MODEL,
                                                 bqkv + (l*2+0)*3072, nullptr, qkv,
                                                 BT, 3072, D_MODEL, 0);
        attn_kernel<<<agrid, 256>>>(qkv, pred);
        // attend #2 on (n1 - pred) -> corr
        sub_kernel<<<ew, ewb>>>(n, pred, diff, NE);
        gemm128<<<dim3(3072/128, BT/128), 256>>>(diff, Wqkv + (size_t)(l*2+1)*3072*D_MODEL,
                                                 bqkv + (l*2+1)*3072, nullptr, qkv,
                                                 BT, 3072, D_MODEL, 0);
        attn_kernel<<<agrid, 256>>>(qkv, corr);
        // gate = sigmoid([pred|corr] @ Wg^T + bg)
        cat_kernel<<<ew2, ewb>>>(pred, corr, cat);
        gemm128<<<dim3(D_MODEL/128, BT/128), 256>>>(cat, Wg + (size_t)l*D_MODEL*2*D_MODEL,
                                                    bg + l*D_MODEL, nullptr, gate,
                                                    BT, D_MODEL, 2*D_MODEL, 3);
        // out = pred + gate*corr ; h += out @ Wo^T + bo
        combine_kernel<<<ew, ewb>>>(pred, gate, corr, diff, NE);
        gemm128<<<dim3(D_MODEL/128, BT/128), 256>>>(diff, Wo + (size_t)l*D_MODEL*D_MODEL,
                                                    bo + l*D_MODEL, h, h,
                                                    BT, D_MODEL, D_MODEL, 1);
        // FF block
        ln_kernel<<<BT, 256>>>(h, ln2_g + l * D_MODEL, ln2_b + l * D_MODEL, n);
        gemm128<<<dim3(FF_DIM/128, BT/128), 256>>>(n, W1 + (size_t)l*FF_DIM*D_MODEL,
                                                   b1 + l*FF_DIM, nullptr, ff,
                                                   BT, FF_DIM, D_MODEL, 2);
        gemm128<<<dim3(D_MODEL/128, BT/128), 256>>>(ff, W2 + (size_t)l*D_MODEL*FF_DIM,
                                                    b2 + l*D_MODEL, h, h,
                                                    BT, D_MODEL, FF_DIM, 1);
    }

    // logits = ln(h) @ embed^T
    ln_kernel<<<BT, 256>>>(h, lnf_g, lnf_b, n);
    gemm128<<<dim3(VOCAB/128, BT/128), 256>>>(n, embed, nullptr, nullptr, out,
                                              BT, VOCAB, D_MODEL, 0);
}

// round 3
// speedup vs baseline: 1.8985x; 1.8985x over previous
#include <cuda_runtime.h>
#include <cuda_bf16.h>
#include <stdint.h>
#include <math.h>

#define T_SEQ   1024
#define D_MODEL 1024
#define NLAYER  4
#define FF_DIM  4096
#define VOCAB   32000
#define BT      2048
#define ATT_SCALE 0.125f

// ---------------- fp32 scratch ----------------------------------------------
__device__ float g_h   [BT * D_MODEL];
__device__ float g_n   [BT * D_MODEL];
__device__ float g_qkv [BT * 3 * D_MODEL];
__device__ float g_pred[BT * D_MODEL];
__device__ float g_corr[BT * D_MODEL];
__device__ float g_gate[BT * D_MODEL];

// ---------------- bf16 hi/lo activation scratch -----------------------------
__device__ __align__(16) __nv_bfloat16 g_ah[BT * FF_DIM];
__device__ __align__(16) __nv_bfloat16 g_al[BT * FF_DIM];
__device__ __align__(16) __nv_bfloat16 g_fh[BT * FF_DIM];
__device__ __align__(16) __nv_bfloat16 g_fl[BT * FF_DIM];

// ---------------- bf16 hi/lo weights ----------------------------------------
#define SZ_WQKV (NLAYER * 2 * 3 * D_MODEL * D_MODEL)
#define SZ_WO   (NLAYER * D_MODEL * D_MODEL)
#define SZ_WG   (NLAYER * D_MODEL * 2 * D_MODEL)
#define SZ_W1   (NLAYER * FF_DIM * D_MODEL)
#define SZ_W2   (NLAYER * D_MODEL * FF_DIM)
#define SZ_EMB  (VOCAB * D_MODEL)
__device__ __align__(16) __nv_bfloat16 g_wqkv_h[SZ_WQKV], g_wqkv_l[SZ_WQKV];
__device__ __align__(16) __nv_bfloat16 g_wo_h  [SZ_WO],   g_wo_l  [SZ_WO];
__device__ __align__(16) __nv_bfloat16 g_wg_h  [SZ_WG],   g_wg_l  [SZ_WG];
__device__ __align__(16) __nv_bfloat16 g_w1_h  [SZ_W1],   g_w1_l  [SZ_W1];
__device__ __align__(16) __nv_bfloat16 g_w2_h  [SZ_W2],   g_w2_l  [SZ_W2];
__device__ __align__(16) __nv_bfloat16 g_emb_h [SZ_EMB],  g_emb_l [SZ_EMB];

// ---------------- helpers ----------------------------------------------------
__device__ __forceinline__ void splt(float x, __nv_bfloat16& h, __nv_bfloat16& l) {
    h = __float2bfloat16_rn(x);
    l = __float2bfloat16_rn(x - __bfloat162float(h));
}
__device__ __forceinline__ uint32_t smem_u32(const void* p) {
    uint32_t a;
    asm("{ .reg .u64 t; cvta.to.shared.u64 t, %1; cvt.u32.u64 %0, t; }" : "=r"(a) : "l"(p));
    return a;
}
__device__ __forceinline__ void cp16(uint32_t s, const void* g) {
    asm volatile("cp.async.cg.shared.global [%0], [%1], 16;" :: "r"(s), "l"(g));
}
#define CP_COMMIT() asm volatile("cp.async.commit_group;" ::: "memory")
#define CP_WAIT1()  asm volatile("cp.async.wait_group 1;" ::: "memory")

__device__ __forceinline__ void ldmx4(uint32_t a, uint32_t& r0, uint32_t& r1,
                                      uint32_t& r2, uint32_t& r3) {
    asm volatile("ldmatrix.sync.aligned.m8n8.x4.shared.b16 {%0,%1,%2,%3}, [%4];"
                 : "=r"(r0), "=r"(r1), "=r"(r2), "=r"(r3) : "r"(a));
}
__device__ __forceinline__ void mma16816(float* d, const uint32_t* a, const uint32_t* b) {
    asm volatile("mma.sync.aligned.m16n8k16.row.col.f32.bf16.bf16.f32 "
                 "{%0,%1,%2,%3}, {%4,%5,%6,%7}, {%8,%9}, {%0,%1,%2,%3};"
                 : "+f"(d[0]), "+f"(d[1]), "+f"(d[2]), "+f"(d[3])
                 : "r"(a[0]), "r"(a[1]), "r"(a[2]), "r"(a[3]), "r"(b[0]), "r"(b[1]));
}

// ---------------- weight split kernel ---------------------------------------
__global__ void split_kernel(const float4* __restrict__ in, uint2* __restrict__ hi,
                             uint2* __restrict__ lo, int n4) {
    int i = blockIdx.x * blockDim.x + threadIdx.x;
    if (i >= n4) return;
    float4 v = in[i];
    __nv_bfloat16 h0, h1, h2, h3, l0, l1, l2, l3;
    splt(v.x, h0, l0); splt(v.y, h1, l1); splt(v.z, h2, l2); splt(v.w, h3, l3);
    uint2 H, L;
    H.x = (uint32_t)__bfloat16_as_ushort(h0) | ((uint32_t)__bfloat16_as_ushort(h1) << 16);
    H.y = (uint32_t)__bfloat16_as_ushort(h2) | ((uint32_t)__bfloat16_as_ushort(h3) << 16);
    L.x = (uint32_t)__bfloat16_as_ushort(l0) | ((uint32_t)__bfloat16_as_ushort(l1) << 16);
    L.y = (uint32_t)__bfloat16_as_ushort(l2) | ((uint32_t)__bfloat16_as_ushort(l3) << 16);
    hi[i] = H; lo[i] = L;
}

// ---------------- GEMM: C[M,N] = A[M,K] @ W[N,K]^T (bf16 3-mma split) -------
#define KC    32
#define SROW  80
#define AOFF_H 0
#define AOFF_L 10240
#define BOFF_H 20480
#define BOFF_L 30720
#define STG   40960
#define GSMEM (2 * STG)

__global__ __launch_bounds__(256, 1) void gemm_tc(
    const __nv_bfloat16* __restrict__ Ah, const __nv_bfloat16* __restrict__ Al,
    const __nv_bfloat16* __restrict__ Wh, const __nv_bfloat16* __restrict__ Wl,
    const float* __restrict__ bias, const float* __restrict__ res,
    float* __restrict__ Cf, __nv_bfloat16* __restrict__ Ch, __nv_bfloat16* __restrict__ Cl,
    int M, int N, int K, int epi)
{
    extern __shared__ char smem[];
    uint32_t sb = smem_u32(smem);
    int tid = threadIdx.x, lane = tid & 31, w = tid >> 5;
    int wm = w & 3, wn = w >> 2;
    int bm = blockIdx.y * 128, bn = blockIdx.x * 128;

    const __nv_bfloat16* pAh = Ah + (size_t)bm * K;
    const __nv_bfloat16* pAl = Al + (size_t)bm * K;
    const __nv_bfloat16* pWh = Wh + (size_t)bn * K;
    const __nv_bfloat16* pWl = Wl + (size_t)bn * K;

    int lrow = tid >> 1;
    int lc   = (tid & 1) * 2;

    float acc[2][8][4];
    #pragma unroll
    for (int i = 0; i < 2; i++)
        #pragma unroll
        for (int j = 0; j < 8; j++)
            #pragma unroll
            for (int e = 0; e < 4; e++) acc[i][j][e] = 0.f;

    int nk = K / KC;

    {
        uint32_t s = sb;
        size_t go = (size_t)lrow * K + lc * 8;
        uint32_t so = lrow * SROW + lc * 16;
        cp16(s + AOFF_H + so, pAh + go); cp16(s + AOFF_H + so + 16, pAh + go + 8);
        cp16(s + AOFF_L + so, pAl + go); cp16(s + AOFF_L + so + 16, pAl + go + 8);
        cp16(s + BOFF_H + so, pWh + go); cp16(s + BOFF_H + so + 16, pWh + go + 8);
        cp16(s + BOFF_L + so, pWl + go); cp16(s + BOFF_L + so + 16, pWl + go + 8);
    }
    CP_COMMIT();

    for (int kc = 0; kc < nk; kc++) {
        if (kc + 1 < nk) {
            uint32_t s = sb + ((kc + 1) & 1) * STG;
            size_t go = (size_t)lrow * K + (kc + 1) * KC + lc * 8;
            uint32_t so = lrow * SROW + lc * 16;
            cp16(s + AOFF_H + so, pAh + go); cp16(s + AOFF_H + so + 16, pAh + go + 8);
            cp16(s + AOFF_L + so, pAl + go); cp16(s + AOFF_L + so + 16, pAl + go + 8);
            cp16(s + BOFF_H + so, pWh + go); cp16(s + BOFF_H + so + 16, pWh + go + 8);
            cp16(s + BOFF_L + so, pWl + go); cp16(s + BOFF_L + so + 16, pWl + go + 8);
        }
        CP_COMMIT();
        CP_WAIT1();
        __syncthreads();

        uint32_t s = sb + (kc & 1) * STG;
        #pragma unroll
        for (int k16 = 0; k16 < 2; k16++) {
            uint32_t bh[4][4], bl[4][4];
            uint32_t brow = wn * 64 + (lane & 7) + ((lane >> 4) << 3);
            uint32_t bk   = k16 * 16 + ((lane >> 3) & 1) * 8;
            #pragma unroll
            for (int ng = 0; ng < 4; ng++) {
                uint32_t off = (brow + ng * 16) * SROW + bk * 2;
                ldmx4(s + BOFF_H + off, bh[ng][0], bh[ng][1], bh[ng][2], bh[ng][3]);
                ldmx4(s + BOFF_L + off, bl[ng][0], bl[ng][1], bl[ng][2], bl[ng][3]);
            }
            uint32_t arow = wm * 32 + (lane & 15);
            uint32_t ak   = k16 * 16 + ((lane >> 4) << 3);
            #pragma unroll
            for (int mg = 0; mg < 2; mg++) {
                uint32_t aoff = (arow + mg * 16) * SROW + ak * 2;
                uint32_t ahr[4], alr[4];
                ldmx4(s + AOFF_H + aoff, ahr[0], ahr[1], ahr[2], ahr[3]);
                ldmx4(s + AOFF_L + aoff, alr[0], alr[1], alr[2], alr[3]);
                #pragma unroll
                for (int ng = 0; ng < 4; ng++) {
                    mma16816(acc[mg][ng*2+0], ahr, &bh[ng][0]);
                    mma16816(acc[mg][ng*2+1], ahr, &bh[ng][2]);
                    mma16816(acc[mg][ng*2+0], ahr, &bl[ng][0]);
                    mma16816(acc[mg][ng*2+1], ahr, &bl[ng][2]);
                    mma16816(acc[mg][ng*2+0], alr, &bh[ng][0]);
                    mma16816(acc[mg][ng*2+1], alr, &bh[ng][2]);
                }
            }
        }
        __syncthreads();
    }

    #pragma unroll
    for (int mg = 0; mg < 2; mg++) {
        #pragma unroll
        for (int j = 0; j < 8; j++) {
            int m0 = bm + wm * 32 + mg * 16 + (lane >> 2);
            int n0 = bn + wn * 64 + j * 8 + (lane & 3) * 2;
            #pragma unroll
            for (int e = 0; e < 4; e++) {
                int m = m0 + (e >> 1) * 8;
                int n = n0 + (e & 1);
                float v = acc[mg][j][e];
                if (bias) v += bias[n];
                if (epi == 1)      v += res[(size_t)m * N + n];
                else if (epi == 2) v = 0.5f * v * (1.f + erff(v * 0.70710678118f));
                else if (epi == 3) v = 1.f / (1.f + __expf(-v));
                if (Cf) Cf[(size_t)m * N + n] = v;
                if (Ch) {
                    __nv_bfloat16 hh, ll;
                    splt(v, hh, ll);
                    Ch[(size_t)m * N + n] = hh;
                    Cl[(size_t)m * N + n] = ll;
                }
            }
        }
    }
}

// ---------------- embedding ------------------------------------------------
__global__ void embed_kernel(const int* __restrict__ x, const float* __restrict__ emb,
                             const float* __restrict__ pos, float* __restrict__ h) {
    int row = blockIdx.x;
    int t   = row & (T_SEQ - 1);
    int tok = x[row];
    const float* e = emb + (size_t)tok * D_MODEL;
    const float* p = pos + (size_t)t   * D_MODEL;
    float* o = h + (size_t)row * D_MODEL;
    for (int d = threadIdx.x; d < D_MODEL; d += blockDim.x)
        o[d] = e[d] + p[d];
}

// ---------------- layernorm -------------------------------------------------
__global__ void ln_kernel(const float* __restrict__ in, const float* __restrict__ g,
                          const float* __restrict__ b, float* __restrict__ of,
                          __nv_bfloat16* __restrict__ oh, __nv_bfloat16* __restrict__ ol) {
    int row = blockIdx.x;
    const float* x = in + (size_t)row * D_MODEL;
    int tid = threadIdx.x;
    float s = 0.f, ss = 0.f;
    for (int d = tid; d < D_MODEL; d += 256) { float v = x[d]; s += v; ss += v * v; }
    #pragma unroll
    for (int off = 16; off; off >>= 1) {
        s  += __shfl_xor_sync(0xffffffffu, s,  off);
        ss += __shfl_xor_sync(0xffffffffu, ss, off);
    }
    __shared__ float shs[8], shss[8];
    if ((tid & 31) == 0) { shs[tid >> 5] = s; shss[tid >> 5] = ss; }
    __syncthreads();
    float tots = 0.f, totss = 0.f;
    #pragma unroll
    for (int i = 0; i < 8; i++) { tots += shs[i]; totss += shss[i]; }
    float mean = tots * (1.f / D_MODEL);
    float var  = totss * (1.f / D_MODEL) - mean * mean;
    float rstd = rsqrtf(var + 1e-5f);
    for (int d = tid; d < D_MODEL; d += 256) {
        float v = (x[d] - mean) * rstd * g[d] + b[d];
        size_t idx = (size_t)row * D_MODEL + d;
        if (of) of[idx] = v;
        if (oh) { __nv_bfloat16 hh, ll; splt(v, hh, ll); oh[idx] = hh; ol[idx] = ll; }
    }
}

// ---------------- fused causal attention (fp32 flash) ----------------------
__global__ __launch_bounds__(256) void attn_kernel(const float* __restrict__ qkv,
                                                   float* __restrict__ out) {
    int qt = blockIdx.x, hh = blockIdx.y, b = blockIdx.z;
    __shared__ __align__(16) float Qs[64][68];
    __shared__ __align__(16) float Ks[32][68];
    __shared__ __align__(16) float Vs[32][68];
    __shared__ float Ps[64][36];
    int tid = threadIdx.x;
    int tx = tid & 15, ty = tid >> 4;
    const float* base = qkv + (size_t)b * T_SEQ * 3072 + hh * 64;

    for (int i = tid; i < 64 * 64; i += 256) {
        int r = i >> 6, d = i & 63;
        Qs[r][d] = base[(size_t)(qt * 64 + r) * 3072 + d];
    }
    float m_i[4], l_i[4], O[4][4];
    #pragma unroll
    for (int i = 0; i < 4; i++) {
        m_i[i] = -1e30f; l_i[i] = 0.f;
        #pragma unroll
        for (int j = 0; j < 4; j++) O[i][j] = 0.f;
    }

    int ntiles = (qt * 64 + 63) / 32 + 1;
    for (int kt = 0; kt < ntiles; kt++) {
        __syncthreads();
        for (int i = tid; i < 32 * 64; i += 256) {
            int r = i >> 6, d = i & 63;
            const float* kb = base + (size_t)(kt * 32 + r) * 3072 + d;
            Ks[r][d] = kb[1024];
            Vs[r][d] = kb[2048];
        }
        __syncthreads();

        float s[4][2];
        #pragma unroll
        for (int i = 0; i < 4; i++) { s[i][0] = 0.f; s[i][1] = 0.f; }
        #pragma unroll
        for (int kk = 0; kk < 64; kk += 4) {
            float4 kv0 = *(const float4*)&Ks[tx*2+0][kk];
            float4 kv1 = *(const float4*)&Ks[tx*2+1][kk];
            #pragma unroll
            for (int i = 0; i < 4; i++) {
                float4 qv = *(const float4*)&Qs[ty*4+i][kk];
                s[i][0] += qv.x*kv0.x + qv.y*kv0.y + qv.z*kv0.z + qv.w*kv0.w;
                s[i][1] += qv.x*kv1.x + qv.y*kv1.y + qv.z*kv1.z + qv.w*kv1.w;
            }
        }

        #pragma unroll
        for (int i = 0; i < 4; i++) {
            int q = qt * 64 + ty * 4 + i;
            float s0 = (kt*32 + tx*2 + 0 <= q) ? s[i][0] * ATT_SCALE : -1e30f;
            float s1 = (kt*32 + tx*2 + 1 <= q) ? s[i][1] * ATT_SCALE : -1e30f;
            float mx = fmaxf(s0, s1);
            #pragma unroll
            for (int off = 8; off; off >>= 1)
                mx = fmaxf(mx, __shfl_xor_sync(0xffffffffu, mx, off));
            float mnew  = fmaxf(m_i[i], mx);
            float alpha = __expf(m_i[i] - mnew);
            float p0 = __expf(s0 - mnew);
            float p1 = __expf(s1 - mnew);
            float psum = p0 + p1;
            #pragma unroll
            for (int off = 8; off; off >>= 1)
                psum += __shfl_xor_sync(0xffffffffu, psum, off);
            l_i[i] = l_i[i] * alpha + psum;
            m_i[i] = mnew;
            #pragma unroll
            for (int j = 0; j < 4; j++) O[i][j] *= alpha;
            Ps[ty*4+i][tx*2+0] = p0;
            Ps[ty*4+i][tx*2+1] = p1;
        }
        __syncthreads();

        #pragma unroll 8
        for (int k = 0; k < 32; k++) {
            float4 vv = *(const float4*)&Vs[k][tx*4];
            #pragma unroll
            for (int i = 0; i < 4; i++) {
                float p = Ps[ty*4+i][k];
                O[i][0] += p * vv.x; O[i][1] += p * vv.y;
                O[i][2] += p * vv.z; O[i][3] += p * vv.w;
            }
        }
    }

    #pragma unroll
    for (int i = 0; i < 4; i++) {
        float inv = 1.f / l_i[i];
        int r = qt * 64 + ty * 4 + i;
        float* op = out + (size_t)(b * T_SEQ + r) * D_MODEL + hh * 64 + tx * 4;
        op[0] = O[i][0]*inv; op[1] = O[i][1]*inv; op[2] = O[i][2]*inv; op[3] = O[i][3]*inv;
    }
}

// ---------------- elementwise (bf16 hi/lo outputs) --------------------------
__global__ void sub_kernel(const float* __restrict__ a, const float* __restrict__ b,
                           __nv_bfloat16* __restrict__ oh, __nv_bfloat16* __restrict__ ol, int n) {
    int i = blockIdx.x * blockDim.x + threadIdx.x;
    if (i < n) { __nv_bfloat16 hh, ll; splt(a[i] - b[i], hh, ll); oh[i] = hh; ol[i] = ll; }
}
__global__ void combine_kernel(const float* __restrict__ pred, const float* __restrict__ gate,
                               const float* __restrict__ corr,
                               __nv_bfloat16* __restrict__ oh, __nv_bfloat16* __restrict__ ol, int n) {
    int i = blockIdx.x * blockDim.x + threadIdx.x;
    if (i < n) { __nv_bfloat16 hh, ll; splt(pred[i] + gate[i] * corr[i], hh, ll); oh[i] = hh; ol[i] = ll; }
}
__global__ void cat_kernel(const float* __restrict__ a, const float* __restrict__ b,
                           __nv_bfloat16* __restrict__ oh, __nv_bfloat16* __restrict__ ol) {
    int i = blockIdx.x * blockDim.x + threadIdx.x;
    if (i < BT * 2 * D_MODEL) {
        int m = i >> 11, n = i & 2047;
        float v = (n < D_MODEL) ? a[m * D_MODEL + n] : b[m * D_MODEL + (n - D_MODEL)];
        __nv_bfloat16 hh, ll; splt(v, hh, ll); oh[i] = hh; ol[i] = ll;
    }
}

// ---------------- driver ----------------------------------------------------
extern "C" void kernel_launch(void* const* d_in, const int* in_sizes, int n_in,
                              void* d_out, int out_size) {
    const int*   x      = (const int*)  d_in[0];
    const float* embed  = (const float*)d_in[1];
    const float* pos    = (const float*)d_in[2];
    const float* Wqkv   = (const float*)d_in[3];
    const float* bqkv   = (const float*)d_in[4];
    const float* Wo     = (const float*)d_in[5];
    const float* bo     = (const float*)d_in[6];
    const float* Wg     = (const float*)d_in[7];
    const float* bg     = (const float*)d_in[8];
    const float* ln1_g  = (const float*)d_in[9];
    const float* ln1_b  = (const float*)d_in[10];
    const float* W1     = (const float*)d_in[11];
    const float* b1     = (const float*)d_in[12];
    const float* W2     = (const float*)d_in[13];
    const float* b2     = (const float*)d_in[14];
    const float* ln2_g  = (const float*)d_in[15];
    const float* ln2_b  = (const float*)d_in[16];
    const float* lnf_g  = (const float*)d_in[17];
    const float* lnf_b  = (const float*)d_in[18];
    float* out = (float*)d_out;

    cudaFuncSetAttribute(gemm_tc, cudaFuncAttributeMaxDynamicSharedMemorySize, GSMEM);

    float *h, *n, *qkv, *pred, *corr, *gate;
    cudaGetSymbolAddress((void**)&h,    g_h);
    cudaGetSymbolAddress((void**)&n,    g_n);
    cudaGetSymbolAddress((void**)&qkv,  g_qkv);
    cudaGetSymbolAddress((void**)&pred, g_pred);
    cudaGetSymbolAddress((void**)&corr, g_corr);
    cudaGetSymbolAddress((void**)&gate, g_gate);
    __nv_bfloat16 *ah, *al, *fh, *fl;
    cudaGetSymbolAddress((void**)&ah, g_ah);
    cudaGetSymbolAddress((void**)&al, g_al);
    cudaGetSymbolAddress((void**)&fh, g_fh);
    cudaGetSymbolAddress((void**)&fl, g_fl);
    __nv_bfloat16 *wqkv_h, *wqkv_l, *wo_h, *wo_l, *wg_h, *wg_l, *w1_h, *w1_l, *w2_h, *w2_l, *emb_h, *emb_l;
    cudaGetSymbolAddress((void**)&wqkv_h, g_wqkv_h); cudaGetSymbolAddress((void**)&wqkv_l, g_wqkv_l);
    cudaGetSymbolAddress((void**)&wo_h,   g_wo_h);   cudaGetSymbolAddress((void**)&wo_l,   g_wo_l);
    cudaGetSymbolAddress((void**)&wg_h,   g_wg_h);   cudaGetSymbolAddress((void**)&wg_l,   g_wg_l);
    cudaGetSymbolAddress((void**)&w1_h,   g_w1_h);   cudaGetSymbolAddress((void**)&w1_l,   g_w1_l);
    cudaGetSymbolAddress((void**)&w2_h,   g_w2_h);   cudaGetSymbolAddress((void**)&w2_l,   g_w2_l);
    cudaGetSymbolAddress((void**)&emb_h,  g_emb_h);  cudaGetSymbolAddress((void**)&emb_l,  g_emb_l);

    {   // weight splits
        int n4;
        n4 = SZ_WQKV/4; split_kernel<<<(n4+255)/256, 256>>>((const float4*)Wqkv,  (uint2*)wqkv_h, (uint2*)wqkv_l, n4);
        n4 = SZ_WO/4;   split_kernel<<<(n4+255)/256, 256>>>((const float4*)Wo,    (uint2*)wo_h,   (uint2*)wo_l,   n4);
        n4 = SZ_WG/4;   split_kernel<<<(n4+255)/256, 256>>>((const float4*)Wg,    (uint2*)wg_h,   (uint2*)wg_l,   n4);
        n4 = SZ_W1/4;   split_kernel<<<(n4+255)/256, 256>>>((const float4*)W1,    (uint2*)w1_h,   (uint2*)w1_l,   n4);
        n4 = SZ_W2/4;   split_kernel<<<(n4+255)/256, 256>>>((const float4*)W2,    (uint2*)w2_h,   (uint2*)w2_l,   n4);
        n4 = SZ_EMB/4;  split_kernel<<<(n4+255)/256, 256>>>((const float4*)embed, (uint2*)emb_h,  (uint2*)emb_l,  n4);
    }

    const int NE = BT * D_MODEL;
    dim3 ew((NE + 255) / 256), ewb(256);
    dim3 ew2((BT * 2 * D_MODEL + 255) / 256);
    dim3 attng(T_SEQ / 64, 16, 2);

    embed_kernel<<<BT, 256>>>(x, embed, pos, h);

    for (int l = 0; l < NLAYER; l++) {
        ln_kernel<<<BT, 256>>>(h, ln1_g + l * D_MODEL, ln1_b + l * D_MODEL, n, ah, al);
        gemm_tc<<<dim3(3072/128, BT/128), 256, GSMEM>>>(
            ah, al, wqkv_h + (size_t)(l*2+0)*3072*D_MODEL, wqkv_l + (size_t)(l*2+0)*3072*D_MODEL,
            bqkv + (l*2+0)*3072, nullptr, qkv, nullptr, nullptr, BT, 3072, D_MODEL, 0);
        attn_kernel<<<attng, 256>>>(qkv, pred);
        sub_kernel<<<ew, ewb>>>(n, pred, ah, al, NE);
        gemm_tc<<<dim3(3072/128, BT/128), 256, GSMEM>>>(
            ah, al, wqkv_h + (size_t)(l*2+1)*3072*D_MODEL, wqkv_l + (size_t)(l*2+1)*3072*D_MODEL,
            bqkv + (l*2+1)*3072, nullptr, qkv, nullptr, nullptr, BT, 3072, D_MODEL, 0);
        attn_kernel<<<attng, 256>>>(qkv, corr);
        cat_kernel<<<ew2, ewb>>>(pred, corr, ah, al);
        gemm_tc<<<dim3(D_MODEL/128, BT/128), 256, GSMEM>>>(
            ah, al, wg_h + (size_t)l*D_MODEL*2*D_MODEL, wg_l + (size_t)l*D_MODEL*2*D_MODEL,
            bg + l*D_MODEL, nullptr, gate, nullptr, nullptr, BT, D_MODEL, 2*D_MODEL, 3);
        combine_kernel<<<ew, ewb>>>(pred, gate, corr, ah, al, NE);
        gemm_tc<<<dim3(D_MODEL/128, BT/128), 256, GSMEM>>>(
            ah, al, wo_h + (size_t)l*D_MODEL*D_MODEL, wo_l + (size_t)l*D_MODEL*D_MODEL,
            bo + l*D_MODEL, h, h, nullptr, nullptr, BT, D_MODEL, D_MODEL, 1);
        ln_kernel<<<BT, 256>>>(h, ln2_g + l * D_MODEL, ln2_b + l * D_MODEL, nullptr, ah, al);
        gemm_tc<<<dim3(FF_DIM/128, BT/128), 256, GSMEM>>>(
            ah, al, w1_h + (size_t)l*FF_DIM*D_MODEL, w1_l + (size_t)l*FF_DIM*D_MODEL,
            b1 + l*FF_DIM, nullptr, nullptr, fh, fl, BT, FF_DIM, D_MODEL, 2);
        gemm_tc<<<dim3(D_MODEL/128, BT/128), 256, GSMEM>>>(
            fh, fl, w2_h + (size_t)l*D_MODEL*FF_DIM, w2_l + (size_t)l*D_MODEL*FF_DIM,
            b2 + l*D_MODEL, h, h, nullptr, nullptr, BT, D_MODEL, FF_DIM, 1);
    }

    ln_kernel<<<BT, 256>>>(h, lnf_g, lnf_b, nullptr, ah, al);
    gemm_tc<<<dim3(VOCAB/128, BT/128), 256, GSMEM>>>(
        ah, al, emb_h, emb_l, nullptr, nullptr, out, nullptr, nullptr, BT, VOCAB, D_MODEL, 0);
}

// round 4
// speedup vs baseline: 2.0669x; 1.0887x over previous
#include <cuda_runtime.h>
#include <cuda_bf16.h>
#include <stdint.h>
#include <math.h>

#define T_SEQ   1024
#define D_MODEL 1024
#define NLAYER  4
#define FF_DIM  4096
#define VOCAB   32000
#define BT      2048
#define ATT_SCALE 0.125f

// ---------------- fp32 scratch ----------------------------------------------
__device__ float g_h   [BT * D_MODEL];
__device__ float g_n   [BT * D_MODEL];
__device__ float g_qkv [BT * 3 * D_MODEL];
__device__ float g_pred[BT * D_MODEL];
__device__ float g_corr[BT * D_MODEL];

// ---------------- bf16 hi/lo activation scratch -----------------------------
__device__ __align__(16) __nv_bfloat16 g_ah[BT * FF_DIM];
__device__ __align__(16) __nv_bfloat16 g_al[BT * FF_DIM];
__device__ __align__(16) __nv_bfloat16 g_fh[BT * FF_DIM];
__device__ __align__(16) __nv_bfloat16 g_fl[BT * FF_DIM];
__device__ __align__(16) __nv_bfloat16 g_ph[BT * D_MODEL], g_pl[BT * D_MODEL];
__device__ __align__(16) __nv_bfloat16 g_ch[BT * D_MODEL], g_cl[BT * D_MODEL];

// ---------------- bf16 hi/lo weights ----------------------------------------
#define SZ_WQKV (NLAYER * 2 * 3 * D_MODEL * D_MODEL)
#define SZ_WO   (NLAYER * D_MODEL * D_MODEL)
#define SZ_WG   (NLAYER * D_MODEL * 2 * D_MODEL)
#define SZ_W1   (NLAYER * FF_DIM * D_MODEL)
#define SZ_W2   (NLAYER * D_MODEL * FF_DIM)
#define SZ_EMB  (VOCAB * D_MODEL)
__device__ __align__(16) __nv_bfloat16 g_wqkv_h[SZ_WQKV], g_wqkv_l[SZ_WQKV];
__device__ __align__(16) __nv_bfloat16 g_wo_h  [SZ_WO],   g_wo_l  [SZ_WO];
__device__ __align__(16) __nv_bfloat16 g_wg_h  [SZ_WG],   g_wg_l  [SZ_WG];
__device__ __align__(16) __nv_bfloat16 g_w1_h  [SZ_W1],   g_w1_l  [SZ_W1];
__device__ __align__(16) __nv_bfloat16 g_w2_h  [SZ_W2],   g_w2_l  [SZ_W2];
__device__ __align__(16) __nv_bfloat16 g_emb_h [SZ_EMB],  g_emb_l [SZ_EMB];

// ---------------- helpers ----------------------------------------------------
__device__ __forceinline__ void splt(float x, __nv_bfloat16& h, __nv_bfloat16& l) {
    h = __float2bfloat16_rn(x);
    l = __float2bfloat16_rn(x - __bfloat162float(h));
}
__device__ __forceinline__ uint32_t smem_u32(const void* p) {
    uint32_t a;
    asm("{ .reg .u64 t; cvta.to.shared.u64 t, %1; cvt.u32.u64 %0, t; }" : "=r"(a) : "l"(p));
    return a;
}
__device__ __forceinline__ void cp16(uint32_t s, const void* g) {
    asm volatile("cp.async.cg.shared.global [%0], [%1], 16;" :: "r"(s), "l"(g));
}
#define CP_COMMIT() asm volatile("cp.async.commit_group;" ::: "memory")
#define CP_WAIT1()  asm volatile("cp.async.wait_group 1;" ::: "memory")

__device__ __forceinline__ void ldmx4(uint32_t a, uint32_t& r0, uint32_t& r1,
                                      uint32_t& r2, uint32_t& r3) {
    asm volatile("ldmatrix.sync.aligned.m8n8.x4.shared.b16 {%0,%1,%2,%3}, [%4];"
                 : "=r"(r0), "=r"(r1), "=r"(r2), "=r"(r3) : "r"(a));
}
__device__ __forceinline__ void mma16816(float* d, const uint32_t* a, const uint32_t* b) {
    asm volatile("mma.sync.aligned.m16n8k16.row.col.f32.bf16.bf16.f32 "
                 "{%0,%1,%2,%3}, {%4,%5,%6,%7}, {%8,%9}, {%0,%1,%2,%3};"
                 : "+f"(d[0]), "+f"(d[1]), "+f"(d[2]), "+f"(d[3])
                 : "r"(a[0]), "r"(a[1]), "r"(a[2]), "r"(a[3]), "r"(b[0]), "r"(b[1]));
}

// ---------------- one-shot weight split (all tensors, one launch) -----------
#define Q0 (SZ_WQKV/4)
#define Q1 (Q0 + SZ_WO/4)
#define Q2 (Q1 + SZ_WG/4)
#define Q3 (Q2 + SZ_W1/4)
#define Q4 (Q3 + SZ_W2/4)
#define Q5 (Q4 + SZ_EMB/4)
__global__ void split_all(
    const float4* w0, const float4* w1, const float4* w2,
    const float4* w3, const float4* w4, const float4* w5,
    uint2* h0, uint2* l0, uint2* h1, uint2* l1, uint2* h2, uint2* l2,
    uint2* h3, uint2* l3, uint2* h4, uint2* l4, uint2* h5, uint2* l5)
{
    long i = (long)blockIdx.x * 256 + threadIdx.x;
    if (i >= Q5) return;
    const float4* src; uint2 *hi, *lo; long off;
    if      (i < Q0) { src = w0; hi = h0; lo = l0; off = i; }
    else if (i < Q1) { src = w1; hi = h1; lo = l1; off = i - Q0; }
    else if (i < Q2) { src = w2; hi = h2; lo = l2; off = i - Q1; }
    else if (i < Q3) { src = w3; hi = h3; lo = l3; off = i - Q2; }
    else if (i < Q4) { src = w4; hi = h4; lo = l4; off = i - Q3; }
    else             { src = w5; hi = h5; lo = l5; off = i - Q4; }
    float4 v = src[off];
    __nv_bfloat16 a0, a1, a2, a3, b0, b1, b2, b3;
    splt(v.x, a0, b0); splt(v.y, a1, b1); splt(v.z, a2, b2); splt(v.w, a3, b3);
    uint2 H, L;
    H.x = (uint32_t)__bfloat16_as_ushort(a0) | ((uint32_t)__bfloat16_as_ushort(a1) << 16);
    H.y = (uint32_t)__bfloat16_as_ushort(a2) | ((uint32_t)__bfloat16_as_ushort(a3) << 16);
    L.x = (uint32_t)__bfloat16_as_ushort(b0) | ((uint32_t)__bfloat16_as_ushort(b1) << 16);
    L.y = (uint32_t)__bfloat16_as_ushort(b2) | ((uint32_t)__bfloat16_as_ushort(b3) << 16);
    hi[off] = H; lo[off] = L;
}

// ---------------- GEMM: C[M,N] = A[M,K] @ W[N,K]^T (bf16 3-mma split) -------
// Two A sources (concat at kSplit) for the gate GEMM. epi:
//   0 none, 1 +res, 2 gelu, 3 gated: out = res + sigmoid(acc)*corr
#define KC    32
#define SROW  80
#define AOFF_H 0
#define AOFF_L 10240
#define BOFF_H 20480
#define BOFF_L 30720
#define STG   40960
#define GSMEM (2 * STG)

__global__ __launch_bounds__(256, 2) void gemm_tc(
    const __nv_bfloat16* __restrict__ Ah, const __nv_bfloat16* __restrict__ Al,
    const __nv_bfloat16* __restrict__ Ah2, const __nv_bfloat16* __restrict__ Al2,
    int kSplit, int lda1, int lda2,
    const __nv_bfloat16* __restrict__ Wh, const __nv_bfloat16* __restrict__ Wl,
    const float* __restrict__ bias, const float* __restrict__ res,
    const float* __restrict__ corr,
    float* __restrict__ Cf, __nv_bfloat16* __restrict__ Ch, __nv_bfloat16* __restrict__ Cl,
    int M, int N, int K, int epi)
{
    extern __shared__ char smem[];
    uint32_t sb = smem_u32(smem);
    int tid = threadIdx.x, lane = tid & 31, w = tid >> 5;
    int wm = w & 3, wn = w >> 2;
    int bm = blockIdx.y * 128, bn = blockIdx.x * 128;

    int lrow = tid >> 1;
    int lc   = (tid & 1) * 2;
    uint32_t so = lrow * SROW + lc * 16;

    float acc[2][8][4];
    #pragma unroll
    for (int i = 0; i < 2; i++)
        #pragma unroll
        for (int j = 0; j < 8; j++)
            #pragma unroll
            for (int e = 0; e < 4; e++) acc[i][j][e] = 0.f;

    int nk = K / KC;

    // ---- loader for chunk kc into stage s ----
    auto load_chunk = [&](int kc, uint32_t s) {
        int kb = kc * KC;
        size_t goW = (size_t)(bn + lrow) * K + kb + lc * 8;
        const __nv_bfloat16 *sAh, *sAl; size_t goA;
        if (kb < kSplit) {
            sAh = Ah;  sAl = Al;
            goA = (size_t)(bm + lrow) * lda1 + kb + lc * 8;
        } else {
            sAh = Ah2; sAl = Al2;
            goA = (size_t)(bm + lrow) * lda2 + (kb - kSplit) + lc * 8;
        }
        cp16(s + AOFF_H + so, sAh + goA); cp16(s + AOFF_H + so + 16, sAh + goA + 8);
        cp16(s + AOFF_L + so, sAl + goA); cp16(s + AOFF_L + so + 16, sAl + goA + 8);
        cp16(s + BOFF_H + so, Wh + goW);  cp16(s + BOFF_H + so + 16, Wh + goW + 8);
        cp16(s + BOFF_L + so, Wl + goW);  cp16(s + BOFF_L + so + 16, Wl + goW + 8);
    };

    load_chunk(0, sb);
    CP_COMMIT();

    for (int kc = 0; kc < nk; kc++) {
        if (kc + 1 < nk) load_chunk(kc + 1, sb + ((kc + 1) & 1) * STG);
        CP_COMMIT();
        CP_WAIT1();
        __syncthreads();

        uint32_t s = sb + (kc & 1) * STG;
        #pragma unroll
        for (int k16 = 0; k16 < 2; k16++) {
            // A fragments for both m-groups (hi+lo): 16 regs
            uint32_t arow = wm * 32 + (lane & 15);
            uint32_t ak   = k16 * 16 + ((lane >> 4) << 3);
            uint32_t ahr[2][4], alr[2][4];
            #pragma unroll
            for (int mg = 0; mg < 2; mg++) {
                uint32_t aoff = (arow + mg * 16) * SROW + ak * 2;
                ldmx4(s + AOFF_H + aoff, ahr[mg][0], ahr[mg][1], ahr[mg][2], ahr[mg][3]);
                ldmx4(s + AOFF_L + aoff, alr[mg][0], alr[mg][1], alr[mg][2], alr[mg][3]);
            }
            uint32_t brow = wn * 64 + (lane & 7) + ((lane >> 4) << 3);
            uint32_t bk   = k16 * 16 + ((lane >> 3) & 1) * 8;
            #pragma unroll
            for (int ng = 0; ng < 4; ng++) {
                uint32_t off = (brow + ng * 16) * SROW + bk * 2;
                uint32_t bh[4], bl[4];
                ldmx4(s + BOFF_H + off, bh[0], bh[1], bh[2], bh[3]);
                ldmx4(s + BOFF_L + off, bl[0], bl[1], bl[2], bl[3]);
                #pragma unroll
                for (int mg = 0; mg < 2; mg++) {
                    mma16816(acc[mg][ng*2+0], ahr[mg], &bh[0]);
                    mma16816(acc[mg][ng*2+1], ahr[mg], &bh[2]);
                    mma16816(acc[mg][ng*2+0], ahr[mg], &bl[0]);
                    mma16816(acc[mg][ng*2+1], ahr[mg], &bl[2]);
                    mma16816(acc[mg][ng*2+0], alr[mg], &bh[0]);
                    mma16816(acc[mg][ng*2+1], alr[mg], &bh[2]);
                }
            }
        }
        __syncthreads();
    }

    #pragma unroll
    for (int mg = 0; mg < 2; mg++) {
        #pragma unroll
        for (int j = 0; j < 8; j++) {
            int m0 = bm + wm * 32 + mg * 16 + (lane >> 2);
            int n0 = bn + wn * 64 + j * 8 + (lane & 3) * 2;
            #pragma unroll
            for (int e = 0; e < 4; e++) {
                int m = m0 + (e >> 1) * 8;
                int n = n0 + (e & 1);
                size_t idx = (size_t)m * N + n;
                float v = acc[mg][j][e];
                if (bias) v += bias[n];
                if (epi == 1)      v += res[idx];
                else if (epi == 2) v = 0.5f * v * (1.f + erff(v * 0.70710678118f));
                else if (epi == 3) v = res[idx] + corr[idx] / (1.f + __expf(-v));
                if (Cf) Cf[idx] = v;
                if (Ch) {
                    __nv_bfloat16 hh, ll;
                    splt(v, hh, ll);
                    Ch[idx] = hh;
                    Cl[idx] = ll;
                }
            }
        }
    }
}

// ---------------- embedding ------------------------------------------------
__global__ void embed_kernel(const int* __restrict__ x, const float* __restrict__ emb,
                             const float* __restrict__ pos, float* __restrict__ h) {
    int row = blockIdx.x;
    int t   = row & (T_SEQ - 1);
    int tok = x[row];
    const float* e = emb + (size_t)tok * D_MODEL;
    const float* p = pos + (size_t)t   * D_MODEL;
    float* o = h + (size_t)row * D_MODEL;
    for (int d = threadIdx.x; d < D_MODEL; d += blockDim.x)
        o[d] = e[d] + p[d];
}

// ---------------- layernorm -------------------------------------------------
__global__ void ln_kernel(const float* __restrict__ in, const float* __restrict__ g,
                          const float* __restrict__ b, float* __restrict__ of,
                          __nv_bfloat16* __restrict__ oh, __nv_bfloat16* __restrict__ ol) {
    int row = blockIdx.x;
    const float* x = in + (size_t)row * D_MODEL;
    int tid = threadIdx.x;
    float s = 0.f, ss = 0.f;
    for (int d = tid; d < D_MODEL; d += 256) { float v = x[d]; s += v; ss += v * v; }
    #pragma unroll
    for (int off = 16; off; off >>= 1) {
        s  += __shfl_xor_sync(0xffffffffu, s,  off);
        ss += __shfl_xor_sync(0xffffffffu, ss, off);
    }
    __shared__ float shs[8], shss[8];
    if ((tid & 31) == 0) { shs[tid >> 5] = s; shss[tid >> 5] = ss; }
    __syncthreads();
    float tots = 0.f, totss = 0.f;
    #pragma unroll
    for (int i = 0; i < 8; i++) { tots += shs[i]; totss += shss[i]; }
    float mean = tots * (1.f / D_MODEL);
    float var  = totss * (1.f / D_MODEL) - mean * mean;
    float rstd = rsqrtf(var + 1e-5f);
    for (int d = tid; d < D_MODEL; d += 256) {
        float v = (x[d] - mean) * rstd * g[d] + b[d];
        size_t idx = (size_t)row * D_MODEL + d;
        if (of) of[idx] = v;
        __nv_bfloat16 hh, ll; splt(v, hh, ll); oh[idx] = hh; ol[idx] = ll;
    }
}

// ---------------- fused causal attention (fp32 flash + fused epilogue) ------
// outF = attention output fp32; outH/outL = bf16 split of output;
// diffH/diffL (optional) = bf16 split of (nIn - output).
__global__ __launch_bounds__(256) void attn_kernel(
    const float* __restrict__ qkv, const float* __restrict__ nIn,
    float* __restrict__ outF,
    __nv_bfloat16* __restrict__ outH, __nv_bfloat16* __restrict__ outL,
    __nv_bfloat16* __restrict__ diffH, __nv_bfloat16* __restrict__ diffL)
{
    int qt = blockIdx.x, hh = blockIdx.y, b = blockIdx.z;
    __shared__ __align__(16) float Qs[64][68];
    __shared__ __align__(16) float Ks[32][68];
    __shared__ __align__(16) float Vs[32][68];
    __shared__ float Ps[64][36];
    int tid = threadIdx.x;
    int tx = tid & 15, ty = tid >> 4;
    const float* base = qkv + (size_t)b * T_SEQ * 3072 + hh * 64;

    for (int i = tid; i < 64 * 64; i += 256) {
        int r = i >> 6, d = i & 63;
        Qs[r][d] = base[(size_t)(qt * 64 + r) * 3072 + d];
    }
    float m_i[4], l_i[4], O[4][4];
    #pragma unroll
    for (int i = 0; i < 4; i++) {
        m_i[i] = -1e30f; l_i[i] = 0.f;
        #pragma unroll
        for (int j = 0; j < 4; j++) O[i][j] = 0.f;
    }

    int ntiles = (qt * 64 + 63) / 32 + 1;
    for (int kt = 0; kt < ntiles; kt++) {
        __syncthreads();
        for (int i = tid; i < 32 * 64; i += 256) {
            int r = i >> 6, d = i & 63;
            const float* kb = base + (size_t)(kt * 32 + r) * 3072 + d;
            Ks[r][d] = kb[1024];
            Vs[r][d] = kb[2048];
        }
        __syncthreads();

        float s[4][2];
        #pragma unroll
        for (int i = 0; i < 4; i++) { s[i][0] = 0.f; s[i][1] = 0.f; }
        #pragma unroll
        for (int kk = 0; kk < 64; kk += 4) {
            float4 kv0 = *(const float4*)&Ks[tx*2+0][kk];
            float4 kv1 = *(const float4*)&Ks[tx*2+1][kk];
            #pragma unroll
            for (int i = 0; i < 4; i++) {
                float4 qv = *(const float4*)&Qs[ty*4+i][kk];
                s[i][0] += qv.x*kv0.x + qv.y*kv0.y + qv.z*kv0.z + qv.w*kv0.w;
                s[i][1] += qv.x*kv1.x + qv.y*kv1.y + qv.z*kv1.z + qv.w*kv1.w;
            }
        }

        #pragma unroll
        for (int i = 0; i < 4; i++) {
            int q = qt * 64 + ty * 4 + i;
            float s0 = (kt*32 + tx*2 + 0 <= q) ? s[i][0] * ATT_SCALE : -1e30f;
            float s1 = (kt*32 + tx*2 + 1 <= q) ? s[i][1] * ATT_SCALE : -1e30f;
            float mx = fmaxf(s0, s1);
            #pragma unroll
            for (int off = 8; off; off >>= 1)
                mx = fmaxf(mx, __shfl_xor_sync(0xffffffffu, mx, off));
            float mnew  = fmaxf(m_i[i], mx);
            float alpha = __expf(m_i[i] - mnew);
            float p0 = __expf(s0 - mnew);
            float p1 = __expf(s1 - mnew);
            float psum = p0 + p1;
            #pragma unroll
            for (int off = 8; off; off >>= 1)
                psum += __shfl_xor_sync(0xffffffffu, psum, off);
            l_i[i] = l_i[i] * alpha + psum;
            m_i[i] = mnew;
            #pragma unroll
            for (int j = 0; j < 4; j++) O[i][j] *= alpha;
            Ps[ty*4+i][tx*2+0] = p0;
            Ps[ty*4+i][tx*2+1] = p1;
        }
        __syncthreads();

        #pragma unroll 8
        for (int k = 0; k < 32; k++) {
            float4 vv = *(const float4*)&Vs[k][tx*4];
            #pragma unroll
            for (int i = 0; i < 4; i++) {
                float p = Ps[ty*4+i][k];
                O[i][0] += p * vv.x; O[i][1] += p * vv.y;
                O[i][2] += p * vv.z; O[i][3] += p * vv.w;
            }
        }
    }

    #pragma unroll
    for (int i = 0; i < 4; i++) {
        float inv = 1.f / l_i[i];
        int r = qt * 64 + ty * 4 + i;
        size_t rowbase = (size_t)(b * T_SEQ + r) * D_MODEL + hh * 64 + tx * 4;
        #pragma unroll
        for (int j = 0; j < 4; j++) {
            float v = O[i][j] * inv;
            size_t idx = rowbase + j;
            outF[idx] = v;
            __nv_bfloat16 hh2, ll2;
            splt(v, hh2, ll2);
            outH[idx] = hh2; outL[idx] = ll2;
            if (diffH) {
                float d = nIn[idx] - v;
                __nv_bfloat16 dh, dl;
                splt(d, dh, dl);
                diffH[idx] = dh; diffL[idx] = dl;
            }
        }
    }
}

// ---------------- driver ----------------------------------------------------
extern "C" void kernel_launch(void* const* d_in, const int* in_sizes, int n_in,
                              void* d_out, int out_size) {
    const int*   x      = (const int*)  d_in[0];
    const float* embed  = (const float*)d_in[1];
    const float* pos    = (const float*)d_in[2];
    const float* Wqkv   = (const float*)d_in[3];
    const float* bqkv   = (const float*)d_in[4];
    const float* Wo     = (const float*)d_in[5];
    const float* bo     = (const float*)d_in[6];
    const float* Wg     = (const float*)d_in[7];
    const float* bg     = (const float*)d_in[8];
    const float* ln1_g  = (const float*)d_in[9];
    const float* ln1_b  = (const float*)d_in[10];
    const float* W1     = (const float*)d_in[11];
    const float* b1     = (const float*)d_in[12];
    const float* W2     = (const float*)d_in[13];
    const float* b2     = (const float*)d_in[14];
    const float* ln2_g  = (const float*)d_in[15];
    const float* ln2_b  = (const float*)d_in[16];
    const float* lnf_g  = (const float*)d_in[17];
    const float* lnf_b  = (const float*)d_in[18];
    float* out = (float*)d_out;

    cudaFuncSetAttribute(gemm_tc, cudaFuncAttributeMaxDynamicSharedMemorySize, GSMEM);

    float *h, *n, *qkv, *pred, *corr;
    cudaGetSymbolAddress((void**)&h,    g_h);
    cudaGetSymbolAddress((void**)&n,    g_n);
    cudaGetSymbolAddress((void**)&qkv,  g_qkv);
    cudaGetSymbolAddress((void**)&pred, g_pred);
    cudaGetSymbolAddress((void**)&corr, g_corr);
    __nv_bfloat16 *ah, *al, *fh, *fl, *ph, *pl, *ch, *cl;
    cudaGetSymbolAddress((void**)&ah, g_ah);
    cudaGetSymbolAddress((void**)&al, g_al);
    cudaGetSymbolAddress((void**)&fh, g_fh);
    cudaGetSymbolAddress((void**)&fl, g_fl);
    cudaGetSymbolAddress((void**)&ph, g_ph);
    cudaGetSymbolAddress((void**)&pl, g_pl);
    cudaGetSymbolAddress((void**)&ch, g_ch);
    cudaGetSymbolAddress((void**)&cl, g_cl);
    __nv_bfloat16 *wqkv_h, *wqkv_l, *wo_h, *wo_l, *wg_h, *wg_l, *w1_h, *w1_l, *w2_h, *w2_l, *emb_h, *emb_l;
    cudaGetSymbolAddress((void**)&wqkv_h, g_wqkv_h); cudaGetSymbolAddress((void**)&wqkv_l, g_wqkv_l);
    cudaGetSymbolAddress((void**)&wo_h,   g_wo_h);   cudaGetSymbolAddress((void**)&wo_l,   g_wo_l);
    cudaGetSymbolAddress((void**)&wg_h,   g_wg_h);   cudaGetSymbolAddress((void**)&wg_l,   g_wg_l);
    cudaGetSymbolAddress((void**)&w1_h,   g_w1_h);   cudaGetSymbolAddress((void**)&w1_l,   g_w1_l);
    cudaGetSymbolAddress((void**)&w2_h,   g_w2_h);   cudaGetSymbolAddress((void**)&w2_l,   g_w2_l);
    cudaGetSymbolAddress((void**)&emb_h,  g_emb_h);  cudaGetSymbolAddress((void**)&emb_l,  g_emb_l);

    split_all<<<(int)((Q5 + 255) / 256), 256>>>(
        (const float4*)Wqkv, (const float4*)Wo, (const float4*)Wg,
        (const float4*)W1, (const float4*)W2, (const float4*)embed,
        (uint2*)wqkv_h, (uint2*)wqkv_l, (uint2*)wo_h, (uint2*)wo_l,
        (uint2*)wg_h, (uint2*)wg_l, (uint2*)w1_h, (uint2*)w1_l,
        (uint2*)w2_h, (uint2*)w2_l, (uint2*)emb_h, (uint2*)emb_l);

    dim3 attng(T_SEQ / 64, 16, 2);

    embed_kernel<<<BT, 256>>>(x, embed, pos, h);

    for (int l = 0; l < NLAYER; l++) {
        // n1 = ln(h) -> fp32 n + bf16 split (ah/al)
        ln_kernel<<<BT, 256>>>(h, ln1_g + l * D_MODEL, ln1_b + l * D_MODEL, n, ah, al);
        // qkv1 = n1 @ Wqkv0^T + b
        gemm_tc<<<dim3(3072/128, BT/128), 256, GSMEM>>>(
            ah, al, nullptr, nullptr, 1 << 30, D_MODEL, 0,
            wqkv_h + (size_t)(l*2+0)*3072*D_MODEL, wqkv_l + (size_t)(l*2+0)*3072*D_MODEL,
            bqkv + (l*2+0)*3072, nullptr, nullptr,
            qkv, nullptr, nullptr, BT, 3072, D_MODEL, 0);
        // attn1 -> pred (fp32 + split) and diff = n1 - pred (split into ah/al)
        attn_kernel<<<attng, 256>>>(qkv, n, pred, ph, pl, ah, al);
        // qkv2 = diff @ Wqkv1^T + b
        gemm_tc<<<dim3(3072/128, BT/128), 256, GSMEM>>>(
            ah, al, nullptr, nullptr, 1 << 30, D_MODEL, 0,
            wqkv_h + (size_t)(l*2+1)*3072*D_MODEL, wqkv_l + (size_t)(l*2+1)*3072*D_MODEL,
            bqkv + (l*2+1)*3072, nullptr, nullptr,
            qkv, nullptr, nullptr, BT, 3072, D_MODEL, 0);
        // attn2 -> corr (fp32 + split)
        attn_kernel<<<attng, 256>>>(qkv, nullptr, corr, ch, cl, nullptr, nullptr);
        // gated = pred + sigmoid([pred|corr]@Wg^T + bg)*corr  (split out into ah/al)
        gemm_tc<<<dim3(D_MODEL/128, BT/128), 256, GSMEM>>>(
            ph, pl, ch, cl, D_MODEL, D_MODEL, D_MODEL,
            wg_h + (size_t)l*D_MODEL*2*D_MODEL, wg_l + (size_t)l*D_MODEL*2*D_MODEL,
            bg + l*D_MODEL, pred, corr,
            nullptr, ah, al, BT, D_MODEL, 2*D_MODEL, 3);
        // h += gated @ Wo^T + bo
        gemm_tc<<<dim3(D_MODEL/128, BT/128), 256, GSMEM>>>(
            ah, al, nullptr, nullptr, 1 << 30, D_MODEL, 0,
            wo_h + (size_t)l*D_MODEL*D_MODEL, wo_l + (size_t)l*D_MODEL*D_MODEL,
            bo + l*D_MODEL, h, nullptr,
            h, nullptr, nullptr, BT, D_MODEL, D_MODEL, 1);
        // FF
        ln_kernel<<<BT, 256>>>(h, ln2_g + l * D_MODEL, ln2_b + l * D_MODEL, nullptr, ah, al);
        gemm_tc<<<dim3(FF_DIM/128, BT/128), 256, GSMEM>>>(
            ah, al, nullptr, nullptr, 1 << 30, D_MODEL, 0,
            w1_h + (size_t)l*FF_DIM*D_MODEL, w1_l + (size_t)l*FF_DIM*D_MODEL,
            b1 + l*FF_DIM, nullptr, nullptr,
            nullptr, fh, fl, BT, FF_DIM, D_MODEL, 2);
        gemm_tc<<<dim3(D_MODEL/128, BT/128), 256, GSMEM>>>(
            fh, fl, nullptr, nullptr, 1 << 30, FF_DIM, 0,
            w2_h + (size_t)l*D_MODEL*FF_DIM, w2_l + (size_t)l*D_MODEL*FF_DIM,
            b2 + l*D_MODEL, h, nullptr,
            h, nullptr, nullptr, BT, D_MODEL, FF_DIM, 1);
    }

    ln_kernel<<<BT, 256>>>(h, lnf_g, lnf_b, nullptr, ah, al);
    gemm_tc<<<dim3(VOCAB/128, BT/128), 256, GSMEM>>>(
        ah, al, nullptr, nullptr, 1 << 30, D_MODEL, 0,
        emb_h, emb_l, nullptr, nullptr, nullptr,
        out, nullptr, nullptr, BT, VOCAB, D_MODEL, 0);
}

// round 5
// speedup vs baseline: 2.5140x; 1.2164x over previous
#include <cuda_runtime.h>
#include <cuda_bf16.h>
#include <stdint.h>
#include <math.h>

#define T_SEQ   1024
#define D_MODEL 1024
#define NLAYER  4
#define FF_DIM  4096
#define VOCAB   32000
#define BT      2048
#define ATT_SCALE 0.125f

// ---------------- fp32 scratch ----------------------------------------------
__device__ float g_h   [BT * D_MODEL];
__device__ float g_n   [BT * D_MODEL];
__device__ float g_pred[BT * D_MODEL];
__device__ float g_corr[BT * D_MODEL];

// ---------------- bf16 hi/lo activation scratch -----------------------------
__device__ __align__(16) __nv_bfloat16 g_ah[BT * FF_DIM];
__device__ __align__(16) __nv_bfloat16 g_al[BT * FF_DIM];
__device__ __align__(16) __nv_bfloat16 g_fh[BT * FF_DIM];
__device__ __align__(16) __nv_bfloat16 g_fl[BT * FF_DIM];
__device__ __align__(16) __nv_bfloat16 g_ph[BT * D_MODEL], g_pl[BT * D_MODEL];
__device__ __align__(16) __nv_bfloat16 g_ch[BT * D_MODEL], g_cl[BT * D_MODEL];
__device__ __align__(16) __nv_bfloat16 g_qkvh[BT * 3 * D_MODEL];
__device__ __align__(16) __nv_bfloat16 g_qkvl[BT * 3 * D_MODEL];

// ---------------- bf16 hi/lo weights ----------------------------------------
#define SZ_WQKV (NLAYER * 2 * 3 * D_MODEL * D_MODEL)
#define SZ_WO   (NLAYER * D_MODEL * D_MODEL)
#define SZ_WG   (NLAYER * D_MODEL * 2 * D_MODEL)
#define SZ_W1   (NLAYER * FF_DIM * D_MODEL)
#define SZ_W2   (NLAYER * D_MODEL * FF_DIM)
#define SZ_EMB  (VOCAB * D_MODEL)
__device__ __align__(16) __nv_bfloat16 g_wqkv_h[SZ_WQKV], g_wqkv_l[SZ_WQKV];
__device__ __align__(16) __nv_bfloat16 g_wo_h  [SZ_WO],   g_wo_l  [SZ_WO];
__device__ __align__(16) __nv_bfloat16 g_wg_h  [SZ_WG],   g_wg_l  [SZ_WG];
__device__ __align__(16) __nv_bfloat16 g_w1_h  [SZ_W1],   g_w1_l  [SZ_W1];
__device__ __align__(16) __nv_bfloat16 g_w2_h  [SZ_W2],   g_w2_l  [SZ_W2];
__device__ __align__(16) __nv_bfloat16 g_emb_h [SZ_EMB],  g_emb_l [SZ_EMB];

// ---------------- helpers ----------------------------------------------------
__device__ __forceinline__ void splt(float x, __nv_bfloat16& h, __nv_bfloat16& l) {
    h = __float2bfloat16_rn(x);
    l = __float2bfloat16_rn(x - __bfloat162float(h));
}
__device__ __forceinline__ void pack_hl(float x, float y, uint32_t& h, uint32_t& l) {
    __nv_bfloat16 h0 = __float2bfloat16_rn(x), h1 = __float2bfloat16_rn(y);
    __nv_bfloat16 l0 = __float2bfloat16_rn(x - __bfloat162float(h0));
    __nv_bfloat16 l1 = __float2bfloat16_rn(y - __bfloat162float(h1));
    h = (uint32_t)__bfloat16_as_ushort(h0) | ((uint32_t)__bfloat16_as_ushort(h1) << 16);
    l = (uint32_t)__bfloat16_as_ushort(l0) | ((uint32_t)__bfloat16_as_ushort(l1) << 16);
}
__device__ __forceinline__ uint32_t smem_u32(const void* p) {
    uint32_t a;
    asm("{ .reg .u64 t; cvta.to.shared.u64 t, %1; cvt.u32.u64 %0, t; }" : "=r"(a) : "l"(p));
    return a;
}
__device__ __forceinline__ void cp16(uint32_t s, const void* g) {
    asm volatile("cp.async.cg.shared.global [%0], [%1], 16;" :: "r"(s), "l"(g));
}
#define CP_COMMIT() asm volatile("cp.async.commit_group;" ::: "memory")
#define CP_WAIT1()  asm volatile("cp.async.wait_group 1;" ::: "memory")

__device__ __forceinline__ void ldmx4(uint32_t a, uint32_t& r0, uint32_t& r1,
                                      uint32_t& r2, uint32_t& r3) {
    asm volatile("ldmatrix.sync.aligned.m8n8.x4.shared.b16 {%0,%1,%2,%3}, [%4];"
                 : "=r"(r0), "=r"(r1), "=r"(r2), "=r"(r3) : "r"(a));
}
__device__ __forceinline__ void ldmx4t(uint32_t a, uint32_t& r0, uint32_t& r1,
                                       uint32_t& r2, uint32_t& r3) {
    asm volatile("ldmatrix.sync.aligned.m8n8.x4.trans.shared.b16 {%0,%1,%2,%3}, [%4];"
                 : "=r"(r0), "=r"(r1), "=r"(r2), "=r"(r3) : "r"(a));
}
__device__ __forceinline__ void mma16816(float* d, const uint32_t* a, const uint32_t* b) {
    asm volatile("mma.sync.aligned.m16n8k16.row.col.f32.bf16.bf16.f32 "
                 "{%0,%1,%2,%3}, {%4,%5,%6,%7}, {%8,%9}, {%0,%1,%2,%3};"
                 : "+f"(d[0]), "+f"(d[1]), "+f"(d[2]), "+f"(d[3])
                 : "r"(a[0]), "r"(a[1]), "r"(a[2]), "r"(a[3]), "r"(b[0]), "r"(b[1]));
}

// ---------------- one-shot weight split -------------------------------------
#define Q0 (SZ_WQKV/4)
#define Q1 (Q0 + SZ_WO/4)
#define Q2 (Q1 + SZ_WG/4)
#define Q3 (Q2 + SZ_W1/4)
#define Q4 (Q3 + SZ_W2/4)
#define Q5 (Q4 + SZ_EMB/4)
__global__ void split_all(
    const float4* w0, const float4* w1, const float4* w2,
    const float4* w3, const float4* w4, const float4* w5,
    uint2* h0, uint2* l0, uint2* h1, uint2* l1, uint2* h2, uint2* l2,
    uint2* h3, uint2* l3, uint2* h4, uint2* l4, uint2* h5, uint2* l5)
{
    long i = (long)blockIdx.x * 256 + threadIdx.x;
    if (i >= Q5) return;
    const float4* src; uint2 *hi, *lo; long off;
    if      (i < Q0) { src = w0; hi = h0; lo = l0; off = i; }
    else if (i < Q1) { src = w1; hi = h1; lo = l1; off = i - Q0; }
    else if (i < Q2) { src = w2; hi = h2; lo = l2; off = i - Q1; }
    else if (i < Q3) { src = w3; hi = h3; lo = l3; off = i - Q2; }
    else if (i < Q4) { src = w4; hi = h4; lo = l4; off = i - Q3; }
    else             { src = w5; hi = h5; lo = l5; off = i - Q4; }
    float4 v = src[off];
    __nv_bfloat16 a0, a1, a2, a3, b0, b1, b2, b3;
    splt(v.x, a0, b0); splt(v.y, a1, b1); splt(v.z, a2, b2); splt(v.w, a3, b3);
    uint2 H, L;
    H.x = (uint32_t)__bfloat16_as_ushort(a0) | ((uint32_t)__bfloat16_as_ushort(a1) << 16);
    H.y = (uint32_t)__bfloat16_as_ushort(a2) | ((uint32_t)__bfloat16_as_ushort(a3) << 16);
    L.x = (uint32_t)__bfloat16_as_ushort(b0) | ((uint32_t)__bfloat16_as_ushort(b1) << 16);
    L.y = (uint32_t)__bfloat16_as_ushort(b2) | ((uint32_t)__bfloat16_as_ushort(b3) << 16);
    hi[off] = H; lo[off] = L;
}

// ---------------- GEMM (bf16 3-mma hi/lo split) ------------------------------
#define KC    32
#define SROW  80
#define AOFF_H 0
#define AOFF_L 10240
#define BOFF_H 20480
#define BOFF_L 30720
#define STG   40960
#define GSMEM (2 * STG)

__global__ __launch_bounds__(256, 2) void gemm_tc(
    const __nv_bfloat16* __restrict__ Ah, const __nv_bfloat16* __restrict__ Al,
    const __nv_bfloat16* __restrict__ Ah2, const __nv_bfloat16* __restrict__ Al2,
    int kSplit, int lda1, int lda2,
    const __nv_bfloat16* __restrict__ Wh, const __nv_bfloat16* __restrict__ Wl,
    const float* __restrict__ bias, const float* __restrict__ res,
    const float* __restrict__ corr,
    float* __restrict__ Cf, __nv_bfloat16* __restrict__ Ch, __nv_bfloat16* __restrict__ Cl,
    int M, int N, int K, int epi)
{
    extern __shared__ char smem[];
    uint32_t sb = smem_u32(smem);
    int tid = threadIdx.x, lane = tid & 31, w = tid >> 5;
    int wm = w & 3, wn = w >> 2;
    int bm = blockIdx.y * 128, bn = blockIdx.x * 128;

    int lrow = tid >> 1;
    int lc   = (tid & 1) * 2;
    uint32_t so = lrow * SROW + lc * 16;

    float acc[2][8][4];
    #pragma unroll
    for (int i = 0; i < 2; i++)
        #pragma unroll
        for (int j = 0; j < 8; j++)
            #pragma unroll
            for (int e = 0; e < 4; e++) acc[i][j][e] = 0.f;

    int nk = K / KC;

    auto load_chunk = [&](int kc, uint32_t s) {
        int kb = kc * KC;
        size_t goW = (size_t)(bn + lrow) * K + kb + lc * 8;
        const __nv_bfloat16 *sAh, *sAl; size_t goA;
        if (kb < kSplit) {
            sAh = Ah;  sAl = Al;
            goA = (size_t)(bm + lrow) * lda1 + kb + lc * 8;
        } else {
            sAh = Ah2; sAl = Al2;
            goA = (size_t)(bm + lrow) * lda2 + (kb - kSplit) + lc * 8;
        }
        cp16(s + AOFF_H + so, sAh + goA); cp16(s + AOFF_H + so + 16, sAh + goA + 8);
        cp16(s + AOFF_L + so, sAl + goA); cp16(s + AOFF_L + so + 16, sAl + goA + 8);
        cp16(s + BOFF_H + so, Wh + goW);  cp16(s + BOFF_H + so + 16, Wh + goW + 8);
        cp16(s + BOFF_L + so, Wl + goW);  cp16(s + BOFF_L + so + 16, Wl + goW + 8);
    };

    load_chunk(0, sb);
    CP_COMMIT();

    for (int kc = 0; kc < nk; kc++) {
        if (kc + 1 < nk) load_chunk(kc + 1, sb + ((kc + 1) & 1) * STG);
        CP_COMMIT();
        CP_WAIT1();
        __syncthreads();

        uint32_t s = sb + (kc & 1) * STG;
        #pragma unroll
        for (int k16 = 0; k16 < 2; k16++) {
            uint32_t arow = wm * 32 + (lane & 15);
            uint32_t ak   = k16 * 16 + ((lane >> 4) << 3);
            uint32_t ahr[2][4], alr[2][4];
            #pragma unroll
            for (int mg = 0; mg < 2; mg++) {
                uint32_t aoff = (arow + mg * 16) * SROW + ak * 2;
                ldmx4(s + AOFF_H + aoff, ahr[mg][0], ahr[mg][1], ahr[mg][2], ahr[mg][3]);
                ldmx4(s + AOFF_L + aoff, alr[mg][0], alr[mg][1], alr[mg][2], alr[mg][3]);
            }
            uint32_t brow = wn * 64 + (lane & 7) + ((lane >> 4) << 3);
            uint32_t bk   = k16 * 16 + ((lane >> 3) & 1) * 8;
            #pragma unroll
            for (int ng = 0; ng < 4; ng++) {
                uint32_t off = (brow + ng * 16) * SROW + bk * 2;
                uint32_t bh[4], bl[4];
                ldmx4(s + BOFF_H + off, bh[0], bh[1], bh[2], bh[3]);
                ldmx4(s + BOFF_L + off, bl[0], bl[1], bl[2], bl[3]);
                #pragma unroll
                for (int mg = 0; mg < 2; mg++) {
                    mma16816(acc[mg][ng*2+0], ahr[mg], &bh[0]);
                    mma16816(acc[mg][ng*2+1], ahr[mg], &bh[2]);
                    mma16816(acc[mg][ng*2+0], ahr[mg], &bl[0]);
                    mma16816(acc[mg][ng*2+1], ahr[mg], &bl[2]);
                    mma16816(acc[mg][ng*2+0], alr[mg], &bh[0]);
                    mma16816(acc[mg][ng*2+1], alr[mg], &bh[2]);
                }
            }
        }
        __syncthreads();
    }

    #pragma unroll
    for (int mg = 0; mg < 2; mg++) {
        #pragma unroll
        for (int j = 0; j < 8; j++) {
            int m0 = bm + wm * 32 + mg * 16 + (lane >> 2);
            int n0 = bn + wn * 64 + j * 8 + (lane & 3) * 2;
            #pragma unroll
            for (int e = 0; e < 4; e++) {
                int m = m0 + (e >> 1) * 8;
                int n = n0 + (e & 1);
                size_t idx = (size_t)m * N + n;
                float v = acc[mg][j][e];
                if (bias) v += bias[n];
                if (epi == 1)      v += res[idx];
                else if (epi == 2) v = 0.5f * v * (1.f + erff(v * 0.70710678118f));
                else if (epi == 3) v = res[idx] + corr[idx] / (1.f + __expf(-v));
                if (Cf) Cf[idx] = v;
                if (Ch) {
                    __nv_bfloat16 hh, ll;
                    splt(v, hh, ll);
                    Ch[idx] = hh;
                    Cl[idx] = ll;
                }
            }
        }
    }
}

// ---------------- embedding ------------------------------------------------
__global__ void embed_kernel(const int* __restrict__ x, const float* __restrict__ emb,
                             const float* __restrict__ pos, float* __restrict__ h) {
    int row = blockIdx.x;
    int t   = row & (T_SEQ - 1);
    int tok = x[row];
    const float* e = emb + (size_t)tok * D_MODEL;
    const float* p = pos + (size_t)t   * D_MODEL;
    float* o = h + (size_t)row * D_MODEL;
    for (int d = threadIdx.x; d < D_MODEL; d += blockDim.x)
        o[d] = e[d] + p[d];
}

// ---------------- layernorm -------------------------------------------------
__global__ void ln_kernel(const float* __restrict__ in, const float* __restrict__ g,
                          const float* __restrict__ b, float* __restrict__ of,
                          __nv_bfloat16* __restrict__ oh, __nv_bfloat16* __restrict__ ol) {
    int row = blockIdx.x;
    const float* x = in + (size_t)row * D_MODEL;
    int tid = threadIdx.x;
    float s = 0.f, ss = 0.f;
    for (int d = tid; d < D_MODEL; d += 256) { float v = x[d]; s += v; ss += v * v; }
    #pragma unroll
    for (int off = 16; off; off >>= 1) {
        s  += __shfl_xor_sync(0xffffffffu, s,  off);
        ss += __shfl_xor_sync(0xffffffffu, ss, off);
    }
    __shared__ float shs[8], shss[8];
    if ((tid & 31) == 0) { shs[tid >> 5] = s; shss[tid >> 5] = ss; }
    __syncthreads();
    float tots = 0.f, totss = 0.f;
    #pragma unroll
    for (int i = 0; i < 8; i++) { tots += shs[i]; totss += shss[i]; }
    float mean = tots * (1.f / D_MODEL);
    float var  = totss * (1.f / D_MODEL) - mean * mean;
    float rstd = rsqrtf(var + 1e-5f);
    for (int d = tid; d < D_MODEL; d += 256) {
        float v = (x[d] - mean) * rstd * g[d] + b[d];
        size_t idx = (size_t)row * D_MODEL + d;
        if (of) of[idx] = v;
        __nv_bfloat16 hh, ll; splt(v, hh, ll); oh[idx] = hh; ol[idx] = ll;
    }
}

// ---------------- HMMA flash attention --------------------------------------
// 128 threads (4 warps), Q-tile 64 (16 rows/warp), K-tile 64.
// qkv stored as bf16 hi/lo ([token][3*1024]); hi/lo 3-mma for S and PV.
// smem (bytes): Qh 0, Ql 9216; stage s at 18432+s*36864: Kh+0 Kl+9216 Vh+18432 Vl+27648
#define AT_ROWB   144                     // bytes per 64-elem row (8 pad elems)
#define AT_QH     0
#define AT_QL     9216
#define AT_STAGE0 18432
#define AT_STGSZ  36864
#define AT_KH     0
#define AT_KL     9216
#define AT_VH     18432
#define AT_VL     27648
#define AT_SMEM   (18432 + 2 * 36864)

__global__ __launch_bounds__(128, 2) void attn_mma(
    const __nv_bfloat16* __restrict__ qkvh, const __nv_bfloat16* __restrict__ qkvl,
    const float* __restrict__ nIn,
    float* __restrict__ outF,
    __nv_bfloat16* __restrict__ outH, __nv_bfloat16* __restrict__ outL,
    __nv_bfloat16* __restrict__ diffH, __nv_bfloat16* __restrict__ diffL)
{
    extern __shared__ char sm[];
    uint32_t sb = smem_u32(sm);
    int qt = blockIdx.x, hh = blockIdx.y, b = blockIdx.z;
    int tid = threadIdx.x, lane = tid & 31, wq = tid >> 5;
    int qb = wq * 16;

    // ---- Q load (one group) ----
    #pragma unroll
    for (int it = 0; it < 8; it++) {
        int i = tid + it * 128;
        int tensor = i >> 9, ww = i & 511, row = ww >> 3, c = ww & 7;
        size_t ge = (size_t)(b * T_SEQ + qt * 64 + row) * 3072 + hh * 64 + c * 8;
        const __nv_bfloat16* src = tensor ? qkvl : qkvh;
        uint32_t dst = sb + (tensor ? AT_QL : AT_QH) + row * AT_ROWB + c * 16;
        cp16(dst, src + ge);
    }
    CP_COMMIT();

    auto load_kv = [&](int kt, int stage) {
        uint32_t stb = sb + AT_STAGE0 + stage * AT_STGSZ;
        #pragma unroll
        for (int it = 0; it < 16; it++) {
            int i = tid + it * 128;
            int tensor = i >> 9, ww = i & 511, row = ww >> 3, c = ww & 7;
            int kvoff = (tensor >= 2) ? 2048 : 1024;
            size_t ge = (size_t)(b * T_SEQ + kt * 64 + row) * 3072 + kvoff + hh * 64 + c * 8;
            const __nv_bfloat16* src = (tensor & 1) ? qkvl : qkvh;
            uint32_t toff = (tensor == 0) ? AT_KH : (tensor == 1) ? AT_KL
                          : (tensor == 2) ? AT_VH : AT_VL;
            cp16(stb + toff + row * AT_ROWB + c * 16, src + ge);
        }
    };
    load_kv(0, 0);
    CP_COMMIT();

    float O[8][4];
    #pragma unroll
    for (int j = 0; j < 8; j++)
        #pragma unroll
        for (int e = 0; e < 4; e++) O[j][e] = 0.f;
    float m0 = -1e30f, m1 = -1e30f, l0 = 0.f, l1 = 0.f;

    int r0 = qt * 64 + qb + (lane >> 2);
    int r1 = r0 + 8;

    for (int kt = 0; kt <= qt; kt++) {
        if (kt < qt) load_kv(kt + 1, (kt + 1) & 1);
        CP_COMMIT();
        CP_WAIT1();
        __syncthreads();

        uint32_t stb = sb + AT_STAGE0 + (kt & 1) * AT_STGSZ;

        // ---- S = Q K^T (3-mma hi/lo) ----
        float S[8][4];
        #pragma unroll
        for (int j = 0; j < 8; j++)
            #pragma unroll
            for (int e = 0; e < 4; e++) S[j][e] = 0.f;

        #pragma unroll
        for (int t = 0; t < 4; t++) {
            uint32_t qa = sb + (qb + (lane & 15)) * AT_ROWB + (t * 16 + (lane >> 4) * 8) * 2;
            uint32_t qh[4], ql[4];
            ldmx4(qa + AT_QH, qh[0], qh[1], qh[2], qh[3]);
            ldmx4(qa + AT_QL, ql[0], ql[1], ql[2], ql[3]);
            #pragma unroll
            for (int jj = 0; jj < 4; jj++) {
                uint32_t ka = stb + (jj * 16 + (lane & 7) + ((lane >> 4) << 3)) * AT_ROWB
                            + (t * 16 + ((lane >> 3) & 1) * 8) * 2;
                uint32_t kh[4], kl[4];
                ldmx4(ka + AT_KH, kh[0], kh[1], kh[2], kh[3]);
                ldmx4(ka + AT_KL, kl[0], kl[1], kl[2], kl[3]);
                mma16816(S[jj*2+0], qh, &kh[0]); mma16816(S[jj*2+1], qh, &kh[2]);
                mma16816(S[jj*2+0], qh, &kl[0]); mma16816(S[jj*2+1], qh, &kl[2]);
                mma16816(S[jj*2+0], ql, &kh[0]); mma16816(S[jj*2+1], ql, &kh[2]);
            }
        }

        // ---- masked online softmax ----
        int cb = kt * 64 + ((lane & 3) << 1);
        float mx0 = -1e30f, mx1 = -1e30f;
        #pragma unroll
        for (int j = 0; j < 8; j++) {
            int c0 = cb + j * 8, c1 = c0 + 1;
            float v;
            v = (c0 <= r0) ? S[j][0] * ATT_SCALE : -1e30f; S[j][0] = v; mx0 = fmaxf(mx0, v);
            v = (c1 <= r0) ? S[j][1] * ATT_SCALE : -1e30f; S[j][1] = v; mx0 = fmaxf(mx0, v);
            v = (c0 <= r1) ? S[j][2] * ATT_SCALE : -1e30f; S[j][2] = v; mx1 = fmaxf(mx1, v);
            v = (c1 <= r1) ? S[j][3] * ATT_SCALE : -1e30f; S[j][3] = v; mx1 = fmaxf(mx1, v);
        }
        mx0 = fmaxf(mx0, __shfl_xor_sync(0xffffffffu, mx0, 1));
        mx0 = fmaxf(mx0, __shfl_xor_sync(0xffffffffu, mx0, 2));
        mx1 = fmaxf(mx1, __shfl_xor_sync(0xffffffffu, mx1, 1));
        mx1 = fmaxf(mx1, __shfl_xor_sync(0xffffffffu, mx1, 2));
        float mn0 = fmaxf(m0, mx0), mn1 = fmaxf(m1, mx1);
        float a0 = __expf(m0 - mn0), a1 = __expf(m1 - mn1);
        m0 = mn0; m1 = mn1;
        float s0 = 0.f, s1 = 0.f;
        #pragma unroll
        for (int j = 0; j < 8; j++) {
            S[j][0] = __expf(S[j][0] - m0); s0 += S[j][0];
            S[j][1] = __expf(S[j][1] - m0); s0 += S[j][1];
            S[j][2] = __expf(S[j][2] - m1); s1 += S[j][2];
            S[j][3] = __expf(S[j][3] - m1); s1 += S[j][3];
        }
        s0 += __shfl_xor_sync(0xffffffffu, s0, 1);
        s0 += __shfl_xor_sync(0xffffffffu, s0, 2);
        s1 += __shfl_xor_sync(0xffffffffu, s1, 1);
        s1 += __shfl_xor_sync(0xffffffffu, s1, 2);
        l0 = l0 * a0 + s0; l1 = l1 * a1 + s1;
        #pragma unroll
        for (int j = 0; j < 8; j++) {
            O[j][0] *= a0; O[j][1] *= a0; O[j][2] *= a1; O[j][3] *= a1;
        }

        // ---- O += P V (3-mma hi/lo, V via ldmatrix.trans) ----
        #pragma unroll
        for (int t = 0; t < 4; t++) {
            uint32_t pah[4], pal[4];
            pack_hl(S[2*t  ][0], S[2*t  ][1], pah[0], pal[0]);
            pack_hl(S[2*t  ][2], S[2*t  ][3], pah[1], pal[1]);
            pack_hl(S[2*t+1][0], S[2*t+1][1], pah[2], pal[2]);
            pack_hl(S[2*t+1][2], S[2*t+1][3], pah[3], pal[3]);
            #pragma unroll
            for (int dd = 0; dd < 4; dd++) {
                uint32_t va = stb + (t * 16 + (lane & 7) + ((lane >> 3) & 1) * 8) * AT_ROWB
                            + (dd * 16 + (lane >> 4) * 8) * 2;
                uint32_t vh[4], vl[4];
                ldmx4t(va + AT_VH, vh[0], vh[1], vh[2], vh[3]);
                ldmx4t(va + AT_VL, vl[0], vl[1], vl[2], vl[3]);
                mma16816(O[dd*2+0], pah, &vh[0]); mma16816(O[dd*2+1], pah, &vh[2]);
                mma16816(O[dd*2+0], pah, &vl[0]); mma16816(O[dd*2+1], pah, &vl[2]);
                mma16816(O[dd*2+0], pal, &vh[0]); mma16816(O[dd*2+1], pal, &vh[2]);
            }
        }
        __syncthreads();
    }

    // ---- epilogue ----
    float i0 = 1.f / l0, i1 = 1.f / l1;
    int tok0 = b * T_SEQ + r0, tok1 = b * T_SEQ + r1;
    #pragma unroll
    for (int j = 0; j < 8; j++) {
        int d = hh * 64 + j * 8 + ((lane & 3) << 1);
        size_t idx0 = (size_t)tok0 * D_MODEL + d;
        size_t idx1 = (size_t)tok1 * D_MODEL + d;
        float v00 = O[j][0] * i0, v01 = O[j][1] * i0;
        float v10 = O[j][2] * i1, v11 = O[j][3] * i1;
        outF[idx0] = v00; outF[idx0 + 1] = v01;
        outF[idx1] = v10; outF[idx1 + 1] = v11;
        __nv_bfloat16 hh0, ll0, hh1, ll1;
        splt(v00, hh0, ll0); splt(v01, hh1, ll1);
        outH[idx0] = hh0; outH[idx0 + 1] = hh1;
        outL[idx0] = ll0; outL[idx0 + 1] = ll1;
        splt(v10, hh0, ll0); splt(v11, hh1, ll1);
        outH[idx1] = hh0; outH[idx1 + 1] = hh1;
        outL[idx1] = ll0; outL[idx1 + 1] = ll1;
        if (diffH) {
            float d00 = nIn[idx0] - v00, d01 = nIn[idx0 + 1] - v01;
            float d10 = nIn[idx1] - v10, d11 = nIn[idx1 + 1] - v11;
            splt(d00, hh0, ll0); splt(d01, hh1, ll1);
            diffH[idx0] = hh0; diffH[idx0 + 1] = hh1;
            diffL[idx0] = ll0; diffL[idx0 + 1] = ll1;
            splt(d10, hh0, ll0); splt(d11, hh1, ll1);
            diffH[idx1] = hh0; diffH[idx1 + 1] = hh1;
            diffL[idx1] = ll0; diffL[idx1 + 1] = ll1;
        }
    }
}

// ---------------- driver ----------------------------------------------------
extern "C" void kernel_launch(void* const* d_in, const int* in_sizes, int n_in,
                              void* d_out, int out_size) {
    const int*   x      = (const int*)  d_in[0];
    const float* embed  = (const float*)d_in[1];
    const float* pos    = (const float*)d_in[2];
    const float* Wqkv   = (const float*)d_in[3];
    const float* bqkv   = (const float*)d_in[4];
    const float* Wo     = (const float*)d_in[5];
    const float* bo     = (const float*)d_in[6];
    const float* Wg     = (const float*)d_in[7];
    const float* bg     = (const float*)d_in[8];
    const float* ln1_g  = (const float*)d_in[9];
    const float* ln1_b  = (const float*)d_in[10];
    const float* W1     = (const float*)d_in[11];
    const float* b1     = (const float*)d_in[12];
    const float* W2     = (const float*)d_in[13];
    const float* b2     = (const float*)d_in[14];
    const float* ln2_g  = (const float*)d_in[15];
    const float* ln2_b  = (const float*)d_in[16];
    const float* lnf_g  = (const float*)d_in[17];
    const float* lnf_b  = (const float*)d_in[18];
    float* out = (float*)d_out;

    cudaFuncSetAttribute(gemm_tc, cudaFuncAttributeMaxDynamicSharedMemorySize, GSMEM);
    cudaFuncSetAttribute(attn_mma, cudaFuncAttributeMaxDynamicSharedMemorySize, AT_SMEM);

    float *h, *n, *pred, *corr;
    cudaGetSymbolAddress((void**)&h,    g_h);
    cudaGetSymbolAddress((void**)&n,    g_n);
    cudaGetSymbolAddress((void**)&pred, g_pred);
    cudaGetSymbolAddress((void**)&corr, g_corr);
    __nv_bfloat16 *ah, *al, *fh, *fl, *ph, *pl, *ch, *cl, *qh, *ql;
    cudaGetSymbolAddress((void**)&ah, g_ah);
    cudaGetSymbolAddress((void**)&al, g_al);
    cudaGetSymbolAddress((void**)&fh, g_fh);
    cudaGetSymbolAddress((void**)&fl, g_fl);
    cudaGetSymbolAddress((void**)&ph, g_ph);
    cudaGetSymbolAddress((void**)&pl, g_pl);
    cudaGetSymbolAddress((void**)&ch, g_ch);
    cudaGetSymbolAddress((void**)&cl, g_cl);
    cudaGetSymbolAddress((void**)&qh, g_qkvh);
    cudaGetSymbolAddress((void**)&ql, g_qkvl);
    __nv_bfloat16 *wqkv_h, *wqkv_l, *wo_h, *wo_l, *wg_h, *wg_l, *w1_h, *w1_l, *w2_h, *w2_l, *emb_h, *emb_l;
    cudaGetSymbolAddress((void**)&wqkv_h, g_wqkv_h); cudaGetSymbolAddress((void**)&wqkv_l, g_wqkv_l);
    cudaGetSymbolAddress((void**)&wo_h,   g_wo_h);   cudaGetSymbolAddress((void**)&wo_l,   g_wo_l);
    cudaGetSymbolAddress((void**)&wg_h,   g_wg_h);   cudaGetSymbolAddress((void**)&wg_l,   g_wg_l);
    cudaGetSymbolAddress((void**)&w1_h,   g_w1_h);   cudaGetSymbolAddress((void**)&w1_l,   g_w1_l);
    cudaGetSymbolAddress((void**)&w2_h,   g_w2_h);   cudaGetSymbolAddress((void**)&w2_l,   g_w2_l);
    cudaGetSymbolAddress((void**)&emb_h,  g_emb_h);  cudaGetSymbolAddress((void**)&emb_l,  g_emb_l);

    split_all<<<(int)((Q5 + 255) / 256), 256>>>(
        (const float4*)Wqkv, (const float4*)Wo, (const float4*)Wg,
        (const float4*)W1, (const float4*)W2, (const float4*)embed,
        (uint2*)wqkv_h, (uint2*)wqkv_l, (uint2*)wo_h, (uint2*)wo_l,
        (uint2*)wg_h, (uint2*)wg_l, (uint2*)w1_h, (uint2*)w1_l,
        (uint2*)w2_h, (uint2*)w2_l, (uint2*)emb_h, (uint2*)emb_l);

    dim3 attng(T_SEQ / 64, 16, 2);

    embed_kernel<<<BT, 256>>>(x, embed, pos, h);

    for (int l = 0; l < NLAYER; l++) {
        ln_kernel<<<BT, 256>>>(h, ln1_g + l * D_MODEL, ln1_b + l * D_MODEL, n, ah, al);
        // qkv1 (bf16 hi/lo out)
        gemm_tc<<<dim3(3072/128, BT/128), 256, GSMEM>>>(
            ah, al, nullptr, nullptr, 1 << 30, D_MODEL, 0,
            wqkv_h + (size_t)(l*2+0)*3072*D_MODEL, wqkv_l + (size_t)(l*2+0)*3072*D_MODEL,
            bqkv + (l*2+0)*3072, nullptr, nullptr,
            nullptr, qh, ql, BT, 3072, D_MODEL, 0);
        // attn1 -> pred + diff split
        attn_mma<<<attng, 128, AT_SMEM>>>(qh, ql, n, pred, ph, pl, ah, al);
        // qkv2
        gemm_tc<<<dim3(3072/128, BT/128), 256, GSMEM>>>(
            ah, al, nullptr, nullptr, 1 << 30, D_MODEL, 0,
            wqkv_h + (size_t)(l*2+1)*3072*D_MODEL, wqkv_l + (size_t)(l*2+1)*3072*D_MODEL,
            bqkv + (l*2+1)*3072, nullptr, nullptr,
            nullptr, qh, ql, BT, 3072, D_MODEL, 0);
        // attn2 -> corr
        attn_mma<<<attng, 128, AT_SMEM>>>(qh, ql, nullptr, corr, ch, cl, nullptr, nullptr);
        // gated = pred + sigmoid([pred|corr]@Wg^T + bg)*corr
        gemm_tc<<<dim3(D_MODEL/128, BT/128), 256, GSMEM>>>(
            ph, pl, ch, cl, D_MODEL, D_MODEL, D_MODEL,
            wg_h + (size_t)l*D_MODEL*2*D_MODEL, wg_l + (size_t)l*D_MODEL*2*D_MODEL,
            bg + l*D_MODEL, pred, corr,
            nullptr, ah, al, BT, D_MODEL, 2*D_MODEL, 3);
        // h += gated @ Wo^T + bo
        gemm_tc<<<dim3(D_MODEL/128, BT/128), 256, GSMEM>>>(
            ah, al, nullptr, nullptr, 1 << 30, D_MODEL, 0,
            wo_h + (size_t)l*D_MODEL*D_MODEL, wo_l + (size_t)l*D_MODEL*D_MODEL,
            bo + l*D_MODEL, h, nullptr,
            h, nullptr, nullptr, BT, D_MODEL, D_MODEL, 1);
        // FF
        ln_kernel<<<BT, 256>>>(h, ln2_g + l * D_MODEL, ln2_b + l * D_MODEL, nullptr, ah, al);
        gemm_tc<<<dim3(FF_DIM/128, BT/128), 256, GSMEM>>>(
            ah, al, nullptr, nullptr, 1 << 30, D_MODEL, 0,
            w1_h + (size_t)l*FF_DIM*D_MODEL, w1_l + (size_t)l*FF_DIM*D_MODEL,
            b1 + l*FF_DIM, nullptr, nullptr,
            nullptr, fh, fl, BT, FF_DIM, D_MODEL, 2);
        gemm_tc<<<dim3(D_MODEL/128, BT/128), 256, GSMEM>>>(
            fh, fl, nullptr, nullptr, 1 << 30, FF_DIM, 0,
            w2_h + (size_t)l*D_MODEL*FF_DIM, w2_l + (size_t)l*D_MODEL*FF_DIM,
            b2 + l*D_MODEL, h, nullptr,
            h, nullptr, nullptr, BT, D_MODEL, FF_DIM, 1);
    }

    ln_kernel<<<BT, 256>>>(h, lnf_g, lnf_b, nullptr, ah, al);
    gemm_tc<<<dim3(VOCAB/128, BT/128), 256, GSMEM>>>(
        ah, al, nullptr, nullptr, 1 << 30, D_MODEL, 0,
        emb_h, emb_l, nullptr, nullptr, nullptr,
        out, nullptr, nullptr, BT, VOCAB, D_MODEL, 0);
}

// round 6
// speedup vs baseline: 3.0978x; 1.2322x over previous
#include <cuda_runtime.h>
#include <cuda_bf16.h>
#include <cuda_fp16.h>
#include <stdint.h>
#include <math.h>

#define T_SEQ   1024
#define D_MODEL 1024
#define NLAYER  4
#define FF_DIM  4096
#define VOCAB   32000
#define BT      2048
#define ATT_SCALE 0.125f

// ---------------- fp32 scratch ----------------------------------------------
__device__ float g_h   [BT * D_MODEL];
__device__ float g_n   [BT * D_MODEL];
__device__ float g_pred[BT * D_MODEL];
__device__ float g_corr[BT * D_MODEL];

// ---------------- bf16 hi/lo activation scratch -----------------------------
__device__ __align__(16) __nv_bfloat16 g_ah[BT * FF_DIM];
__device__ __align__(16) __nv_bfloat16 g_al[BT * FF_DIM];
__device__ __align__(16) __nv_bfloat16 g_fh[BT * FF_DIM];
__device__ __align__(16) __nv_bfloat16 g_fl[BT * FF_DIM];
__device__ __align__(16) __nv_bfloat16 g_ph[BT * D_MODEL], g_pl[BT * D_MODEL];
__device__ __align__(16) __nv_bfloat16 g_ch[BT * D_MODEL], g_cl[BT * D_MODEL];
__device__ __align__(16) __nv_bfloat16 g_qkvh[BT * 3 * D_MODEL];
__device__ __align__(16) __nv_bfloat16 g_qkvl[BT * 3 * D_MODEL];
__device__ __align__(16) __half        g_a16 [BT * D_MODEL];

// ---------------- weights ----------------------------------------------------
#define SZ_WQKV (NLAYER * 2 * 3 * D_MODEL * D_MODEL)
#define SZ_WO   (NLAYER * D_MODEL * D_MODEL)
#define SZ_WG   (NLAYER * D_MODEL * 2 * D_MODEL)
#define SZ_W1   (NLAYER * FF_DIM * D_MODEL)
#define SZ_W2   (NLAYER * D_MODEL * FF_DIM)
#define SZ_EMB  (VOCAB * D_MODEL)
__device__ __align__(16) __nv_bfloat16 g_wqkv_h[SZ_WQKV], g_wqkv_l[SZ_WQKV];
__device__ __align__(16) __nv_bfloat16 g_wo_h  [SZ_WO],   g_wo_l  [SZ_WO];
__device__ __align__(16) __nv_bfloat16 g_wg_h  [SZ_WG],   g_wg_l  [SZ_WG];
__device__ __align__(16) __nv_bfloat16 g_w1_h  [SZ_W1],   g_w1_l  [SZ_W1];
__device__ __align__(16) __nv_bfloat16 g_w2_h  [SZ_W2],   g_w2_l  [SZ_W2];
__device__ __align__(16) __half        g_embf_h[SZ_EMB],  g_embf_l[SZ_EMB];

// ---------------- helpers ----------------------------------------------------
__device__ __forceinline__ void splt(float x, __nv_bfloat16& h, __nv_bfloat16& l) {
    h = __float2bfloat16_rn(x);
    l = __float2bfloat16_rn(x - __bfloat162float(h));
}
__device__ __forceinline__ void pack_hl(float x, float y, uint32_t& h, uint32_t& l) {
    __nv_bfloat16 h0 = __float2bfloat16_rn(x), h1 = __float2bfloat16_rn(y);
    __nv_bfloat16 l0 = __float2bfloat16_rn(x - __bfloat162float(h0));
    __nv_bfloat16 l1 = __float2bfloat16_rn(y - __bfloat162float(h1));
    h = (uint32_t)__bfloat16_as_ushort(h0) | ((uint32_t)__bfloat16_as_ushort(h1) << 16);
    l = (uint32_t)__bfloat16_as_ushort(l0) | ((uint32_t)__bfloat16_as_ushort(l1) << 16);
}
__device__ __forceinline__ uint32_t smem_u32(const void* p) {
    uint32_t a;
    asm("{ .reg .u64 t; cvta.to.shared.u64 t, %1; cvt.u32.u64 %0, t; }" : "=r"(a) : "l"(p));
    return a;
}
__device__ __forceinline__ void cp16(uint32_t s, const void* g) {
    asm volatile("cp.async.cg.shared.global [%0], [%1], 16;" :: "r"(s), "l"(g));
}
#define CP_COMMIT() asm volatile("cp.async.commit_group;" ::: "memory")
#define CP_WAIT1()  asm volatile("cp.async.wait_group 1;" ::: "memory")

__device__ __forceinline__ void ldmx4(uint32_t a, uint32_t& r0, uint32_t& r1,
                                      uint32_t& r2, uint32_t& r3) {
    asm volatile("ldmatrix.sync.aligned.m8n8.x4.shared.b16 {%0,%1,%2,%3}, [%4];"
                 : "=r"(r0), "=r"(r1), "=r"(r2), "=r"(r3) : "r"(a));
}
__device__ __forceinline__ void ldmx4t(uint32_t a, uint32_t& r0, uint32_t& r1,
                                       uint32_t& r2, uint32_t& r3) {
    asm volatile("ldmatrix.sync.aligned.m8n8.x4.trans.shared.b16 {%0,%1,%2,%3}, [%4];"
                 : "=r"(r0), "=r"(r1), "=r"(r2), "=r"(r3) : "r"(a));
}
__device__ __forceinline__ void mma16816(float* d, const uint32_t* a, const uint32_t* b) {
    asm volatile("mma.sync.aligned.m16n8k16.row.col.f32.bf16.bf16.f32 "
                 "{%0,%1,%2,%3}, {%4,%5,%6,%7}, {%8,%9}, {%0,%1,%2,%3};"
                 : "+f"(d[0]), "+f"(d[1]), "+f"(d[2]), "+f"(d[3])
                 : "r"(a[0]), "r"(a[1]), "r"(a[2]), "r"(a[3]), "r"(b[0]), "r"(b[1]));
}
__device__ __forceinline__ void mma16816h(float* d, const uint32_t* a, const uint32_t* b) {
    asm volatile("mma.sync.aligned.m16n8k16.row.col.f32.f16.f16.f32 "
                 "{%0,%1,%2,%3}, {%4,%5,%6,%7}, {%8,%9}, {%0,%1,%2,%3};"
                 : "+f"(d[0]), "+f"(d[1]), "+f"(d[2]), "+f"(d[3])
                 : "r"(a[0]), "r"(a[1]), "r"(a[2]), "r"(a[3]), "r"(b[0]), "r"(b[1]));
}

// ---------------- one-shot weight split -------------------------------------
#define Q0 (SZ_WQKV/4)
#define Q1 (Q0 + SZ_WO/4)
#define Q2 (Q1 + SZ_WG/4)
#define Q3 (Q2 + SZ_W1/4)
#define Q4 (Q3 + SZ_W2/4)
#define Q5 (Q4 + SZ_EMB/4)
__global__ void split_all(
    const float4* w0, const float4* w1, const float4* w2,
    const float4* w3, const float4* w4, const float4* w5,
    uint2* h0, uint2* l0, uint2* h1, uint2* l1, uint2* h2, uint2* l2,
    uint2* h3, uint2* l3, uint2* h4, uint2* l4,
    uint2* fh5, uint2* fl5)
{
    long i = (long)blockIdx.x * 256 + threadIdx.x;
    if (i >= Q5) return;
    if (i >= Q4) {
        // embed -> fp16 hi/lo pair (for logits gemm)
        long off = i - Q4;
        float4 v = w5[off];
        float vv[4] = {v.x, v.y, v.z, v.w};
        uint32_t H[2] = {0, 0}, L[2] = {0, 0};
        #pragma unroll
        for (int k = 0; k < 4; k++) {
            __half hh = __float2half_rn(vv[k]);
            __half ll = __float2half_rn(vv[k] - __half2float(hh));
            H[k >> 1] |= (uint32_t)__half_as_ushort(hh) << ((k & 1) * 16);
            L[k >> 1] |= (uint32_t)__half_as_ushort(ll) << ((k & 1) * 16);
        }
        fh5[off] = make_uint2(H[0], H[1]);
        fl5[off] = make_uint2(L[0], L[1]);
        return;
    }
    const float4* src; uint2 *hi, *lo; long off;
    if      (i < Q0) { src = w0; hi = h0; lo = l0; off = i; }
    else if (i < Q1) { src = w1; hi = h1; lo = l1; off = i - Q0; }
    else if (i < Q2) { src = w2; hi = h2; lo = l2; off = i - Q1; }
    else if (i < Q3) { src = w3; hi = h3; lo = l3; off = i - Q2; }
    else             { src = w4; hi = h4; lo = l4; off = i - Q3; }
    float4 v = src[off];
    __nv_bfloat16 a0, a1, a2, a3, b0, b1, b2, b3;
    splt(v.x, a0, b0); splt(v.y, a1, b1); splt(v.z, a2, b2); splt(v.w, a3, b3);
    uint2 H, L;
    H.x = (uint32_t)__bfloat16_as_ushort(a0) | ((uint32_t)__bfloat16_as_ushort(a1) << 16);
    H.y = (uint32_t)__bfloat16_as_ushort(a2) | ((uint32_t)__bfloat16_as_ushort(a3) << 16);
    L.x = (uint32_t)__bfloat16_as_ushort(b0) | ((uint32_t)__bfloat16_as_ushort(b1) << 16);
    L.y = (uint32_t)__bfloat16_as_ushort(b2) | ((uint32_t)__bfloat16_as_ushort(b3) << 16);
    hi[off] = H; lo[off] = L;
}

// ---------------- GEMM (bf16 3-mma, 128x64 tile, KC=64) ----------------------
#define KC     64
#define SROW   144
#define AOFF_H 0
#define AOFF_L 18432
#define BOFF_H 36864
#define BOFF_L 46080
#define STG    55296
#define GSMEM  (2 * STG)

__global__ __launch_bounds__(256, 2) void gemm_tc(
    const __nv_bfloat16* __restrict__ Ah, const __nv_bfloat16* __restrict__ Al,
    const __nv_bfloat16* __restrict__ Ah2, const __nv_bfloat16* __restrict__ Al2,
    int kSplit, int lda1, int lda2,
    const __nv_bfloat16* __restrict__ Wh, const __nv_bfloat16* __restrict__ Wl,
    const float* __restrict__ bias, const float* __restrict__ res,
    const float* __restrict__ corr,
    float* __restrict__ Cf, __nv_bfloat16* __restrict__ Ch, __nv_bfloat16* __restrict__ Cl,
    int M, int N, int K, int epi)
{
    extern __shared__ char smem[];
    uint32_t sb = smem_u32(smem);
    int tid = threadIdx.x, lane = tid & 31, w = tid >> 5;
    int wm = w & 3, wn = w >> 2;
    int bm = blockIdx.y * 128, bn = blockIdx.x * 64;

    float acc[2][4][4];
    #pragma unroll
    for (int i = 0; i < 2; i++)
        #pragma unroll
        for (int j = 0; j < 4; j++)
            #pragma unroll
            for (int e = 0; e < 4; e++) acc[i][j][e] = 0.f;

    int nk = K / KC;

    auto load_chunk = [&](int kc, uint32_t s) {
        int kb = kc * KC;
        #pragma unroll
        for (int it = 0; it < 12; it++) {
            int i = tid + it * 256;
            if (i < 2048) {                       // A hi/lo
                int hf = i >> 10;
                int ww = i & 1023;
                int row = ww >> 3, c = ww & 7;
                int kcol = kb + c * 8;
                const __nv_bfloat16* src; size_t go;
                if (kcol < kSplit) {
                    src = hf ? Al : Ah;
                    go = (size_t)(bm + row) * lda1 + kcol;
                } else {
                    src = hf ? Al2 : Ah2;
                    go = (size_t)(bm + row) * lda2 + (kcol - kSplit);
                }
                cp16(s + (hf ? AOFF_L : AOFF_H) + row * SROW + c * 16, src + go);
            } else {                              // B hi/lo
                int ii = i - 2048;
                int hf = ii >> 9;
                int ww = ii & 511;
                int row = ww >> 3, c = ww & 7;
                size_t go = (size_t)(bn + row) * K + kb + c * 8;
                cp16(s + (hf ? BOFF_L : BOFF_H) + row * SROW + c * 16, (hf ? Wl : Wh) + go);
            }
        }
    };

    load_chunk(0, sb);
    CP_COMMIT();

    for (int kc = 0; kc < nk; kc++) {
        if (kc + 1 < nk) load_chunk(kc + 1, sb + ((kc + 1) & 1) * STG);
        CP_COMMIT();
        CP_WAIT1();
        __syncthreads();

        uint32_t s = sb + (kc & 1) * STG;
        #pragma unroll
        for (int t = 0; t < 4; t++) {
            uint32_t arow = wm * 32 + (lane & 15);
            uint32_t ak = (t * 16 + (lane >> 4) * 8) * 2;
            uint32_t ahr[2][4], alr[2][4];
            #pragma unroll
            for (int mg = 0; mg < 2; mg++) {
                uint32_t aoff = (arow + mg * 16) * SROW + ak;
                ldmx4(s + AOFF_H + aoff, ahr[mg][0], ahr[mg][1], ahr[mg][2], ahr[mg][3]);
                ldmx4(s + AOFF_L + aoff, alr[mg][0], alr[mg][1], alr[mg][2], alr[mg][3]);
            }
            #pragma unroll
            for (int ng = 0; ng < 2; ng++) {
                uint32_t brow = wn * 32 + ng * 16 + (lane & 7) + ((lane >> 4) << 3);
                uint32_t boff = brow * SROW + (t * 16 + ((lane >> 3) & 1) * 8) * 2;
                uint32_t bh[4], bl[4];
                ldmx4(s + BOFF_H + boff, bh[0], bh[1], bh[2], bh[3]);
                ldmx4(s + BOFF_L + boff, bl[0], bl[1], bl[2], bl[3]);
                #pragma unroll
                for (int mg = 0; mg < 2; mg++) {
                    mma16816(acc[mg][ng*2+0], ahr[mg], &bh[0]);
                    mma16816(acc[mg][ng*2+1], ahr[mg], &bh[2]);
                    mma16816(acc[mg][ng*2+0], ahr[mg], &bl[0]);
                    mma16816(acc[mg][ng*2+1], ahr[mg], &bl[2]);
                    mma16816(acc[mg][ng*2+0], alr[mg], &bh[0]);
                    mma16816(acc[mg][ng*2+1], alr[mg], &bh[2]);
                }
            }
        }
        __syncthreads();
    }

    #pragma unroll
    for (int mg = 0; mg < 2; mg++) {
        #pragma unroll
        for (int j = 0; j < 4; j++) {
            int m0 = bm + wm * 32 + mg * 16 + (lane >> 2);
            int n0 = bn + wn * 32 + j * 8 + (lane & 3) * 2;
            #pragma unroll
            for (int e = 0; e < 4; e++) {
                int m = m0 + (e >> 1) * 8;
                int n = n0 + (e & 1);
                size_t idx = (size_t)m * N + n;
                float v = acc[mg][j][e];
                if (bias) v += bias[n];
                if (epi == 1)      v += res[idx];
                else if (epi == 2) v = 0.5f * v * (1.f + erff(v * 0.70710678118f));
                else if (epi == 3) v = res[idx] + corr[idx] / (1.f + __expf(-v));
                if (Cf) Cf[idx] = v;
                if (Ch) {
                    __nv_bfloat16 hh, ll;
                    splt(v, hh, ll);
                    Ch[idx] = hh;
                    Cl[idx] = ll;
                }
            }
        }
    }
}

// ---------------- logits GEMM (fp16, 2-mma: Ah*Wh + Ah*Wl) -------------------
#define FAOFF  0
#define FBH    18432
#define FBL    27648
#define FSTG   36864
#define FSMEM  (2 * FSTG)

__global__ __launch_bounds__(256, 3) void gemm_f16(
    const __half* __restrict__ Ah,
    const __half* __restrict__ Wh, const __half* __restrict__ Wl,
    float* __restrict__ Cf, int M, int N, int K)
{
    extern __shared__ char smem[];
    uint32_t sb = smem_u32(smem);
    int tid = threadIdx.x, lane = tid & 31, w = tid >> 5;
    int wm = w & 3, wn = w >> 2;
    int bm = blockIdx.y * 128, bn = blockIdx.x * 64;

    float acc[2][4][4];
    #pragma unroll
    for (int i = 0; i < 2; i++)
        #pragma unroll
        for (int j = 0; j < 4; j++)
            #pragma unroll
            for (int e = 0; e < 4; e++) acc[i][j][e] = 0.f;

    int nk = K / KC;

    auto load_chunk = [&](int kc, uint32_t s) {
        int kb = kc * KC;
        #pragma unroll
        for (int it = 0; it < 8; it++) {
            int i = tid + it * 256;
            if (i < 1024) {                       // A
                int row = i >> 3, c = i & 7;
                size_t go = (size_t)(bm + row) * K + kb + c * 8;
                cp16(s + FAOFF + row * SROW + c * 16, Ah + go);
            } else {                              // B hi/lo
                int ii = i - 1024;
                int hf = ii >> 9;
                int ww = ii & 511;
                int row = ww >> 3, c = ww & 7;
                size_t go = (size_t)(bn + row) * K + kb + c * 8;
                cp16(s + (hf ? FBL : FBH) + row * SROW + c * 16, (hf ? Wl : Wh) + go);
            }
        }
    };

    load_chunk(0, sb);
    CP_COMMIT();

    for (int kc = 0; kc < nk; kc++) {
        if (kc + 1 < nk) load_chunk(kc + 1, sb + ((kc + 1) & 1) * FSTG);
        CP_COMMIT();
        CP_WAIT1();
        __syncthreads();

        uint32_t s = sb + (kc & 1) * FSTG;
        #pragma unroll
        for (int t = 0; t < 4; t++) {
            uint32_t arow = wm * 32 + (lane & 15);
            uint32_t ak = (t * 16 + (lane >> 4) * 8) * 2;
            uint32_t ahr[2][4];
            #pragma unroll
            for (int mg = 0; mg < 2; mg++) {
                uint32_t aoff = (arow + mg * 16) * SROW + ak;
                ldmx4(s + FAOFF + aoff, ahr[mg][0], ahr[mg][1], ahr[mg][2], ahr[mg][3]);
            }
            #pragma unroll
            for (int ng = 0; ng < 2; ng++) {
                uint32_t brow = wn * 32 + ng * 16 + (lane & 7) + ((lane >> 4) << 3);
                uint32_t boff = brow * SROW + (t * 16 + ((lane >> 3) & 1) * 8) * 2;
                uint32_t bh[4], bl[4];
                ldmx4(s + FBH + boff, bh[0], bh[1], bh[2], bh[3]);
                ldmx4(s + FBL + boff, bl[0], bl[1], bl[2], bl[3]);
                #pragma unroll
                for (int mg = 0; mg < 2; mg++) {
                    mma16816h(acc[mg][ng*2+0], ahr[mg], &bh[0]);
                    mma16816h(acc[mg][ng*2+1], ahr[mg], &bh[2]);
                    mma16816h(acc[mg][ng*2+0], ahr[mg], &bl[0]);
                    mma16816h(acc[mg][ng*2+1], ahr[mg], &bl[2]);
                }
            }
        }
        __syncthreads();
    }

    #pragma unroll
    for (int mg = 0; mg < 2; mg++) {
        #pragma unroll
        for (int j = 0; j < 4; j++) {
            int m0 = bm + wm * 32 + mg * 16 + (lane >> 2);
            int n0 = bn + wn * 32 + j * 8 + (lane & 3) * 2;
            #pragma unroll
            for (int e = 0; e < 4; e++) {
                int m = m0 + (e >> 1) * 8;
                int n = n0 + (e & 1);
                Cf[(size_t)m * N + n] = acc[mg][j][e];
            }
        }
    }
}

// ---------------- embedding ------------------------------------------------
__global__ void embed_kernel(const int* __restrict__ x, const float* __restrict__ emb,
                             const float* __restrict__ pos, float* __restrict__ h) {
    int row = blockIdx.x;
    int t   = row & (T_SEQ - 1);
    int tok = x[row];
    const float* e = emb + (size_t)tok * D_MODEL;
    const float* p = pos + (size_t)t   * D_MODEL;
    float* o = h + (size_t)row * D_MODEL;
    for (int d = threadIdx.x; d < D_MODEL; d += blockDim.x)
        o[d] = e[d] + p[d];
}

// ---------------- layernorm -------------------------------------------------
__global__ void ln_kernel(const float* __restrict__ in, const float* __restrict__ g,
                          const float* __restrict__ b, float* __restrict__ of,
                          __nv_bfloat16* __restrict__ oh, __nv_bfloat16* __restrict__ ol,
                          __half* __restrict__ o16) {
    int row = blockIdx.x;
    const float* x = in + (size_t)row * D_MODEL;
    int tid = threadIdx.x;
    float s = 0.f, ss = 0.f;
    for (int d = tid; d < D_MODEL; d += 256) { float v = x[d]; s += v; ss += v * v; }
    #pragma unroll
    for (int off = 16; off; off >>= 1) {
        s  += __shfl_xor_sync(0xffffffffu, s,  off);
        ss += __shfl_xor_sync(0xffffffffu, ss, off);
    }
    __shared__ float shs[8], shss[8];
    if ((tid & 31) == 0) { shs[tid >> 5] = s; shss[tid >> 5] = ss; }
    __syncthreads();
    float tots = 0.f, totss = 0.f;
    #pragma unroll
    for (int i = 0; i < 8; i++) { tots += shs[i]; totss += shss[i]; }
    float mean = tots * (1.f / D_MODEL);
    float var  = totss * (1.f / D_MODEL) - mean * mean;
    float rstd = rsqrtf(var + 1e-5f);
    for (int d = tid; d < D_MODEL; d += 256) {
        float v = (x[d] - mean) * rstd * g[d] + b[d];
        size_t idx = (size_t)row * D_MODEL + d;
        if (of) of[idx] = v;
        if (oh) { __nv_bfloat16 hh, ll; splt(v, hh, ll); oh[idx] = hh; ol[idx] = ll; }
        if (o16) o16[idx] = __float2half_rn(v);
    }
}

// ---------------- HMMA flash attention --------------------------------------
#define AT_ROWB   144
#define AT_QH     0
#define AT_QL     9216
#define AT_STAGE0 18432
#define AT_STGSZ  36864
#define AT_KH     0
#define AT_KL     9216
#define AT_VH     18432
#define AT_VL     27648
#define AT_SMEM   (18432 + 2 * 36864)

__global__ __launch_bounds__(128, 2) void attn_mma(
    const __nv_bfloat16* __restrict__ qkvh, const __nv_bfloat16* __restrict__ qkvl,
    const float* __restrict__ nIn,
    float* __restrict__ outF,
    __nv_bfloat16* __restrict__ outH, __nv_bfloat16* __restrict__ outL,
    __nv_bfloat16* __restrict__ diffH, __nv_bfloat16* __restrict__ diffL)
{
    extern __shared__ char sm[];
    uint32_t sb = smem_u32(sm);
    int qt = blockIdx.x, hh = blockIdx.y, b = blockIdx.z;
    int tid = threadIdx.x, lane = tid & 31, wq = tid >> 5;
    int qb = wq * 16;

    #pragma unroll
    for (int it = 0; it < 8; it++) {
        int i = tid + it * 128;
        int tensor = i >> 9, ww = i & 511, row = ww >> 3, c = ww & 7;
        size_t ge = (size_t)(b * T_SEQ + qt * 64 + row) * 3072 + hh * 64 + c * 8;
        const __nv_bfloat16* src = tensor ? qkvl : qkvh;
        uint32_t dst = sb + (tensor ? AT_QL : AT_QH) + row * AT_ROWB + c * 16;
        cp16(dst, src + ge);
    }
    CP_COMMIT();

    auto load_kv = [&](int kt, int stage) {
        uint32_t stb = sb + AT_STAGE0 + stage * AT_STGSZ;
        #pragma unroll
        for (int it = 0; it < 16; it++) {
            int i = tid + it * 128;
            int tensor = i >> 9, ww = i & 511, row = ww >> 3, c = ww & 7;
            int kvoff = (tensor >= 2) ? 2048 : 1024;
            size_t ge = (size_t)(b * T_SEQ + kt * 64 + row) * 3072 + kvoff + hh * 64 + c * 8;
            const __nv_bfloat16* src = (tensor & 1) ? qkvl : qkvh;
            uint32_t toff = (tensor == 0) ? AT_KH : (tensor == 1) ? AT_KL
                          : (tensor == 2) ? AT_VH : AT_VL;
            cp16(stb + toff + row * AT_ROWB + c * 16, src + ge);
        }
    };
    load_kv(0, 0);
    CP_COMMIT();

    float O[8][4];
    #pragma unroll
    for (int j = 0; j < 8; j++)
        #pragma unroll
        for (int e = 0; e < 4; e++) O[j][e] = 0.f;
    float m0 = -1e30f, m1 = -1e30f, l0 = 0.f, l1 = 0.f;

    int r0 = qt * 64 + qb + (lane >> 2);
    int r1 = r0 + 8;

    for (int kt = 0; kt <= qt; kt++) {
        if (kt < qt) load_kv(kt + 1, (kt + 1) & 1);
        CP_COMMIT();
        CP_WAIT1();
        __syncthreads();

        uint32_t stb = sb + AT_STAGE0 + (kt & 1) * AT_STGSZ;

        float S[8][4];
        #pragma unroll
        for (int j = 0; j < 8; j++)
            #pragma unroll
            for (int e = 0; e < 4; e++) S[j][e] = 0.f;

        #pragma unroll
        for (int t = 0; t < 4; t++) {
            uint32_t qa = sb + (qb + (lane & 15)) * AT_ROWB + (t * 16 + (lane >> 4) * 8) * 2;
            uint32_t qh[4], ql[4];
            ldmx4(qa + AT_QH, qh[0], qh[1], qh[2], qh[3]);
            ldmx4(qa + AT_QL, ql[0], ql[1], ql[2], ql[3]);
            #pragma unroll
            for (int jj = 0; jj < 4; jj++) {
                uint32_t ka = stb + (jj * 16 + (lane & 7) + ((lane >> 4) << 3)) * AT_ROWB
                            + (t * 16 + ((lane >> 3) & 1) * 8) * 2;
                uint32_t kh[4], kl[4];
                ldmx4(ka + AT_KH, kh[0], kh[1], kh[2], kh[3]);
                ldmx4(ka + AT_KL, kl[0], kl[1], kl[2], kl[3]);
                mma16816(S[jj*2+0], qh, &kh[0]); mma16816(S[jj*2+1], qh, &kh[2]);
                mma16816(S[jj*2+0], qh, &kl[0]); mma16816(S[jj*2+1], qh, &kl[2]);
                mma16816(S[jj*2+0], ql, &kh[0]); mma16816(S[jj*2+1], ql, &kh[2]);
            }
        }

        int cb = kt * 64 + ((lane & 3) << 1);
        float mx0 = -1e30f, mx1 = -1e30f;
        #pragma unroll
        for (int j = 0; j < 8; j++) {
            int c0 = cb + j * 8, c1 = c0 + 1;
            float v;
            v = (c0 <= r0) ? S[j][0] * ATT_SCALE : -1e30f; S[j][0] = v; mx0 = fmaxf(mx0, v);
            v = (c1 <= r0) ? S[j][1] * ATT_SCALE : -1e30f; S[j][1] = v; mx0 = fmaxf(mx0, v);
            v = (c0 <= r1) ? S[j][2] * ATT_SCALE : -1e30f; S[j][2] = v; mx1 = fmaxf(mx1, v);
            v = (c1 <= r1) ? S[j][3] * ATT_SCALE : -1e30f; S[j][3] = v; mx1 = fmaxf(mx1, v);
        }
        mx0 = fmaxf(mx0, __shfl_xor_sync(0xffffffffu, mx0, 1));
        mx0 = fmaxf(mx0, __shfl_xor_sync(0xffffffffu, mx0, 2));
        mx1 = fmaxf(mx1, __shfl_xor_sync(0xffffffffu, mx1, 1));
        mx1 = fmaxf(mx1, __shfl_xor_sync(0xffffffffu, mx1, 2));
        float mn0 = fmaxf(m0, mx0), mn1 = fmaxf(m1, mx1);
        float a0 = __expf(m0 - mn0), a1 = __expf(m1 - mn1);
        m0 = mn0; m1 = mn1;
        float s0 = 0.f, s1 = 0.f;
        #pragma unroll
        for (int j = 0; j < 8; j++) {
            S[j][0] = __expf(S[j][0] - m0); s0 += S[j][0];
            S[j][1] = __expf(S[j][1] - m0); s0 += S[j][1];
            S[j][2] = __expf(S[j][2] - m1); s1 += S[j][2];
            S[j][3] = __expf(S[j][3] - m1); s1 += S[j][3];
        }
        s0 += __shfl_xor_sync(0xffffffffu, s0, 1);
        s0 += __shfl_xor_sync(0xffffffffu, s0, 2);
        s1 += __shfl_xor_sync(0xffffffffu, s1, 1);
        s1 += __shfl_xor_sync(0xffffffffu, s1, 2);
        l0 = l0 * a0 + s0; l1 = l1 * a1 + s1;
        #pragma unroll
        for (int j = 0; j < 8; j++) {
            O[j][0] *= a0; O[j][1] *= a0; O[j][2] *= a1; O[j][3] *= a1;
        }

        #pragma unroll
        for (int t = 0; t < 4; t++) {
            uint32_t pah[4], pal[4];
            pack_hl(S[2*t  ][0], S[2*t  ][1], pah[0], pal[0]);
            pack_hl(S[2*t  ][2], S[2*t  ][3], pah[1], pal[1]);
            pack_hl(S[2*t+1][0], S[2*t+1][1], pah[2], pal[2]);
            pack_hl(S[2*t+1][2], S[2*t+1][3], pah[3], pal[3]);
            #pragma unroll
            for (int dd = 0; dd < 4; dd++) {
                uint32_t va = stb + (t * 16 + (lane & 7) + ((lane >> 3) & 1) * 8) * AT_ROWB
                            + (dd * 16 + (lane >> 4) * 8) * 2;
                uint32_t vh[4], vl[4];
                ldmx4t(va + AT_VH, vh[0], vh[1], vh[2], vh[3]);
                ldmx4t(va + AT_VL, vl[0], vl[1], vl[2], vl[3]);
                mma16816(O[dd*2+0], pah, &vh[0]); mma16816(O[dd*2+1], pah, &vh[2]);
                mma16816(O[dd*2+0], pah, &vl[0]); mma16816(O[dd*2+1], pah, &vl[2]);
                mma16816(O[dd*2+0], pal, &vh[0]); mma16816(O[dd*2+1], pal, &vh[2]);
            }
        }
        __syncthreads();
    }

    float i0 = 1.f / l0, i1 = 1.f / l1;
    int tok0 = b * T_SEQ + r0, tok1 = b * T_SEQ + r1;
    #pragma unroll
    for (int j = 0; j < 8; j++) {
        int d = hh * 64 + j * 8 + ((lane & 3) << 1);
        size_t idx0 = (size_t)tok0 * D_MODEL + d;
        size_t idx1 = (size_t)tok1 * D_MODEL + d;
        float v00 = O[j][0] * i0, v01 = O[j][1] * i0;
        float v10 = O[j][2] * i1, v11 = O[j][3] * i1;
        outF[idx0] = v00; outF[idx0 + 1] = v01;
        outF[idx1] = v10; outF[idx1 + 1] = v11;
        __nv_bfloat16 hh0, ll0, hh1, ll1;
        splt(v00, hh0, ll0); splt(v01, hh1, ll1);
        outH[idx0] = hh0; outH[idx0 + 1] = hh1;
        outL[idx0] = ll0; outL[idx0 + 1] = ll1;
        splt(v10, hh0, ll0); splt(v11, hh1, ll1);
        outH[idx1] = hh0; outH[idx1 + 1] = hh1;
        outL[idx1] = ll0; outL[idx1 + 1] = ll1;
        if (diffH) {
            float d00 = nIn[idx0] - v00, d01 = nIn[idx0 + 1] - v01;
            float d10 = nIn[idx1] - v10, d11 = nIn[idx1 + 1] - v11;
            splt(d00, hh0, ll0); splt(d01, hh1, ll1);
            diffH[idx0] = hh0; diffH[idx0 + 1] = hh1;
            diffL[idx0] = ll0; diffL[idx0 + 1] = ll1;
            splt(d10, hh0, ll0); splt(d11, hh1, ll1);
            diffH[idx1] = hh0; diffH[idx1 + 1] = hh1;
            diffL[idx1] = ll0; diffL[idx1 + 1] = ll1;
        }
    }
}

// ---------------- driver ----------------------------------------------------
extern "C" void kernel_launch(void* const* d_in, const int* in_sizes, int n_in,
                              void* d_out, int out_size) {
    const int*   x      = (const int*)  d_in[0];
    const float* embed  = (const float*)d_in[1];
    const float* pos    = (const float*)d_in[2];
    const float* Wqkv   = (const float*)d_in[3];
    const float* bqkv   = (const float*)d_in[4];
    const float* Wo     = (const float*)d_in[5];
    const float* bo     = (const float*)d_in[6];
    const float* Wg     = (const float*)d_in[7];
    const float* bg     = (const float*)d_in[8];
    const float* ln1_g  = (const float*)d_in[9];
    const float* ln1_b  = (const float*)d_in[10];
    const float* W1     = (const float*)d_in[11];
    const float* b1     = (const float*)d_in[12];
    const float* W2     = (const float*)d_in[13];
    const float* b2     = (const float*)d_in[14];
    const float* ln2_g  = (const float*)d_in[15];
    const float* ln2_b  = (const float*)d_in[16];
    const float* lnf_g  = (const float*)d_in[17];
    const float* lnf_b  = (const float*)d_in[18];
    float* out = (float*)d_out;

    cudaFuncSetAttribute(gemm_tc,  cudaFuncAttributeMaxDynamicSharedMemorySize, GSMEM);
    cudaFuncSetAttribute(gemm_f16, cudaFuncAttributeMaxDynamicSharedMemorySize, FSMEM);
    cudaFuncSetAttribute(attn_mma, cudaFuncAttributeMaxDynamicSharedMemorySize, AT_SMEM);

    float *h, *n, *pred, *corr;
    cudaGetSymbolAddress((void**)&h,    g_h);
    cudaGetSymbolAddress((void**)&n,    g_n);
    cudaGetSymbolAddress((void**)&pred, g_pred);
    cudaGetSymbolAddress((void**)&corr, g_corr);
    __nv_bfloat16 *ah, *al, *fh, *fl, *ph, *pl, *ch, *cl, *qh, *ql;
    cudaGetSymbolAddress((void**)&ah, g_ah);
    cudaGetSymbolAddress((void**)&al, g_al);
    cudaGetSymbolAddress((void**)&fh, g_fh);
    cudaGetSymbolAddress((void**)&fl, g_fl);
    cudaGetSymbolAddress((void**)&ph, g_ph);
    cudaGetSymbolAddress((void**)&pl, g_pl);
    cudaGetSymbolAddress((void**)&ch, g_ch);
    cudaGetSymbolAddress((void**)&cl, g_cl);
    cudaGetSymbolAddress((void**)&qh, g_qkvh);
    cudaGetSymbolAddress((void**)&ql, g_qkvl);
    __half *a16, *embf_h, *embf_l;
    cudaGetSymbolAddress((void**)&a16,    g_a16);
    cudaGetSymbolAddress((void**)&embf_h, g_embf_h);
    cudaGetSymbolAddress((void**)&embf_l, g_embf_l);
    __nv_bfloat16 *wqkv_h, *wqkv_l, *wo_h, *wo_l, *wg_h, *wg_l, *w1_h, *w1_l, *w2_h, *w2_l;
    cudaGetSymbolAddress((void**)&wqkv_h, g_wqkv_h); cudaGetSymbolAddress((void**)&wqkv_l, g_wqkv_l);
    cudaGetSymbolAddress((void**)&wo_h,   g_wo_h);   cudaGetSymbolAddress((void**)&wo_l,   g_wo_l);
    cudaGetSymbolAddress((void**)&wg_h,   g_wg_h);   cudaGetSymbolAddress((void**)&wg_l,   g_wg_l);
    cudaGetSymbolAddress((void**)&w1_h,   g_w1_h);   cudaGetSymbolAddress((void**)&w1_l,   g_w1_l);
    cudaGetSymbolAddress((void**)&w2_h,   g_w2_h);   cudaGetSymbolAddress((void**)&w2_l,   g_w2_l);

    split_all<<<(int)((Q5 + 255) / 256), 256>>>(
        (const float4*)Wqkv, (const float4*)Wo, (const float4*)Wg,
        (const float4*)W1, (const float4*)W2, (const float4*)embed,
        (uint2*)wqkv_h, (uint2*)wqkv_l, (uint2*)wo_h, (uint2*)wo_l,
        (uint2*)wg_h, (uint2*)wg_l, (uint2*)w1_h, (uint2*)w1_l,
        (uint2*)w2_h, (uint2*)w2_l, (uint2*)embf_h, (uint2*)embf_l);

    dim3 attng(T_SEQ / 64, 16, 2);

    embed_kernel<<<BT, 256>>>(x, embed, pos, h);

    for (int l = 0; l < NLAYER; l++) {
        ln_kernel<<<BT, 256>>>(h, ln1_g + l * D_MODEL, ln1_b + l * D_MODEL, n, ah, al, nullptr);
        gemm_tc<<<dim3(3072/64, BT/128), 256, GSMEM>>>(
            ah, al, nullptr, nullptr, 1 << 30, D_MODEL, 0,
            wqkv_h + (size_t)(l*2+0)*3072*D_MODEL, wqkv_l + (size_t)(l*2+0)*3072*D_MODEL,
            bqkv + (l*2+0)*3072, nullptr, nullptr,
            nullptr, qh, ql, BT, 3072, D_MODEL, 0);
        attn_mma<<<attng, 128, AT_SMEM>>>(qh, ql, n, pred, ph, pl, ah, al);
        gemm_tc<<<dim3(3072/64, BT/128), 256, GSMEM>>>(
            ah, al, nullptr, nullptr, 1 << 30, D_MODEL, 0,
            wqkv_h + (size_t)(l*2+1)*3072*D_MODEL, wqkv_l + (size_t)(l*2+1)*3072*D_MODEL,
            bqkv + (l*2+1)*3072, nullptr, nullptr,
            nullptr, qh, ql, BT, 3072, D_MODEL, 0);
        attn_mma<<<attng, 128, AT_SMEM>>>(qh, ql, nullptr, corr, ch, cl, nullptr, nullptr);
        gemm_tc<<<dim3(D_MODEL/64, BT/128), 256, GSMEM>>>(
            ph, pl, ch, cl, D_MODEL, D_MODEL, D_MODEL,
            wg_h + (size_t)l*D_MODEL*2*D_MODEL, wg_l + (size_t)l*D_MODEL*2*D_MODEL,
            bg + l*D_MODEL, pred, corr,
            nullptr, ah, al, BT, D_MODEL, 2*D_MODEL, 3);
        gemm_tc<<<dim3(D_MODEL/64, BT/128), 256, GSMEM>>>(
            ah, al, nullptr, nullptr, 1 << 30, D_MODEL, 0,
            wo_h + (size_t)l*D_MODEL*D_MODEL, wo_l + (size_t)l*D_MODEL*D_MODEL,
            bo + l*D_MODEL, h, nullptr,
            h, nullptr, nullptr, BT, D_MODEL, D_MODEL, 1);
        ln_kernel<<<BT, 256>>>(h, ln2_g + l * D_MODEL, ln2_b + l * D_MODEL, nullptr, ah, al, nullptr);
        gemm_tc<<<dim3(FF_DIM/64, BT/128), 256, GSMEM>>>(
            ah, al, nullptr, nullptr, 1 << 30, D_MODEL, 0,
            w1_h + (size_t)l*FF_DIM*D_MODEL, w1_l + (size_t)l*FF_DIM*D_MODEL,
            b1 + l*FF_DIM, nullptr, nullptr,
            nullptr, fh, fl, BT, FF_DIM, D_MODEL, 2);
        gemm_tc<<<dim3(D_MODEL/64, BT/128), 256, GSMEM>>>(
            fh, fl, nullptr, nullptr, 1 << 30, FF_DIM, 0,
            w2_h + (size_t)l*D_MODEL*FF_DIM, w2_l + (size_t)l*D_MODEL*FF_DIM,
            b2 + l*D_MODEL, h, nullptr,
            h, nullptr, nullptr, BT, D_MODEL, FF_DIM, 1);
    }

    ln_kernel<<<BT, 256>>>(h, lnf_g, lnf_b, nullptr, nullptr, nullptr, a16);
    gemm_f16<<<dim3(VOCAB/64, BT/128), 256, FSMEM>>>(
        a16, embf_h, embf_l, out, BT, VOCAB, D_MODEL);
}

// round 7
// speedup vs baseline: 3.0981x; 1.0001x over previous
#include <cuda_runtime.h>
#include <cuda_bf16.h>
#include <cuda_fp16.h>
#include <stdint.h>
#include <math.h>

#define T_SEQ   1024
#define D_MODEL 1024
#define NLAYER  4
#define FF_DIM  4096
#define VOCAB   32000
#define BT      2048
#define ATT_SCALE 0.125f

// ---------------- fp32 scratch ----------------------------------------------
__device__ float g_h   [BT * D_MODEL];
__device__ float g_n   [BT * D_MODEL];
__device__ float g_pred[BT * D_MODEL];
__device__ float g_corr[BT * D_MODEL];

// ---------------- bf16 hi/lo activation scratch -----------------------------
__device__ __align__(16) __nv_bfloat16 g_ah[BT * FF_DIM];
__device__ __align__(16) __nv_bfloat16 g_al[BT * FF_DIM];
__device__ __align__(16) __nv_bfloat16 g_fh[BT * FF_DIM];
__device__ __align__(16) __nv_bfloat16 g_fl[BT * FF_DIM];
__device__ __align__(16) __nv_bfloat16 g_ph[BT * D_MODEL], g_pl[BT * D_MODEL];
__device__ __align__(16) __nv_bfloat16 g_ch[BT * D_MODEL], g_cl[BT * D_MODEL];
__device__ __align__(16) __nv_bfloat16 g_qkvh[BT * 3 * D_MODEL];
__device__ __align__(16) __nv_bfloat16 g_qkvl[BT * 3 * D_MODEL];
__device__ __align__(16) __half        g_a16 [BT * D_MODEL];

// ---------------- weights ----------------------------------------------------
#define SZ_WQKV (NLAYER * 2 * 3 * D_MODEL * D_MODEL)
#define SZ_WO   (NLAYER * D_MODEL * D_MODEL)
#define SZ_WG   (NLAYER * D_MODEL * 2 * D_MODEL)
#define SZ_W1   (NLAYER * FF_DIM * D_MODEL)
#define SZ_W2   (NLAYER * D_MODEL * FF_DIM)
#define SZ_EMB  (VOCAB * D_MODEL)
__device__ __align__(16) __nv_bfloat16 g_wqkv_h[SZ_WQKV], g_wqkv_l[SZ_WQKV];
__device__ __align__(16) __nv_bfloat16 g_wo_h  [SZ_WO],   g_wo_l  [SZ_WO];
__device__ __align__(16) __nv_bfloat16 g_wg_h  [SZ_WG],   g_wg_l  [SZ_WG];
__device__ __align__(16) __nv_bfloat16 g_w1_h  [SZ_W1],   g_w1_l  [SZ_W1];
__device__ __align__(16) __nv_bfloat16 g_w2_h  [SZ_W2],   g_w2_l  [SZ_W2];
__device__ __align__(16) __half        g_embf  [SZ_EMB];

// ---------------- helpers ----------------------------------------------------
__device__ __forceinline__ void splt(float x, __nv_bfloat16& h, __nv_bfloat16& l) {
    h = __float2bfloat16_rn(x);
    l = __float2bfloat16_rn(x - __bfloat162float(h));
}
__device__ __forceinline__ void pack_hl(float x, float y, uint32_t& h, uint32_t& l) {
    __nv_bfloat16 h0 = __float2bfloat16_rn(x), h1 = __float2bfloat16_rn(y);
    __nv_bfloat16 l0 = __float2bfloat16_rn(x - __bfloat162float(h0));
    __nv_bfloat16 l1 = __float2bfloat16_rn(y - __bfloat162float(h1));
    h = (uint32_t)__bfloat16_as_ushort(h0) | ((uint32_t)__bfloat16_as_ushort(h1) << 16);
    l = (uint32_t)__bfloat16_as_ushort(l0) | ((uint32_t)__bfloat16_as_ushort(l1) << 16);
}
__device__ __forceinline__ uint32_t smem_u32(const void* p) {
    uint32_t a;
    asm("{ .reg .u64 t; cvta.to.shared.u64 t, %1; cvt.u32.u64 %0, t; }" : "=r"(a) : "l"(p));
    return a;
}
__device__ __forceinline__ void cp16(uint32_t s, const void* g) {
    asm volatile("cp.async.cg.shared.global [%0], [%1], 16;" :: "r"(s), "l"(g));
}
#define CP_COMMIT() asm volatile("cp.async.commit_group;" ::: "memory")
#define CP_WAIT1()  asm volatile("cp.async.wait_group 1;" ::: "memory")

__device__ __forceinline__ void ldmx4(uint32_t a, uint32_t& r0, uint32_t& r1,
                                      uint32_t& r2, uint32_t& r3) {
    asm volatile("ldmatrix.sync.aligned.m8n8.x4.shared.b16 {%0,%1,%2,%3}, [%4];"
                 : "=r"(r0), "=r"(r1), "=r"(r2), "=r"(r3) : "r"(a));
}
__device__ __forceinline__ void ldmx4t(uint32_t a, uint32_t& r0, uint32_t& r1,
                                       uint32_t& r2, uint32_t& r3) {
    asm volatile("ldmatrix.sync.aligned.m8n8.x4.trans.shared.b16 {%0,%1,%2,%3}, [%4];"
                 : "=r"(r0), "=r"(r1), "=r"(r2), "=r"(r3) : "r"(a));
}
__device__ __forceinline__ void mma16816(float* d, const uint32_t* a, const uint32_t* b) {
    asm volatile("mma.sync.aligned.m16n8k16.row.col.f32.bf16.bf16.f32 "
                 "{%0,%1,%2,%3}, {%4,%5,%6,%7}, {%8,%9}, {%0,%1,%2,%3};"
                 : "+f"(d[0]), "+f"(d[1]), "+f"(d[2]), "+f"(d[3])
                 : "r"(a[0]), "r"(a[1]), "r"(a[2]), "r"(a[3]), "r"(b[0]), "r"(b[1]));
}
__device__ __forceinline__ void mma16816h(float* d, const uint32_t* a, const uint32_t* b) {
    asm volatile("mma.sync.aligned.m16n8k16.row.col.f32.f16.f16.f32 "
                 "{%0,%1,%2,%3}, {%4,%5,%6,%7}, {%8,%9}, {%0,%1,%2,%3};"
                 : "+f"(d[0]), "+f"(d[1]), "+f"(d[2]), "+f"(d[3])
                 : "r"(a[0]), "r"(a[1]), "r"(a[2]), "r"(a[3]), "r"(b[0]), "r"(b[1]));
}

// ---------------- one-shot weight split -------------------------------------
#define Q0 (SZ_WQKV/4)
#define Q1 (Q0 + SZ_WO/4)
#define Q2 (Q1 + SZ_WG/4)
#define Q3 (Q2 + SZ_W1/4)
#define Q4 (Q3 + SZ_W2/4)
#define Q5 (Q4 + SZ_EMB/4)
__global__ void split_all(
    const float4* w0, const float4* w1, const float4* w2,
    const float4* w3, const float4* w4, const float4* w5,
    uint2* h0, uint2* l0, uint2* h1, uint2* l1, uint2* h2, uint2* l2,
    uint2* h3, uint2* l3, uint2* h4, uint2* l4,
    uint2* f5)
{
    long i = (long)blockIdx.x * 256 + threadIdx.x;
    if (i >= Q5) return;
    if (i >= Q4) {
        long off = i - Q4;
        float4 v = w5[off];
        float vv[4] = {v.x, v.y, v.z, v.w};
        uint32_t H[2] = {0, 0};
        #pragma unroll
        for (int k = 0; k < 4; k++) {
            __half hh = __float2half_rn(vv[k]);
            H[k >> 1] |= (uint32_t)__half_as_ushort(hh) << ((k & 1) * 16);
        }
        f5[off] = make_uint2(H[0], H[1]);
        return;
    }
    const float4* src; uint2 *hi, *lo; long off;
    if      (i < Q0) { src = w0; hi = h0; lo = l0; off = i; }
    else if (i < Q1) { src = w1; hi = h1; lo = l1; off = i - Q0; }
    else if (i < Q2) { src = w2; hi = h2; lo = l2; off = i - Q1; }
    else if (i < Q3) { src = w3; hi = h3; lo = l3; off = i - Q2; }
    else             { src = w4; hi = h4; lo = l4; off = i - Q3; }
    float4 v = src[off];
    __nv_bfloat16 a0, a1, a2, a3, b0, b1, b2, b3;
    splt(v.x, a0, b0); splt(v.y, a1, b1); splt(v.z, a2, b2); splt(v.w, a3, b3);
    uint2 H, L;
    H.x = (uint32_t)__bfloat16_as_ushort(a0) | ((uint32_t)__bfloat16_as_ushort(a1) << 16);
    H.y = (uint32_t)__bfloat16_as_ushort(a2) | ((uint32_t)__bfloat16_as_ushort(a3) << 16);
    L.x = (uint32_t)__bfloat16_as_ushort(b0) | ((uint32_t)__bfloat16_as_ushort(b1) << 16);
    L.y = (uint32_t)__bfloat16_as_ushort(b2) | ((uint32_t)__bfloat16_as_ushort(b3) << 16);
    hi[off] = H; lo[off] = L;
}

// ---------------- templated GEMM (bf16 3-mma, 128xBN tile, KC=32) ------------
// epi: 0 none, 1 +res, 2 gelu, 3 gated (res + sigmoid(acc)*corr)
#define SROW 80

template<int BN>
__global__ __launch_bounds__(256, 2) void gemm_tc(
    const __nv_bfloat16* __restrict__ Ah, const __nv_bfloat16* __restrict__ Al,
    const __nv_bfloat16* __restrict__ Ah2, const __nv_bfloat16* __restrict__ Al2,
    int kSplit, int lda1, int lda2,
    const __nv_bfloat16* __restrict__ Wh, const __nv_bfloat16* __restrict__ Wl,
    const float* __restrict__ bias, const float* __restrict__ res,
    const float* __restrict__ corr,
    float* __restrict__ Cf, __nv_bfloat16* __restrict__ Ch, __nv_bfloat16* __restrict__ Cl,
    int M, int N, int K, int epi)
{
    constexpr int ASZ  = 128 * SROW;          // bytes per A half
    constexpr int BSZ  = BN * SROW;           // bytes per B half
    constexpr int BOFF = 2 * ASZ;
    constexpr int STGB = 2 * ASZ + 2 * BSZ;
    constexpr int NG   = BN / 32;             // n16 groups per warp
    constexpr int NB16 = 128 * 8 + BN * 8;    // 16B chunks per stage
    extern __shared__ char smem[];
    uint32_t sb = smem_u32(smem);
    int tid = threadIdx.x, lane = tid & 31, w = tid >> 5;
    int wm = w & 3, wn = w >> 2;
    int bm = blockIdx.y * 128, bn = blockIdx.x * BN;

    float acc[2][NG * 2][4];
    #pragma unroll
    for (int i = 0; i < 2; i++)
        #pragma unroll
        for (int j = 0; j < NG * 2; j++)
            #pragma unroll
            for (int e = 0; e < 4; e++) acc[i][j][e] = 0.f;

    int nk = K / 32;

    auto load_chunk = [&](int kc, uint32_t s) {
        int kb = kc * 32;
        // hoisted source select (kb is uniform per chunk)
        const __nv_bfloat16 *sAh, *sAl; int lda, koff;
        if (kb < kSplit) { sAh = Ah;  sAl = Al;  lda = lda1; koff = kb; }
        else             { sAh = Ah2; sAl = Al2; lda = lda2; koff = kb - kSplit; }
        #pragma unroll
        for (int it = 0; it < NB16 / 256; it++) {
            int i = tid + it * 256;
            if (i < 1024) {                       // A hi/lo
                int hf = i >> 9, ww = i & 511;
                int row = ww >> 2, c = ww & 3;
                size_t go = (size_t)(bm + row) * lda + koff + c * 8;
                cp16(s + (hf ? ASZ : 0) + row * SROW + c * 16, (hf ? sAl : sAh) + go);
            } else {                              // B hi/lo
                int ii = i - 1024;
                int hf = ii >= BN * 4;
                int ww = ii & (BN * 4 - 1);
                int row = ww >> 2, c = ww & 3;
                size_t go = (size_t)(bn + row) * K + kb + c * 8;
                cp16(s + BOFF + (hf ? BSZ : 0) + row * SROW + c * 16, (hf ? Wl : Wh) + go);
            }
        }
    };

    load_chunk(0, sb);
    CP_COMMIT();

    for (int kc = 0; kc < nk; kc++) {
        if (kc + 1 < nk) load_chunk(kc + 1, sb + ((kc + 1) & 1) * STGB);
        CP_COMMIT();
        CP_WAIT1();
        __syncthreads();

        uint32_t s = sb + (kc & 1) * STGB;
        #pragma unroll
        for (int t = 0; t < 2; t++) {
            uint32_t arow = wm * 32 + (lane & 15);
            uint32_t ak = (t * 16 + (lane >> 4) * 8) * 2;
            uint32_t ahr[2][4], alr[2][4];
            #pragma unroll
            for (int mg = 0; mg < 2; mg++) {
                uint32_t aoff = (arow + mg * 16) * SROW + ak;
                ldmx4(s + aoff,       ahr[mg][0], ahr[mg][1], ahr[mg][2], ahr[mg][3]);
                ldmx4(s + ASZ + aoff, alr[mg][0], alr[mg][1], alr[mg][2], alr[mg][3]);
            }
            #pragma unroll
            for (int ng = 0; ng < NG; ng++) {
                uint32_t brow = wn * (BN / 2) + ng * 16 + (lane & 7) + ((lane >> 4) << 3);
                uint32_t boff = brow * SROW + (t * 16 + ((lane >> 3) & 1) * 8) * 2;
                uint32_t bh[4], bl[4];
                ldmx4(s + BOFF + boff,       bh[0], bh[1], bh[2], bh[3]);
                ldmx4(s + BOFF + BSZ + boff, bl[0], bl[1], bl[2], bl[3]);
                #pragma unroll
                for (int mg = 0; mg < 2; mg++) {
                    mma16816(acc[mg][ng*2+0], ahr[mg], &bh[0]);
                    mma16816(acc[mg][ng*2+1], ahr[mg], &bh[2]);
                    mma16816(acc[mg][ng*2+0], ahr[mg], &bl[0]);
                    mma16816(acc[mg][ng*2+1], ahr[mg], &bl[2]);
                    mma16816(acc[mg][ng*2+0], alr[mg], &bh[0]);
                    mma16816(acc[mg][ng*2+1], alr[mg], &bh[2]);
                }
            }
        }
        __syncthreads();
    }

    #pragma unroll
    for (int mg = 0; mg < 2; mg++) {
        #pragma unroll
        for (int j = 0; j < NG * 2; j++) {
            int m0 = bm + wm * 32 + mg * 16 + (lane >> 2);
            int n0 = bn + wn * (BN / 2) + j * 8 + (lane & 3) * 2;
            #pragma unroll
            for (int e = 0; e < 4; e++) {
                int m = m0 + (e >> 1) * 8;
                int n = n0 + (e & 1);
                size_t idx = (size_t)m * N + n;
                float v = acc[mg][j][e];
                if (bias) v += bias[n];
                if (epi == 1)      v += res[idx];
                else if (epi == 2) v = 0.5f * v * (1.f + erff(v * 0.70710678118f));
                else if (epi == 3) v = res[idx] + corr[idx] / (1.f + __expf(-v));
                if (Cf) Cf[idx] = v;
                if (Ch) {
                    __nv_bfloat16 hh, ll;
                    splt(v, hh, ll);
                    Ch[idx] = hh;
                    Cl[idx] = ll;
                }
            }
        }
    }
}

// ---------------- logits GEMM (fp16, 1-mma, 128x64, KC=64) -------------------
#define FROW  144
#define FB    18432
#define FSTG  27648
#define FSMEM (2 * FSTG)

__global__ __launch_bounds__(256, 3) void gemm_f16(
    const __half* __restrict__ Ah, const __half* __restrict__ Wh,
    float* __restrict__ Cf, int M, int N, int K)
{
    extern __shared__ char smem[];
    uint32_t sb = smem_u32(smem);
    int tid = threadIdx.x, lane = tid & 31, w = tid >> 5;
    int wm = w & 3, wn = w >> 2;
    int bm = blockIdx.y * 128, bn = blockIdx.x * 64;

    float acc[2][4][4];
    #pragma unroll
    for (int i = 0; i < 2; i++)
        #pragma unroll
        for (int j = 0; j < 4; j++)
            #pragma unroll
            for (int e = 0; e < 4; e++) acc[i][j][e] = 0.f;

    int nk = K / 64;

    auto load_chunk = [&](int kc, uint32_t s) {
        int kb = kc * 64;
        #pragma unroll
        for (int it = 0; it < 6; it++) {
            int i = tid + it * 256;
            if (i < 1024) {                       // A
                int row = i >> 3, c = i & 7;
                size_t go = (size_t)(bm + row) * K + kb + c * 8;
                cp16(s + row * FROW + c * 16, Ah + go);
            } else {                              // B
                int ii = i - 1024;
                int row = ii >> 3, c = ii & 7;
                size_t go = (size_t)(bn + row) * K + kb + c * 8;
                cp16(s + FB + row * FROW + c * 16, Wh + go);
            }
        }
    };

    load_chunk(0, sb);
    CP_COMMIT();

    for (int kc = 0; kc < nk; kc++) {
        if (kc + 1 < nk) load_chunk(kc + 1, sb + ((kc + 1) & 1) * FSTG);
        CP_COMMIT();
        CP_WAIT1();
        __syncthreads();

        uint32_t s = sb + (kc & 1) * FSTG;
        #pragma unroll
        for (int t = 0; t < 4; t++) {
            uint32_t arow = wm * 32 + (lane & 15);
            uint32_t ak = (t * 16 + (lane >> 4) * 8) * 2;
            uint32_t ahr[2][4];
            #pragma unroll
            for (int mg = 0; mg < 2; mg++) {
                uint32_t aoff = (arow + mg * 16) * FROW + ak;
                ldmx4(s + aoff, ahr[mg][0], ahr[mg][1], ahr[mg][2], ahr[mg][3]);
            }
            #pragma unroll
            for (int ng = 0; ng < 2; ng++) {
                uint32_t brow = wn * 32 + ng * 16 + (lane & 7) + ((lane >> 4) << 3);
                uint32_t boff = brow * FROW + (t * 16 + ((lane >> 3) & 1) * 8) * 2;
                uint32_t bw[4];
                ldmx4(s + FB + boff, bw[0], bw[1], bw[2], bw[3]);
                #pragma unroll
                for (int mg = 0; mg < 2; mg++) {
                    mma16816h(acc[mg][ng*2+0], ahr[mg], &bw[0]);
                    mma16816h(acc[mg][ng*2+1], ahr[mg], &bw[2]);
                }
            }
        }
        __syncthreads();
    }

    #pragma unroll
    for (int mg = 0; mg < 2; mg++) {
        #pragma unroll
        for (int j = 0; j < 4; j++) {
            int m0 = bm + wm * 32 + mg * 16 + (lane >> 2);
            int n0 = bn + wn * 32 + j * 8 + (lane & 3) * 2;
            #pragma unroll
            for (int e = 0; e < 4; e++) {
                int m = m0 + (e >> 1) * 8;
                int n = n0 + (e & 1);
                Cf[(size_t)m * N + n] = acc[mg][j][e];
            }
        }
    }
}

// ---------------- embedding ------------------------------------------------
__global__ void embed_kernel(const int* __restrict__ x, const float* __restrict__ emb,
                             const float* __restrict__ pos, float* __restrict__ h) {
    int row = blockIdx.x;
    int t   = row & (T_SEQ - 1);
    int tok = x[row];
    const float* e = emb + (size_t)tok * D_MODEL;
    const float* p = pos + (size_t)t   * D_MODEL;
    float* o = h + (size_t)row * D_MODEL;
    for (int d = threadIdx.x; d < D_MODEL; d += blockDim.x)
        o[d] = e[d] + p[d];
}

// ---------------- layernorm -------------------------------------------------
__global__ void ln_kernel(const float* __restrict__ in, const float* __restrict__ g,
                          const float* __restrict__ b, float* __restrict__ of,
                          __nv_bfloat16* __restrict__ oh, __nv_bfloat16* __restrict__ ol,
                          __half* __restrict__ o16) {
    int row = blockIdx.x;
    const float* x = in + (size_t)row * D_MODEL;
    int tid = threadIdx.x;
    float s = 0.f, ss = 0.f;
    for (int d = tid; d < D_MODEL; d += 256) { float v = x[d]; s += v; ss += v * v; }
    #pragma unroll
    for (int off = 16; off; off >>= 1) {
        s  += __shfl_xor_sync(0xffffffffu, s,  off);
        ss += __shfl_xor_sync(0xffffffffu, ss, off);
    }
    __shared__ float shs[8], shss[8];
    if ((tid & 31) == 0) { shs[tid >> 5] = s; shss[tid >> 5] = ss; }
    __syncthreads();
    float tots = 0.f, totss = 0.f;
    #pragma unroll
    for (int i = 0; i < 8; i++) { tots += shs[i]; totss += shss[i]; }
    float mean = tots * (1.f / D_MODEL);
    float var  = totss * (1.f / D_MODEL) - mean * mean;
    float rstd = rsqrtf(var + 1e-5f);
    for (int d = tid; d < D_MODEL; d += 256) {
        float v = (x[d] - mean) * rstd * g[d] + b[d];
        size_t idx = (size_t)row * D_MODEL + d;
        if (of) of[idx] = v;
        if (oh) { __nv_bfloat16 hh, ll; splt(v, hh, ll); oh[idx] = hh; ol[idx] = ll; }
        if (o16) o16[idx] = __float2half_rn(v);
    }
}

// ---------------- HMMA flash attention --------------------------------------
#define AT_ROWB   144
#define AT_QH     0
#define AT_QL     9216
#define AT_STAGE0 18432
#define AT_STGSZ  36864
#define AT_KH     0
#define AT_KL     9216
#define AT_VH     18432
#define AT_VL     27648
#define AT_SMEM   (18432 + 2 * 36864)

__global__ __launch_bounds__(128, 2) void attn_mma(
    const __nv_bfloat16* __restrict__ qkvh, const __nv_bfloat16* __restrict__ qkvl,
    const float* __restrict__ nIn,
    float* __restrict__ outF,
    __nv_bfloat16* __restrict__ outH, __nv_bfloat16* __restrict__ outL,
    __nv_bfloat16* __restrict__ diffH, __nv_bfloat16* __restrict__ diffL)
{
    extern __shared__ char sm[];
    uint32_t sb = smem_u32(sm);
    int qt = blockIdx.x, hh = blockIdx.y, b = blockIdx.z;
    int tid = threadIdx.x, lane = tid & 31, wq = tid >> 5;
    int qb = wq * 16;

    #pragma unroll
    for (int it = 0; it < 8; it++) {
        int i = tid + it * 128;
        int tensor = i >> 9, ww = i & 511, row = ww >> 3, c = ww & 7;
        size_t ge = (size_t)(b * T_SEQ + qt * 64 + row) * 3072 + hh * 64 + c * 8;
        const __nv_bfloat16* src = tensor ? qkvl : qkvh;
        uint32_t dst = sb + (tensor ? AT_QL : AT_QH) + row * AT_ROWB + c * 16;
        cp16(dst, src + ge);
    }
    CP_COMMIT();

    auto load_kv = [&](int kt, int stage) {
        uint32_t stb = sb + AT_STAGE0 + stage * AT_STGSZ;
        #pragma unroll
        for (int it = 0; it < 16; it++) {
            int i = tid + it * 128;
            int tensor = i >> 9, ww = i & 511, row = ww >> 3, c = ww & 7;
            int kvoff = (tensor >= 2) ? 2048 : 1024;
            size_t ge = (size_t)(b * T_SEQ + kt * 64 + row) * 3072 + kvoff + hh * 64 + c * 8;
            const __nv_bfloat16* src = (tensor & 1) ? qkvl : qkvh;
            uint32_t toff = (tensor == 0) ? AT_KH : (tensor == 1) ? AT_KL
                          : (tensor == 2) ? AT_VH : AT_VL;
            cp16(stb + toff + row * AT_ROWB + c * 16, src + ge);
        }
    };
    load_kv(0, 0);
    CP_COMMIT();

    float O[8][4];
    #pragma unroll
    for (int j = 0; j < 8; j++)
        #pragma unroll
        for (int e = 0; e < 4; e++) O[j][e] = 0.f;
    float m0 = -1e30f, m1 = -1e30f, l0 = 0.f, l1 = 0.f;

    int r0 = qt * 64 + qb + (lane >> 2);
    int r1 = r0 + 8;

    for (int kt = 0; kt <= qt; kt++) {
        if (kt < qt) load_kv(kt + 1, (kt + 1) & 1);
        CP_COMMIT();
        CP_WAIT1();
        __syncthreads();

        uint32_t stb = sb + AT_STAGE0 + (kt & 1) * AT_STGSZ;

        float S[8][4];
        #pragma unroll
        for (int j = 0; j < 8; j++)
            #pragma unroll
            for (int e = 0; e < 4; e++) S[j][e] = 0.f;

        #pragma unroll
        for (int t = 0; t < 4; t++) {
            uint32_t qa = sb + (qb + (lane & 15)) * AT_ROWB + (t * 16 + (lane >> 4) * 8) * 2;
            uint32_t qh[4], ql[4];
            ldmx4(qa + AT_QH, qh[0], qh[1], qh[2], qh[3]);
            ldmx4(qa + AT_QL, ql[0], ql[1], ql[2], ql[3]);
            #pragma unroll
            for (int jj = 0; jj < 4; jj++) {
                uint32_t ka = stb + (jj * 16 + (lane & 7) + ((lane >> 4) << 3)) * AT_ROWB
                            + (t * 16 + ((lane >> 3) & 1) * 8) * 2;
                uint32_t kh[4], kl[4];
                ldmx4(ka + AT_KH, kh[0], kh[1], kh[2], kh[3]);
                ldmx4(ka + AT_KL, kl[0], kl[1], kl[2], kl[3]);
                mma16816(S[jj*2+0], qh, &kh[0]); mma16816(S[jj*2+1], qh, &kh[2]);
                mma16816(S[jj*2+0], qh, &kl[0]); mma16816(S[jj*2+1], qh, &kl[2]);
                mma16816(S[jj*2+0], ql, &kh[0]); mma16816(S[jj*2+1], ql, &kh[2]);
            }
        }

        int cb = kt * 64 + ((lane & 3) << 1);
        float mx0 = -1e30f, mx1 = -1e30f;
        #pragma unroll
        for (int j = 0; j < 8; j++) {
            int c0 = cb + j * 8, c1 = c0 + 1;
            float v;
            v = (c0 <= r0) ? S[j][0] * ATT_SCALE : -1e30f; S[j][0] = v; mx0 = fmaxf(mx0, v);
            v = (c1 <= r0) ? S[j][1] * ATT_SCALE : -1e30f; S[j][1] = v; mx0 = fmaxf(mx0, v);
            v = (c0 <= r1) ? S[j][2] * ATT_SCALE : -1e30f; S[j][2] = v; mx1 = fmaxf(mx1, v);
            v = (c1 <= r1) ? S[j][3] * ATT_SCALE : -1e30f; S[j][3] = v; mx1 = fmaxf(mx1, v);
        }
        mx0 = fmaxf(mx0, __shfl_xor_sync(0xffffffffu, mx0, 1));
        mx0 = fmaxf(mx0, __shfl_xor_sync(0xffffffffu, mx0, 2));
        mx1 = fmaxf(mx1, __shfl_xor_sync(0xffffffffu, mx1, 1));
        mx1 = fmaxf(mx1, __shfl_xor_sync(0xffffffffu, mx1, 2));
        float mn0 = fmaxf(m0, mx0), mn1 = fmaxf(m1, mx1);
        float a0 = __expf(m0 - mn0), a1 = __expf(m1 - mn1);
        m0 = mn0; m1 = mn1;
        float s0 = 0.f, s1 = 0.f;
        #pragma unroll
        for (int j = 0; j < 8; j++) {
            S[j][0] = __expf(S[j][0] - m0); s0 += S[j][0];
            S[j][1] = __expf(S[j][1] - m0); s0 += S[j][1];
            S[j][2] = __expf(S[j][2] - m1); s1 += S[j][2];
            S[j][3] = __expf(S[j][3] - m1); s1 += S[j][3];
        }
        s0 += __shfl_xor_sync(0xffffffffu, s0, 1);
        s0 += __shfl_xor_sync(0xffffffffu, s0, 2);
        s1 += __shfl_xor_sync(0xffffffffu, s1, 1);
        s1 += __shfl_xor_sync(0xffffffffu, s1, 2);
        l0 = l0 * a0 + s0; l1 = l1 * a1 + s1;
        #pragma unroll
        for (int j = 0; j < 8; j++) {
            O[j][0] *= a0; O[j][1] *= a0; O[j][2] *= a1; O[j][3] *= a1;
        }

        #pragma unroll
        for (int t = 0; t < 4; t++) {
            uint32_t pah[4], pal[4];
            pack_hl(S[2*t  ][0], S[2*t  ][1], pah[0], pal[0]);
            pack_hl(S[2*t  ][2], S[2*t  ][3], pah[1], pal[1]);
            pack_hl(S[2*t+1][0], S[2*t+1][1], pah[2], pal[2]);
            pack_hl(S[2*t+1][2], S[2*t+1][3], pah[3], pal[3]);
            #pragma unroll
            for (int dd = 0; dd < 4; dd++) {
                uint32_t va = stb + (t * 16 + (lane & 7) + ((lane >> 3) & 1) * 8) * AT_ROWB
                            + (dd * 16 + (lane >> 4) * 8) * 2;
                uint32_t vh[4], vl[4];
                ldmx4t(va + AT_VH, vh[0], vh[1], vh[2], vh[3]);
                ldmx4t(va + AT_VL, vl[0], vl[1], vl[2], vl[3]);
                mma16816(O[dd*2+0], pah, &vh[0]); mma16816(O[dd*2+1], pah, &vh[2]);
                mma16816(O[dd*2+0], pah, &vl[0]); mma16816(O[dd*2+1], pah, &vl[2]);
                mma16816(O[dd*2+0], pal, &vh[0]); mma16816(O[dd*2+1], pal, &vh[2]);
            }
        }
        __syncthreads();
    }

    float i0 = 1.f / l0, i1 = 1.f / l1;
    int tok0 = b * T_SEQ + r0, tok1 = b * T_SEQ + r1;
    #pragma unroll
    for (int j = 0; j < 8; j++) {
        int d = hh * 64 + j * 8 + ((lane & 3) << 1);
        size_t idx0 = (size_t)tok0 * D_MODEL + d;
        size_t idx1 = (size_t)tok1 * D_MODEL + d;
        float v00 = O[j][0] * i0, v01 = O[j][1] * i0;
        float v10 = O[j][2] * i1, v11 = O[j][3] * i1;
        outF[idx0] = v00; outF[idx0 + 1] = v01;
        outF[idx1] = v10; outF[idx1 + 1] = v11;
        __nv_bfloat16 hh0, ll0, hh1, ll1;
        splt(v00, hh0, ll0); splt(v01, hh1, ll1);
        outH[idx0] = hh0; outH[idx0 + 1] = hh1;
        outL[idx0] = ll0; outL[idx0 + 1] = ll1;
        splt(v10, hh0, ll0); splt(v11, hh1, ll1);
        outH[idx1] = hh0; outH[idx1 + 1] = hh1;
        outL[idx1] = ll0; outL[idx1 + 1] = ll1;
        if (diffH) {
            float d00 = nIn[idx0] - v00, d01 = nIn[idx0 + 1] - v01;
            float d10 = nIn[idx1] - v10, d11 = nIn[idx1 + 1] - v11;
            splt(d00, hh0, ll0); splt(d01, hh1, ll1);
            diffH[idx0] = hh0; diffH[idx0 + 1] = hh1;
            diffL[idx0] = ll0; diffL[idx0 + 1] = ll1;
            splt(d10, hh0, ll0); splt(d11, hh1, ll1);
            diffH[idx1] = hh0; diffH[idx1 + 1] = hh1;
            diffL[idx1] = ll0; diffL[idx1 + 1] = ll1;
        }
    }
}

// ---------------- driver ----------------------------------------------------
#define GSMEM128 (2 * (2 * 128 * SROW + 2 * 128 * SROW))
#define GSMEM64  (2 * (2 * 128 * SROW + 2 * 64 * SROW))

extern "C" void kernel_launch(void* const* d_in, const int* in_sizes, int n_in,
                              void* d_out, int out_size) {
    const int*   x      = (const int*)  d_in[0];
    const float* embed  = (const float*)d_in[1];
    const float* pos    = (const float*)d_in[2];
    const float* Wqkv   = (const float*)d_in[3];
    const float* bqkv   = (const float*)d_in[4];
    const float* Wo     = (const float*)d_in[5];
    const float* bo     = (const float*)d_in[6];
    const float* Wg     = (const float*)d_in[7];
    const float* bg     = (const float*)d_in[8];
    const float* ln1_g  = (const float*)d_in[9];
    const float* ln1_b  = (const float*)d_in[10];
    const float* W1     = (const float*)d_in[11];
    const float* b1     = (const float*)d_in[12];
    const float* W2     = (const float*)d_in[13];
    const float* b2     = (const float*)d_in[14];
    const float* ln2_g  = (const float*)d_in[15];
    const float* ln2_b  = (const float*)d_in[16];
    const float* lnf_g  = (const float*)d_in[17];
    const float* lnf_b  = (const float*)d_in[18];
    float* out = (float*)d_out;

    cudaFuncSetAttribute(gemm_tc<128>, cudaFuncAttributeMaxDynamicSharedMemorySize, GSMEM128);
    cudaFuncSetAttribute(gemm_tc<64>,  cudaFuncAttributeMaxDynamicSharedMemorySize, GSMEM64);
    cudaFuncSetAttribute(gemm_f16,     cudaFuncAttributeMaxDynamicSharedMemorySize, FSMEM);
    cudaFuncSetAttribute(attn_mma,     cudaFuncAttributeMaxDynamicSharedMemorySize, AT_SMEM);

    float *h, *n, *pred, *corr;
    cudaGetSymbolAddress((void**)&h,    g_h);
    cudaGetSymbolAddress((void**)&n,    g_n);
    cudaGetSymbolAddress((void**)&pred, g_pred);
    cudaGetSymbolAddress((void**)&corr, g_corr);
    __nv_bfloat16 *ah, *al, *fh, *fl, *ph, *pl, *ch, *cl, *qh, *ql;
    cudaGetSymbolAddress((void**)&ah, g_ah);
    cudaGetSymbolAddress((void**)&al, g_al);
    cudaGetSymbolAddress((void**)&fh, g_fh);
    cudaGetSymbolAddress((void**)&fl, g_fl);
    cudaGetSymbolAddress((void**)&ph, g_ph);
    cudaGetSymbolAddress((void**)&pl, g_pl);
    cudaGetSymbolAddress((void**)&ch, g_ch);
    cudaGetSymbolAddress((void**)&cl, g_cl);
    cudaGetSymbolAddress((void**)&qh, g_qkvh);
    cudaGetSymbolAddress((void**)&ql, g_qkvl);
    __half *a16, *embf;
    cudaGetSymbolAddress((void**)&a16,  g_a16);
    cudaGetSymbolAddress((void**)&embf, g_embf);
    __nv_bfloat16 *wqkv_h, *wqkv_l, *wo_h, *wo_l, *wg_h, *wg_l, *w1_h, *w1_l, *w2_h, *w2_l;
    cudaGetSymbolAddress((void**)&wqkv_h, g_wqkv_h); cudaGetSymbolAddress((void**)&wqkv_l, g_wqkv_l);
    cudaGetSymbolAddress((void**)&wo_h,   g_wo_h);   cudaGetSymbolAddress((void**)&wo_l,   g_wo_l);
    cudaGetSymbolAddress((void**)&wg_h,   g_wg_h);   cudaGetSymbolAddress((void**)&wg_l,   g_wg_l);
    cudaGetSymbolAddress((void**)&w1_h,   g_w1_h);   cudaGetSymbolAddress((void**)&w1_l,   g_w1_l);
    cudaGetSymbolAddress((void**)&w2_h,   g_w2_h);   cudaGetSymbolAddress((void**)&w2_l,   g_w2_l);

    split_all<<<(int)((Q5 + 255) / 256), 256>>>(
        (const float4*)Wqkv, (const float4*)Wo, (const float4*)Wg,
        (const float4*)W1, (const float4*)W2, (const float4*)embed,
        (uint2*)wqkv_h, (uint2*)wqkv_l, (uint2*)wo_h, (uint2*)wo_l,
        (uint2*)wg_h, (uint2*)wg_l, (uint2*)w1_h, (uint2*)w1_l,
        (uint2*)w2_h, (uint2*)w2_l, (uint2*)embf);

    dim3 attng(T_SEQ / 64, 16, 2);

    embed_kernel<<<BT, 256>>>(x, embed, pos, h);

    for (int l = 0; l < NLAYER; l++) {
        ln_kernel<<<BT, 256>>>(h, ln1_g + l * D_MODEL, ln1_b + l * D_MODEL, n, ah, al, nullptr);
        gemm_tc<128><<<dim3(3072/128, BT/128), 256, GSMEM128>>>(
            ah, al, nullptr, nullptr, 1 << 30, D_MODEL, 0,
            wqkv_h + (size_t)(l*2+0)*3072*D_MODEL, wqkv_l + (size_t)(l*2+0)*3072*D_MODEL,
            bqkv + (l*2+0)*3072, nullptr, nullptr,
            nullptr, qh, ql, BT, 3072, D_MODEL, 0);
        attn_mma<<<attng, 128, AT_SMEM>>>(qh, ql, n, pred, ph, pl, ah, al);
        gemm_tc<128><<<dim3(3072/128, BT/128), 256, GSMEM128>>>(
            ah, al, nullptr, nullptr, 1 << 30, D_MODEL, 0,
            wqkv_h + (size_t)(l*2+1)*3072*D_MODEL, wqkv_l + (size_t)(l*2+1)*3072*D_MODEL,
            bqkv + (l*2+1)*3072, nullptr, nullptr,
            nullptr, qh, ql, BT, 3072, D_MODEL, 0);
        attn_mma<<<attng, 128, AT_SMEM>>>(qh, ql, nullptr, corr, ch, cl, nullptr, nullptr);
        gemm_tc<64><<<dim3(D_MODEL/64, BT/128), 256, GSMEM64>>>(
            ph, pl, ch, cl, D_MODEL, D_MODEL, D_MODEL,
            wg_h + (size_t)l*D_MODEL*2*D_MODEL, wg_l + (size_t)l*D_MODEL*2*D_MODEL,
            bg + l*D_MODEL, pred, corr,
            nullptr, ah, al, BT, D_MODEL, 2*D_MODEL, 3);
        gemm_tc<64><<<dim3(D_MODEL/64, BT/128), 256, GSMEM64>>>(
            ah, al, nullptr, nullptr, 1 << 30, D_MODEL, 0,
            wo_h + (size_t)l*D_MODEL*D_MODEL, wo_l + (size_t)l*D_MODEL*D_MODEL,
            bo + l*D_MODEL, h, nullptr,
            h, nullptr, nullptr, BT, D_MODEL, D_MODEL, 1);
        ln_kernel<<<BT, 256>>>(h, ln2_g + l * D_MODEL, ln2_b + l * D_MODEL, nullptr, ah, al, nullptr);
        gemm_tc<128><<<dim3(FF_DIM/128, BT/128), 256, GSMEM128>>>(
            ah, al, nullptr, nullptr, 1 << 30, D_MODEL, 0,
            w1_h + (size_t)l*FF_DIM*D_MODEL, w1_l + (size_t)l*FF_DIM*D_MODEL,
            b1 + l*FF_DIM, nullptr, nullptr,
            nullptr, fh, fl, BT, FF_DIM, D_MODEL, 2);
        gemm_tc<64><<<dim3(D_MODEL/64, BT/128), 256, GSMEM64>>>(
            fh, fl, nullptr, nullptr, 1 << 30, FF_DIM, 0,
            w2_h + (size_t)l*D_MODEL*FF_DIM, w2_l + (size_t)l*D_MODEL*FF_DIM,
            b2 + l*D_MODEL, h, nullptr,
            h, nullptr, nullptr, BT, D_MODEL, FF_DIM, 1);
    }

    ln_kernel<<<BT, 256>>>(h, lnf_g, lnf_b, nullptr, nullptr, nullptr, a16);
    gemm_f16<<<dim3(VOCAB/64, BT/128), 256, FSMEM>>>(
        a16, embf, out, BT, VOCAB, D_MODEL);
}

// round 8
// speedup vs baseline: 3.8103x; 1.2299x over previous
#include <cuda_runtime.h>
#include <cuda_bf16.h>
#include <cuda_fp16.h>
#include <stdint.h>
#include <math.h>

#define T_SEQ   1024
#define D_MODEL 1024
#define NLAYER  4
#define FF_DIM  4096
#define VOCAB   32000
#define BT      2048
#define ATT_SCALE 0.125f

// ---------------- fp32 scratch ----------------------------------------------
__device__ float g_h   [BT * D_MODEL];
__device__ float g_n   [BT * D_MODEL];
__device__ float g_pred[BT * D_MODEL];
__device__ float g_corr[BT * D_MODEL];

// ---------------- activation scratch ----------------------------------------
__device__ __align__(16) __nv_bfloat16 g_ah[BT * D_MODEL];
__device__ __align__(16) __nv_bfloat16 g_al[BT * D_MODEL];
__device__ __align__(16) __nv_bfloat16 g_ph[BT * D_MODEL], g_pl[BT * D_MODEL];
__device__ __align__(16) __nv_bfloat16 g_ch[BT * D_MODEL], g_cl[BT * D_MODEL];
__device__ __align__(16) __nv_bfloat16 g_qkvh[BT * 3 * D_MODEL];
__device__ __align__(16) __nv_bfloat16 g_qkvl[BT * 3 * D_MODEL];
__device__ __align__(16) __half        g_a16 [BT * D_MODEL];
__device__ __align__(16) __half        g_d16 [BT * D_MODEL];
__device__ __align__(16) __half        g_f16 [BT * FF_DIM];

// ---------------- weights ----------------------------------------------------
#define SZ_WQKV (NLAYER * 2 * 3 * D_MODEL * D_MODEL)
#define SZ_WO   (NLAYER * D_MODEL * D_MODEL)
#define SZ_WG   (NLAYER * D_MODEL * 2 * D_MODEL)
#define SZ_W1   (NLAYER * FF_DIM * D_MODEL)
#define SZ_W2   (NLAYER * D_MODEL * FF_DIM)
#define SZ_EMB  (VOCAB * D_MODEL)
__device__ __align__(16) __half        g_wqkv_h[SZ_WQKV], g_wqkv_l[SZ_WQKV];
__device__ __align__(16) __nv_bfloat16 g_wo_h  [SZ_WO],   g_wo_l  [SZ_WO];
__device__ __align__(16) __nv_bfloat16 g_wg_h  [SZ_WG],   g_wg_l  [SZ_WG];
__device__ __align__(16) __half        g_w1_h  [SZ_W1],   g_w1_l  [SZ_W1];
__device__ __align__(16) __half        g_w2_h  [SZ_W2],   g_w2_l  [SZ_W2];
__device__ __align__(16) __half        g_embf  [SZ_EMB];

// ---------------- helpers ----------------------------------------------------
__device__ __forceinline__ void splt(float x, __nv_bfloat16& h, __nv_bfloat16& l) {
    h = __float2bfloat16_rn(x);
    l = __float2bfloat16_rn(x - __bfloat162float(h));
}
__device__ __forceinline__ void pack_hl(float x, float y, uint32_t& h, uint32_t& l) {
    __nv_bfloat16 h0 = __float2bfloat16_rn(x), h1 = __float2bfloat16_rn(y);
    __nv_bfloat16 l0 = __float2bfloat16_rn(x - __bfloat162float(h0));
    __nv_bfloat16 l1 = __float2bfloat16_rn(y - __bfloat162float(h1));
    h = (uint32_t)__bfloat16_as_ushort(h0) | ((uint32_t)__bfloat16_as_ushort(h1) << 16);
    l = (uint32_t)__bfloat16_as_ushort(l0) | ((uint32_t)__bfloat16_as_ushort(l1) << 16);
}
__device__ __forceinline__ uint32_t smem_u32(const void* p) {
    uint32_t a;
    asm("{ .reg .u64 t; cvta.to.shared.u64 t, %1; cvt.u32.u64 %0, t; }" : "=r"(a) : "l"(p));
    return a;
}
__device__ __forceinline__ void cp16(uint32_t s, const void* g) {
    asm volatile("cp.async.cg.shared.global [%0], [%1], 16;" :: "r"(s), "l"(g));
}
#define CP_COMMIT() asm volatile("cp.async.commit_group;" ::: "memory")
#define CP_WAIT0()  asm volatile("cp.async.wait_group 0;" ::: "memory")

__device__ __forceinline__ void ldmx4(uint32_t a, uint32_t& r0, uint32_t& r1,
                                      uint32_t& r2, uint32_t& r3) {
    asm volatile("ldmatrix.sync.aligned.m8n8.x4.shared.b16 {%0,%1,%2,%3}, [%4];"
                 : "=r"(r0), "=r"(r1), "=r"(r2), "=r"(r3) : "r"(a));
}
__device__ __forceinline__ void ldmx4t(uint32_t a, uint32_t& r0, uint32_t& r1,
                                       uint32_t& r2, uint32_t& r3) {
    asm volatile("ldmatrix.sync.aligned.m8n8.x4.trans.shared.b16 {%0,%1,%2,%3}, [%4];"
                 : "=r"(r0), "=r"(r1), "=r"(r2), "=r"(r3) : "r"(a));
}
__device__ __forceinline__ void mma16816(float* d, const uint32_t* a, const uint32_t* b) {
    asm volatile("mma.sync.aligned.m16n8k16.row.col.f32.bf16.bf16.f32 "
                 "{%0,%1,%2,%3}, {%4,%5,%6,%7}, {%8,%9}, {%0,%1,%2,%3};"
                 : "+f"(d[0]), "+f"(d[1]), "+f"(d[2]), "+f"(d[3])
                 : "r"(a[0]), "r"(a[1]), "r"(a[2]), "r"(a[3]), "r"(b[0]), "r"(b[1]));
}
__device__ __forceinline__ void mma16816h(float* d, const uint32_t* a, const uint32_t* b) {
    asm volatile("mma.sync.aligned.m16n8k16.row.col.f32.f16.f16.f32 "
                 "{%0,%1,%2,%3}, {%4,%5,%6,%7}, {%8,%9}, {%0,%1,%2,%3};"
                 : "+f"(d[0]), "+f"(d[1]), "+f"(d[2]), "+f"(d[3])
                 : "r"(a[0]), "r"(a[1]), "r"(a[2]), "r"(a[3]), "r"(b[0]), "r"(b[1]));
}

// ---------------- one-shot weight split -------------------------------------
// modes: 0 = bf16 hi/lo, 1 = fp16 hi/lo, 2 = fp16 single
#define Q0 (SZ_WQKV/4)
#define Q1 (Q0 + SZ_WO/4)
#define Q2 (Q1 + SZ_WG/4)
#define Q3 (Q2 + SZ_W1/4)
#define Q4 (Q3 + SZ_W2/4)
#define Q5 (Q4 + SZ_EMB/4)
__global__ void split_all(
    const float4* w0, const float4* w1, const float4* w2,
    const float4* w3, const float4* w4, const float4* w5,
    uint2* h0, uint2* l0, uint2* h1, uint2* l1, uint2* h2, uint2* l2,
    uint2* h3, uint2* l3, uint2* h4, uint2* l4, uint2* f5)
{
    long i = (long)blockIdx.x * 256 + threadIdx.x;
    if (i >= Q5) return;
    const float4* src; uint2 *hi, *lo; long off; int mode;
    if      (i < Q0) { src = w0; hi = h0; lo = l0; off = i;      mode = 1; }
    else if (i < Q1) { src = w1; hi = h1; lo = l1; off = i - Q0; mode = 0; }
    else if (i < Q2) { src = w2; hi = h2; lo = l2; off = i - Q1; mode = 0; }
    else if (i < Q3) { src = w3; hi = h3; lo = l3; off = i - Q2; mode = 1; }
    else if (i < Q4) { src = w4; hi = h4; lo = l4; off = i - Q3; mode = 1; }
    else             { src = w5; hi = f5; lo = f5; off = i - Q4; mode = 2; }
    float4 v = src[off];
    float vv[4] = {v.x, v.y, v.z, v.w};
    uint2 H, L;
    uint32_t Hw[2] = {0, 0}, Lw[2] = {0, 0};
    if (mode == 0) {
        #pragma unroll
        for (int k = 0; k < 4; k++) {
            __nv_bfloat16 a, b; splt(vv[k], a, b);
            Hw[k >> 1] |= (uint32_t)__bfloat16_as_ushort(a) << ((k & 1) * 16);
            Lw[k >> 1] |= (uint32_t)__bfloat16_as_ushort(b) << ((k & 1) * 16);
        }
        H = make_uint2(Hw[0], Hw[1]); L = make_uint2(Lw[0], Lw[1]);
        hi[off] = H; lo[off] = L;
    } else if (mode == 1) {
        #pragma unroll
        for (int k = 0; k < 4; k++) {
            __half a = __float2half_rn(vv[k]);
            __half b = __float2half_rn(vv[k] - __half2float(a));
            Hw[k >> 1] |= (uint32_t)__half_as_ushort(a) << ((k & 1) * 16);
            Lw[k >> 1] |= (uint32_t)__half_as_ushort(b) << ((k & 1) * 16);
        }
        hi[off] = make_uint2(Hw[0], Hw[1]); lo[off] = make_uint2(Lw[0], Lw[1]);
    } else {
        #pragma unroll
        for (int k = 0; k < 4; k++) {
            __half a = __float2half_rn(vv[k]);
            Hw[k >> 1] |= (uint32_t)__half_as_ushort(a) << ((k & 1) * 16);
        }
        hi[off] = make_uint2(Hw[0], Hw[1]);
    }
}

#define SROW 80

// ---------------- bf16 3-mma GEMM (gate / Wo), single-sync loop --------------
template<int BN>
__global__ __launch_bounds__(256, 2) void gemm_tc(
    const __nv_bfloat16* __restrict__ Ah, const __nv_bfloat16* __restrict__ Al,
    const __nv_bfloat16* __restrict__ Ah2, const __nv_bfloat16* __restrict__ Al2,
    int kSplit, int lda1, int lda2,
    const __nv_bfloat16* __restrict__ Wh, const __nv_bfloat16* __restrict__ Wl,
    const float* __restrict__ bias, const float* __restrict__ res,
    const float* __restrict__ corr,
    float* __restrict__ Cf, __nv_bfloat16* __restrict__ Ch, __nv_bfloat16* __restrict__ Cl,
    int M, int N, int K, int epi)
{
    constexpr int ASZ  = 128 * SROW;
    constexpr int BSZ  = BN * SROW;
    constexpr int BOFF = 2 * ASZ;
    constexpr int STGB = 2 * ASZ + 2 * BSZ;
    constexpr int NG   = BN / 32;
    constexpr int NB16 = 128 * 8 + BN * 8;
    extern __shared__ char smem[];
    uint32_t sb = smem_u32(smem);
    int tid = threadIdx.x, lane = tid & 31, w = tid >> 5;
    int wm = w & 3, wn = w >> 2;
    int bm = blockIdx.y * 128, bn = blockIdx.x * BN;

    float acc[2][NG * 2][4];
    #pragma unroll
    for (int i = 0; i < 2; i++)
        #pragma unroll
        for (int j = 0; j < NG * 2; j++)
            #pragma unroll
            for (int e = 0; e < 4; e++) acc[i][j][e] = 0.f;

    int nk = K / 32;

    auto load_chunk = [&](int kc, uint32_t s) {
        int kb = kc * 32;
        const __nv_bfloat16 *sAh, *sAl; int lda, koff;
        if (kb < kSplit) { sAh = Ah;  sAl = Al;  lda = lda1; koff = kb; }
        else             { sAh = Ah2; sAl = Al2; lda = lda2; koff = kb - kSplit; }
        #pragma unroll
        for (int it = 0; it < NB16 / 256; it++) {
            int i = tid + it * 256;
            if (i < 1024) {
                int hf = i >> 9, ww = i & 511;
                int row = ww >> 2, c = ww & 3;
                size_t go = (size_t)(bm + row) * lda + koff + c * 8;
                cp16(s + (hf ? ASZ : 0) + row * SROW + c * 16, (hf ? sAl : sAh) + go);
            } else {
                int ii = i - 1024;
                int hf = ii >= BN * 4;
                int ww = ii & (BN * 4 - 1);
                int row = ww >> 2, c = ww & 3;
                size_t go = (size_t)(bn + row) * K + kb + c * 8;
                cp16(s + BOFF + (hf ? BSZ : 0) + row * SROW + c * 16, (hf ? Wl : Wh) + go);
            }
        }
    };

    load_chunk(0, sb);
    CP_COMMIT();

    for (int kc = 0; kc < nk; kc++) {
        CP_WAIT0();
        __syncthreads();
        if (kc + 1 < nk) { load_chunk(kc + 1, sb + ((kc + 1) & 1) * STGB); CP_COMMIT(); }

        uint32_t s = sb + (kc & 1) * STGB;
        #pragma unroll
        for (int t = 0; t < 2; t++) {
            uint32_t arow = wm * 32 + (lane & 15);
            uint32_t ak = (t * 16 + (lane >> 4) * 8) * 2;
            uint32_t ahr[2][4], alr[2][4];
            #pragma unroll
            for (int mg = 0; mg < 2; mg++) {
                uint32_t aoff = (arow + mg * 16) * SROW + ak;
                ldmx4(s + aoff,       ahr[mg][0], ahr[mg][1], ahr[mg][2], ahr[mg][3]);
                ldmx4(s + ASZ + aoff, alr[mg][0], alr[mg][1], alr[mg][2], alr[mg][3]);
            }
            #pragma unroll
            for (int ng = 0; ng < NG; ng++) {
                uint32_t brow = wn * (BN / 2) + ng * 16 + (lane & 7) + ((lane >> 4) << 3);
                uint32_t boff = brow * SROW + (t * 16 + ((lane >> 3) & 1) * 8) * 2;
                uint32_t bh[4], bl[4];
                ldmx4(s + BOFF + boff,       bh[0], bh[1], bh[2], bh[3]);
                ldmx4(s + BOFF + BSZ + boff, bl[0], bl[1], bl[2], bl[3]);
                #pragma unroll
                for (int mg = 0; mg < 2; mg++) {
                    mma16816(acc[mg][ng*2+0], ahr[mg], &bh[0]);
                    mma16816(acc[mg][ng*2+1], ahr[mg], &bh[2]);
                    mma16816(acc[mg][ng*2+0], ahr[mg], &bl[0]);
                    mma16816(acc[mg][ng*2+1], ahr[mg], &bl[2]);
                    mma16816(acc[mg][ng*2+0], alr[mg], &bh[0]);
                    mma16816(acc[mg][ng*2+1], alr[mg], &bh[2]);
                }
            }
        }
    }

    #pragma unroll
    for (int mg = 0; mg < 2; mg++) {
        #pragma unroll
        for (int j = 0; j < NG * 2; j++) {
            int m0 = bm + wm * 32 + mg * 16 + (lane >> 2);
            int n0 = bn + wn * (BN / 2) + j * 8 + (lane & 3) * 2;
            #pragma unroll
            for (int e = 0; e < 4; e++) {
                int m = m0 + (e >> 1) * 8;
                int n = n0 + (e & 1);
                size_t idx = (size_t)m * N + n;
                float v = acc[mg][j][e];
                if (bias) v += bias[n];
                if (epi == 1)      v += res[idx];
                else if (epi == 3) v = res[idx] + corr[idx] / (1.f + __expf(-v));
                if (Cf) Cf[idx] = v;
                if (Ch) {
                    __nv_bfloat16 hh, ll;
                    splt(v, hh, ll);
                    Ch[idx] = hh; Cl[idx] = ll;
                }
            }
        }
    }
}

// ---------------- fp16 2-mma GEMM (qkv / W1 / W2), single-sync ---------------
// epi: 0 none, 1 +res, 2 gelu
template<int BN>
__global__ __launch_bounds__(256, 2) void gemm_h(
    const __half* __restrict__ A16,
    const __half* __restrict__ Wh, const __half* __restrict__ Wl,
    const float* __restrict__ bias, const float* __restrict__ res,
    float* __restrict__ Cf, __nv_bfloat16* __restrict__ Ch, __nv_bfloat16* __restrict__ Cl,
    __half* __restrict__ C16,
    int M, int N, int K, int epi)
{
    constexpr int ASZ  = 128 * SROW;
    constexpr int BSZ  = BN * SROW;
    constexpr int BOFF = ASZ;
    constexpr int STGB = ASZ + 2 * BSZ;
    constexpr int NG   = BN / 32;
    constexpr int NB16 = 128 * 4 + BN * 8;
    extern __shared__ char smem[];
    uint32_t sb = smem_u32(smem);
    int tid = threadIdx.x, lane = tid & 31, w = tid >> 5;
    int wm = w & 3, wn = w >> 2;
    int bm = blockIdx.y * 128, bn = blockIdx.x * BN;

    float acc[2][NG * 2][4];
    #pragma unroll
    for (int i = 0; i < 2; i++)
        #pragma unroll
        for (int j = 0; j < NG * 2; j++)
            #pragma unroll
            for (int e = 0; e < 4; e++) acc[i][j][e] = 0.f;

    int nk = K / 32;

    auto load_chunk = [&](int kc, uint32_t s) {
        int kb = kc * 32;
        #pragma unroll
        for (int it = 0; it < NB16 / 256; it++) {
            int i = tid + it * 256;
            if (i < 512) {
                int row = i >> 2, c = i & 3;
                size_t go = (size_t)(bm + row) * K + kb + c * 8;
                cp16(s + row * SROW + c * 16, A16 + go);
            } else {
                int ii = i - 512;
                int hf = ii >= BN * 4;
                int ww = ii & (BN * 4 - 1);
                int row = ww >> 2, c = ww & 3;
                size_t go = (size_t)(bn + row) * K + kb + c * 8;
                cp16(s + BOFF + (hf ? BSZ : 0) + row * SROW + c * 16, (hf ? Wl : Wh) + go);
            }
        }
    };

    load_chunk(0, sb);
    CP_COMMIT();

    for (int kc = 0; kc < nk; kc++) {
        CP_WAIT0();
        __syncthreads();
        if (kc + 1 < nk) { load_chunk(kc + 1, sb + ((kc + 1) & 1) * STGB); CP_COMMIT(); }

        uint32_t s = sb + (kc & 1) * STGB;
        #pragma unroll
        for (int t = 0; t < 2; t++) {
            uint32_t arow = wm * 32 + (lane & 15);
            uint32_t ak = (t * 16 + (lane >> 4) * 8) * 2;
            uint32_t ar[2][4];
            #pragma unroll
            for (int mg = 0; mg < 2; mg++) {
                uint32_t aoff = (arow + mg * 16) * SROW + ak;
                ldmx4(s + aoff, ar[mg][0], ar[mg][1], ar[mg][2], ar[mg][3]);
            }
            #pragma unroll
            for (int ng = 0; ng < NG; ng++) {
                uint32_t brow = wn * (BN / 2) + ng * 16 + (lane & 7) + ((lane >> 4) << 3);
                uint32_t boff = brow * SROW + (t * 16 + ((lane >> 3) & 1) * 8) * 2;
                uint32_t bh[4], bl[4];
                ldmx4(s + BOFF + boff,       bh[0], bh[1], bh[2], bh[3]);
                ldmx4(s + BOFF + BSZ + boff, bl[0], bl[1], bl[2], bl[3]);
                #pragma unroll
                for (int mg = 0; mg < 2; mg++) {
                    mma16816h(acc[mg][ng*2+0], ar[mg], &bh[0]);
                    mma16816h(acc[mg][ng*2+1], ar[mg], &bh[2]);
                    mma16816h(acc[mg][ng*2+0], ar[mg], &bl[0]);
                    mma16816h(acc[mg][ng*2+1], ar[mg], &bl[2]);
                }
            }
        }
    }

    #pragma unroll
    for (int mg = 0; mg < 2; mg++) {
        #pragma unroll
        for (int j = 0; j < NG * 2; j++) {
            int m0 = bm + wm * 32 + mg * 16 + (lane >> 2);
            int n0 = bn + wn * (BN / 2) + j * 8 + (lane & 3) * 2;
            #pragma unroll
            for (int e = 0; e < 4; e++) {
                int m = m0 + (e >> 1) * 8;
                int n = n0 + (e & 1);
                size_t idx = (size_t)m * N + n;
                float v = acc[mg][j][e];
                if (bias) v += bias[n];
                if (epi == 1)      v += res[idx];
                else if (epi == 2) v = 0.5f * v * (1.f + erff(v * 0.70710678118f));
                if (Cf) Cf[idx] = v;
                if (Ch) {
                    __nv_bfloat16 hh, ll;
                    splt(v, hh, ll);
                    Ch[idx] = hh; Cl[idx] = ll;
                }
                if (C16) C16[idx] = __float2half_rn(v);
            }
        }
    }
}

// ---------------- logits GEMM (fp16 1-mma, 128x64, KC=64, single-sync) -------
#define FROW  144
#define FB    18432
#define FSTG  27648
#define FSMEM (2 * FSTG)

__global__ __launch_bounds__(256, 3) void gemm_f16(
    const __half* __restrict__ Ah, const __half* __restrict__ Wh,
    float* __restrict__ Cf, int M, int N, int K)
{
    extern __shared__ char smem[];
    uint32_t sb = smem_u32(smem);
    int tid = threadIdx.x, lane = tid & 31, w = tid >> 5;
    int wm = w & 3, wn = w >> 2;
    int bm = blockIdx.y * 128, bn = blockIdx.x * 64;

    float acc[2][4][4];
    #pragma unroll
    for (int i = 0; i < 2; i++)
        #pragma unroll
        for (int j = 0; j < 4; j++)
            #pragma unroll
            for (int e = 0; e < 4; e++) acc[i][j][e] = 0.f;

    int nk = K / 64;

    auto load_chunk = [&](int kc, uint32_t s) {
        int kb = kc * 64;
        #pragma unroll
        for (int it = 0; it < 6; it++) {
            int i = tid + it * 256;
            if (i < 1024) {
                int row = i >> 3, c = i & 7;
                size_t go = (size_t)(bm + row) * K + kb + c * 8;
                cp16(s + row * FROW + c * 16, Ah + go);
            } else {
                int ii = i - 1024;
                int row = ii >> 3, c = ii & 7;
                size_t go = (size_t)(bn + row) * K + kb + c * 8;
                cp16(s + FB + row * FROW + c * 16, Wh + go);
            }
        }
    };

    load_chunk(0, sb);
    CP_COMMIT();

    for (int kc = 0; kc < nk; kc++) {
        CP_WAIT0();
        __syncthreads();
        if (kc + 1 < nk) { load_chunk(kc + 1, sb + ((kc + 1) & 1) * FSTG); CP_COMMIT(); }

        uint32_t s = sb + (kc & 1) * FSTG;
        #pragma unroll
        for (int t = 0; t < 4; t++) {
            uint32_t arow = wm * 32 + (lane & 15);
            uint32_t ak = (t * 16 + (lane >> 4) * 8) * 2;
            uint32_t ahr[2][4];
            #pragma unroll
            for (int mg = 0; mg < 2; mg++) {
                uint32_t aoff = (arow + mg * 16) * FROW + ak;
                ldmx4(s + aoff, ahr[mg][0], ahr[mg][1], ahr[mg][2], ahr[mg][3]);
            }
            #pragma unroll
            for (int ng = 0; ng < 2; ng++) {
                uint32_t brow = wn * 32 + ng * 16 + (lane & 7) + ((lane >> 4) << 3);
                uint32_t boff = brow * FROW + (t * 16 + ((lane >> 3) & 1) * 8) * 2;
                uint32_t bw[4];
                ldmx4(s + FB + boff, bw[0], bw[1], bw[2], bw[3]);
                #pragma unroll
                for (int mg = 0; mg < 2; mg++) {
                    mma16816h(acc[mg][ng*2+0], ahr[mg], &bw[0]);
                    mma16816h(acc[mg][ng*2+1], ahr[mg], &bw[2]);
                }
            }
        }
    }

    #pragma unroll
    for (int mg = 0; mg < 2; mg++) {
        #pragma unroll
        for (int j = 0; j < 4; j++) {
            int m0 = bm + wm * 32 + mg * 16 + (lane >> 2);
            int n0 = bn + wn * 32 + j * 8 + (lane & 3) * 2;
            #pragma unroll
            for (int e = 0; e < 4; e++) {
                int m = m0 + (e >> 1) * 8;
                int n = n0 + (e & 1);
                Cf[(size_t)m * N + n] = acc[mg][j][e];
            }
        }
    }
}

// ---------------- embedding ------------------------------------------------
__global__ void embed_kernel(const int* __restrict__ x, const float* __restrict__ emb,
                             const float* __restrict__ pos, float* __restrict__ h) {
    int row = blockIdx.x;
    int t   = row & (T_SEQ - 1);
    int tok = x[row];
    const float* e = emb + (size_t)tok * D_MODEL;
    const float* p = pos + (size_t)t   * D_MODEL;
    float* o = h + (size_t)row * D_MODEL;
    for (int d = threadIdx.x; d < D_MODEL; d += blockDim.x)
        o[d] = e[d] + p[d];
}

// ---------------- layernorm -------------------------------------------------
__global__ void ln_kernel(const float* __restrict__ in, const float* __restrict__ g,
                          const float* __restrict__ b, float* __restrict__ of,
                          __half* __restrict__ o16) {
    int row = blockIdx.x;
    const float* x = in + (size_t)row * D_MODEL;
    int tid = threadIdx.x;
    float s = 0.f, ss = 0.f;
    for (int d = tid; d < D_MODEL; d += 256) { float v = x[d]; s += v; ss += v * v; }
    #pragma unroll
    for (int off = 16; off; off >>= 1) {
        s  += __shfl_xor_sync(0xffffffffu, s,  off);
        ss += __shfl_xor_sync(0xffffffffu, ss, off);
    }
    __shared__ float shs[8], shss[8];
    if ((tid & 31) == 0) { shs[tid >> 5] = s; shss[tid >> 5] = ss; }
    __syncthreads();
    float tots = 0.f, totss = 0.f;
    #pragma unroll
    for (int i = 0; i < 8; i++) { tots += shs[i]; totss += shss[i]; }
    float mean = tots * (1.f / D_MODEL);
    float var  = totss * (1.f / D_MODEL) - mean * mean;
    float rstd = rsqrtf(var + 1e-5f);
    for (int d = tid; d < D_MODEL; d += 256) {
        float v = (x[d] - mean) * rstd * g[d] + b[d];
        size_t idx = (size_t)row * D_MODEL + d;
        if (of) of[idx] = v;
        o16[idx] = __float2half_rn(v);
    }
}

// ---------------- HMMA flash attention (single-sync, fp16 diff out) ----------
#define AT_ROWB   144
#define AT_QH     0
#define AT_QL     9216
#define AT_STAGE0 18432
#define AT_STGSZ  36864
#define AT_KH     0
#define AT_KL     9216
#define AT_VH     18432
#define AT_VL     27648
#define AT_SMEM   (18432 + 2 * 36864)

__global__ __launch_bounds__(128, 2) void attn_mma(
    const __nv_bfloat16* __restrict__ qkvh, const __nv_bfloat16* __restrict__ qkvl,
    const float* __restrict__ nIn,
    float* __restrict__ outF,
    __nv_bfloat16* __restrict__ outH, __nv_bfloat16* __restrict__ outL,
    __half* __restrict__ d16)
{
    extern __shared__ char sm[];
    uint32_t sb = smem_u32(sm);
    int qt = blockIdx.x, hh = blockIdx.y, b = blockIdx.z;
    int tid = threadIdx.x, lane = tid & 31, wq = tid >> 5;
    int qb = wq * 16;

    #pragma unroll
    for (int it = 0; it < 8; it++) {
        int i = tid + it * 128;
        int tensor = i >> 9, ww = i & 511, row = ww >> 3, c = ww & 7;
        size_t ge = (size_t)(b * T_SEQ + qt * 64 + row) * 3072 + hh * 64 + c * 8;
        const __nv_bfloat16* src = tensor ? qkvl : qkvh;
        uint32_t dst = sb + (tensor ? AT_QL : AT_QH) + row * AT_ROWB + c * 16;
        cp16(dst, src + ge);
    }

    auto load_kv = [&](int kt, int stage) {
        uint32_t stb = sb + AT_STAGE0 + stage * AT_STGSZ;
        #pragma unroll
        for (int it = 0; it < 16; it++) {
            int i = tid + it * 128;
            int tensor = i >> 9, ww = i & 511, row = ww >> 3, c = ww & 7;
            int kvoff = (tensor >= 2) ? 2048 : 1024;
            size_t ge = (size_t)(b * T_SEQ + kt * 64 + row) * 3072 + kvoff + hh * 64 + c * 8;
            const __nv_bfloat16* src = (tensor & 1) ? qkvl : qkvh;
            uint32_t toff = (tensor == 0) ? AT_KH : (tensor == 1) ? AT_KL
                          : (tensor == 2) ? AT_VH : AT_VL;
            cp16(stb + toff + row * AT_ROWB + c * 16, src + ge);
        }
    };
    load_kv(0, 0);
    CP_COMMIT();

    float O[8][4];
    #pragma unroll
    for (int j = 0; j < 8; j++)
        #pragma unroll
        for (int e = 0; e < 4; e++) O[j][e] = 0.f;
    float m0 = -1e30f, m1 = -1e30f, l0 = 0.f, l1 = 0.f;

    int r0 = qt * 64 + qb + (lane >> 2);
    int r1 = r0 + 8;

    for (int kt = 0; kt <= qt; kt++) {
        CP_WAIT0();
        __syncthreads();
        if (kt < qt) { load_kv(kt + 1, (kt + 1) & 1); CP_COMMIT(); }

        uint32_t stb = sb + AT_STAGE0 + (kt & 1) * AT_STGSZ;

        float S[8][4];
        #pragma unroll
        for (int j = 0; j < 8; j++)
            #pragma unroll
            for (int e = 0; e < 4; e++) S[j][e] = 0.f;

        #pragma unroll
        for (int t = 0; t < 4; t++) {
            uint32_t qa = sb + (qb + (lane & 15)) * AT_ROWB + (t * 16 + (lane >> 4) * 8) * 2;
            uint32_t qh[4], ql[4];
            ldmx4(qa + AT_QH, qh[0], qh[1], qh[2], qh[3]);
            ldmx4(qa + AT_QL, ql[0], ql[1], ql[2], ql[3]);
            #pragma unroll
            for (int jj = 0; jj < 4; jj++) {
                uint32_t ka = stb + (jj * 16 + (lane & 7) + ((lane >> 4) << 3)) * AT_ROWB
                            + (t * 16 + ((lane >> 3) & 1) * 8) * 2;
                uint32_t kh[4], kl[4];
                ldmx4(ka + AT_KH, kh[0], kh[1], kh[2], kh[3]);
                ldmx4(ka + AT_KL, kl[0], kl[1], kl[2], kl[3]);
                mma16816(S[jj*2+0], qh, &kh[0]); mma16816(S[jj*2+1], qh, &kh[2]);
                mma16816(S[jj*2+0], qh, &kl[0]); mma16816(S[jj*2+1], qh, &kl[2]);
                mma16816(S[jj*2+0], ql, &kh[0]); mma16816(S[jj*2+1], ql, &kh[2]);
            }
        }

        int cb = kt * 64 + ((lane & 3) << 1);
        float mx0 = -1e30f, mx1 = -1e30f;
        #pragma unroll
        for (int j = 0; j < 8; j++) {
            int c0 = cb + j * 8, c1 = c0 + 1;
            float v;
            v = (c0 <= r0) ? S[j][0] * ATT_SCALE : -1e30f; S[j][0] = v; mx0 = fmaxf(mx0, v);
            v = (c1 <= r0) ? S[j][1] * ATT_SCALE : -1e30f; S[j][1] = v; mx0 = fmaxf(mx0, v);
            v = (c0 <= r1) ? S[j][2] * ATT_SCALE : -1e30f; S[j][2] = v; mx1 = fmaxf(mx1, v);
            v = (c1 <= r1) ? S[j][3] * ATT_SCALE : -1e30f; S[j][3] = v; mx1 = fmaxf(mx1, v);
        }
        mx0 = fmaxf(mx0, __shfl_xor_sync(0xffffffffu, mx0, 1));
        mx0 = fmaxf(mx0, __shfl_xor_sync(0xffffffffu, mx0, 2));
        mx1 = fmaxf(mx1, __shfl_xor_sync(0xffffffffu, mx1, 1));
        mx1 = fmaxf(mx1, __shfl_xor_sync(0xffffffffu, mx1, 2));
        float mn0 = fmaxf(m0, mx0), mn1 = fmaxf(m1, mx1);
        float a0 = __expf(m0 - mn0), a1 = __expf(m1 - mn1);
        m0 = mn0; m1 = mn1;
        float s0 = 0.f, s1 = 0.f;
        #pragma unroll
        for (int j = 0; j < 8; j++) {
            S[j][0] = __expf(S[j][0] - m0); s0 += S[j][0];
            S[j][1] = __expf(S[j][1] - m0); s0 += S[j][1];
            S[j][2] = __expf(S[j][2] - m1); s1 += S[j][2];
            S[j][3] = __expf(S[j][3] - m1); s1 += S[j][3];
        }
        s0 += __shfl_xor_sync(0xffffffffu, s0, 1);
        s0 += __shfl_xor_sync(0xffffffffu, s0, 2);
        s1 += __shfl_xor_sync(0xffffffffu, s1, 1);
        s1 += __shfl_xor_sync(0xffffffffu, s1, 2);
        l0 = l0 * a0 + s0; l1 = l1 * a1 + s1;
        #pragma unroll
        for (int j = 0; j < 8; j++) {
            O[j][0] *= a0; O[j][1] *= a0; O[j][2] *= a1; O[j][3] *= a1;
        }

        #pragma unroll
        for (int t = 0; t < 4; t++) {
            uint32_t pah[4], pal[4];
            pack_hl(S[2*t  ][0], S[2*t  ][1], pah[0], pal[0]);
            pack_hl(S[2*t  ][2], S[2*t  ][3], pah[1], pal[1]);
            pack_hl(S[2*t+1][0], S[2*t+1][1], pah[2], pal[2]);
            pack_hl(S[2*t+1][2], S[2*t+1][3], pah[3], pal[3]);
            #pragma unroll
            for (int dd = 0; dd < 4; dd++) {
                uint32_t va = stb + (t * 16 + (lane & 7) + ((lane >> 3) & 1) * 8) * AT_ROWB
                            + (dd * 16 + (lane >> 4) * 8) * 2;
                uint32_t vh[4], vl[4];
                ldmx4t(va + AT_VH, vh[0], vh[1], vh[2], vh[3]);
                ldmx4t(va + AT_VL, vl[0], vl[1], vl[2], vl[3]);
                mma16816(O[dd*2+0], pah, &vh[0]); mma16816(O[dd*2+1], pah, &vh[2]);
                mma16816(O[dd*2+0], pah, &vl[0]); mma16816(O[dd*2+1], pah, &vl[2]);
                mma16816(O[dd*2+0], pal, &vh[0]); mma16816(O[dd*2+1], pal, &vh[2]);
            }
        }
    }

    float i0 = 1.f / l0, i1 = 1.f / l1;
    int tok0 = b * T_SEQ + r0, tok1 = b * T_SEQ + r1;
    #pragma unroll
    for (int j = 0; j < 8; j++) {
        int d = hh * 64 + j * 8 + ((lane & 3) << 1);
        size_t idx0 = (size_t)tok0 * D_MODEL + d;
        size_t idx1 = (size_t)tok1 * D_MODEL + d;
        float v00 = O[j][0] * i0, v01 = O[j][1] * i0;
        float v10 = O[j][2] * i1, v11 = O[j][3] * i1;
        outF[idx0] = v00; outF[idx0 + 1] = v01;
        outF[idx1] = v10; outF[idx1 + 1] = v11;
        __nv_bfloat16 hh0, ll0, hh1, ll1;
        splt(v00, hh0, ll0); splt(v01, hh1, ll1);
        outH[idx0] = hh0; outH[idx0 + 1] = hh1;
        outL[idx0] = ll0; outL[idx0 + 1] = ll1;
        splt(v10, hh0, ll0); splt(v11, hh1, ll1);
        outH[idx1] = hh0; outH[idx1 + 1] = hh1;
        outL[idx1] = ll0; outL[idx1 + 1] = ll1;
        if (d16) {
            d16[idx0]     = __float2half_rn(nIn[idx0]     - v00);
            d16[idx0 + 1] = __float2half_rn(nIn[idx0 + 1] - v01);
            d16[idx1]     = __float2half_rn(nIn[idx1]     - v10);
            d16[idx1 + 1] = __float2half_rn(nIn[idx1 + 1] - v11);
        }
    }
}

// ---------------- driver ----------------------------------------------------
#define GSMEM64  (2 * (2 * 128 * SROW + 2 * 64 * SROW))
#define GH128    (2 * (128 * SROW + 2 * 128 * SROW))
#define GH64     (2 * (128 * SROW + 2 * 64 * SROW))

extern "C" void kernel_launch(void* const* d_in, const int* in_sizes, int n_in,
                              void* d_out, int out_size) {
    const int*   x      = (const int*)  d_in[0];
    const float* embed  = (const float*)d_in[1];
    const float* pos    = (const float*)d_in[2];
    const float* Wqkv   = (const float*)d_in[3];
    const float* bqkv   = (const float*)d_in[4];
    const float* Wo     = (const float*)d_in[5];
    const float* bo     = (const float*)d_in[6];
    const float* Wg     = (const float*)d_in[7];
    const float* bg     = (const float*)d_in[8];
    const float* ln1_g  = (const float*)d_in[9];
    const float* ln1_b  = (const float*)d_in[10];
    const float* W1     = (const float*)d_in[11];
    const float* b1     = (const float*)d_in[12];
    const float* W2     = (const float*)d_in[13];
    const float* b2     = (const float*)d_in[14];
    const float* ln2_g  = (const float*)d_in[15];
    const float* ln2_b  = (const float*)d_in[16];
    const float* lnf_g  = (const float*)d_in[17];
    const float* lnf_b  = (const float*)d_in[18];
    float* out = (float*)d_out;

    cudaFuncSetAttribute(gemm_tc<64>,  cudaFuncAttributeMaxDynamicSharedMemorySize, GSMEM64);
    cudaFuncSetAttribute(gemm_h<128>,  cudaFuncAttributeMaxDynamicSharedMemorySize, GH128);
    cudaFuncSetAttribute(gemm_h<64>,   cudaFuncAttributeMaxDynamicSharedMemorySize, GH64);
    cudaFuncSetAttribute(gemm_f16,     cudaFuncAttributeMaxDynamicSharedMemorySize, FSMEM);
    cudaFuncSetAttribute(attn_mma,     cudaFuncAttributeMaxDynamicSharedMemorySize, AT_SMEM);

    float *h, *n, *pred, *corr;
    cudaGetSymbolAddress((void**)&h,    g_h);
    cudaGetSymbolAddress((void**)&n,    g_n);
    cudaGetSymbolAddress((void**)&pred, g_pred);
    cudaGetSymbolAddress((void**)&corr, g_corr);
    __nv_bfloat16 *ah, *al, *ph, *pl, *ch, *cl, *qh, *ql;
    cudaGetSymbolAddress((void**)&ah, g_ah);
    cudaGetSymbolAddress((void**)&al, g_al);
    cudaGetSymbolAddress((void**)&ph, g_ph);
    cudaGetSymbolAddress((void**)&pl, g_pl);
    cudaGetSymbolAddress((void**)&ch, g_ch);
    cudaGetSymbolAddress((void**)&cl, g_cl);
    cudaGetSymbolAddress((void**)&qh, g_qkvh);
    cudaGetSymbolAddress((void**)&ql, g_qkvl);
    __half *a16, *d16, *f16, *embf;
    cudaGetSymbolAddress((void**)&a16,  g_a16);
    cudaGetSymbolAddress((void**)&d16,  g_d16);
    cudaGetSymbolAddress((void**)&f16,  g_f16);
    cudaGetSymbolAddress((void**)&embf, g_embf);
    __half *wqkv_h, *wqkv_l, *w1_h, *w1_l, *w2_h, *w2_l;
    __nv_bfloat16 *wo_h, *wo_l, *wg_h, *wg_l;
    cudaGetSymbolAddress((void**)&wqkv_h, g_wqkv_h); cudaGetSymbolAddress((void**)&wqkv_l, g_wqkv_l);
    cudaGetSymbolAddress((void**)&wo_h,   g_wo_h);   cudaGetSymbolAddress((void**)&wo_l,   g_wo_l);
    cudaGetSymbolAddress((void**)&wg_h,   g_wg_h);   cudaGetSymbolAddress((void**)&wg_l,   g_wg_l);
    cudaGetSymbolAddress((void**)&w1_h,   g_w1_h);   cudaGetSymbolAddress((void**)&w1_l,   g_w1_l);
    cudaGetSymbolAddress((void**)&w2_h,   g_w2_h);   cudaGetSymbolAddress((void**)&w2_l,   g_w2_l);

    split_all<<<(int)((Q5 + 255) / 256), 256>>>(
        (const float4*)Wqkv, (const float4*)Wo, (const float4*)Wg,
        (const float4*)W1, (const float4*)W2, (const float4*)embed,
        (uint2*)wqkv_h, (uint2*)wqkv_l, (uint2*)wo_h, (uint2*)wo_l,
        (uint2*)wg_h, (uint2*)wg_l, (uint2*)w1_h, (uint2*)w1_l,
        (uint2*)w2_h, (uint2*)w2_l, (uint2*)embf);

    dim3 attng(T_SEQ / 64, 16, 2);

    embed_kernel<<<BT, 256>>>(x, embed, pos, h);

    for (int l = 0; l < NLAYER; l++) {
        // n1 = ln(h): fp32 (for diff) + fp16 (qkv1 A)
        ln_kernel<<<BT, 256>>>(h, ln1_g + l * D_MODEL, ln1_b + l * D_MODEL, n, a16);
        // qkv1 (fp16 2-mma), out bf16 hi/lo
        gemm_h<128><<<dim3(3072/128, BT/128), 256, GH128>>>(
            a16, wqkv_h + (size_t)(l*2+0)*3072*D_MODEL, wqkv_l + (size_t)(l*2+0)*3072*D_MODEL,
            bqkv + (l*2+0)*3072, nullptr,
            nullptr, qh, ql, nullptr, BT, 3072, D_MODEL, 0);
        // attn1 -> pred fp32 + bf16 split; diff = n - pred as fp16
        attn_mma<<<attng, 128, AT_SMEM>>>(qh, ql, n, pred, ph, pl, d16);
        // qkv2 (fp16 2-mma)
        gemm_h<128><<<dim3(3072/128, BT/128), 256, GH128>>>(
            d16, wqkv_h + (size_t)(l*2+1)*3072*D_MODEL, wqkv_l + (size_t)(l*2+1)*3072*D_MODEL,
            bqkv + (l*2+1)*3072, nullptr,
            nullptr, qh, ql, nullptr, BT, 3072, D_MODEL, 0);
        // attn2 -> corr
        attn_mma<<<attng, 128, AT_SMEM>>>(qh, ql, nullptr, corr, ch, cl, nullptr);
        // gated = pred + sigmoid([pred|corr]@Wg^T + bg)*corr  (bf16 3-mma)
        gemm_tc<64><<<dim3(D_MODEL/64, BT/128), 256, GSMEM64>>>(
            ph, pl, ch, cl, D_MODEL, D_MODEL, D_MODEL,
            wg_h + (size_t)l*D_MODEL*2*D_MODEL, wg_l + (size_t)l*D_MODEL*2*D_MODEL,
            bg + l*D_MODEL, pred, corr,
            nullptr, ah, al, BT, D_MODEL, 2*D_MODEL, 3);
        // h += gated @ Wo^T + bo  (bf16 3-mma)
        gemm_tc<64><<<dim3(D_MODEL/64, BT/128), 256, GSMEM64>>>(
            ah, al, nullptr, nullptr, 1 << 30, D_MODEL, 0,
            wo_h + (size_t)l*D_MODEL*D_MODEL, wo_l + (size_t)l*D_MODEL*D_MODEL,
            bo + l*D_MODEL, h, nullptr,
            h, nullptr, nullptr, BT, D_MODEL, D_MODEL, 1);
        // FF (fp16 2-mma both)
        ln_kernel<<<BT, 256>>>(h, ln2_g + l * D_MODEL, ln2_b + l * D_MODEL, nullptr, a16);
        gemm_h<128><<<dim3(FF_DIM/128, BT/128), 256, GH128>>>(
            a16, w1_h + (size_t)l*FF_DIM*D_MODEL, w1_l + (size_t)l*FF_DIM*D_MODEL,
            b1 + l*FF_DIM, nullptr,
            nullptr, nullptr, nullptr, f16, BT, FF_DIM, D_MODEL, 2);
        gemm_h<64><<<dim3(D_MODEL/64, BT/128), 256, GH64>>>(
            f16, w2_h + (size_t)l*D_MODEL*FF_DIM, w2_l + (size_t)l*D_MODEL*FF_DIM,
            b2 + l*D_MODEL, h,
            h, nullptr, nullptr, nullptr, BT, D_MODEL, FF_DIM, 1);
    }

    ln_kernel<<<BT, 256>>>(h, lnf_g, lnf_b, nullptr, a16);
    gemm_f16<<<dim3(VOCAB/64, BT/128), 256, FSMEM>>>(
        a16, embf, out, BT, VOCAB, D_MODEL);
}

// round 9
// speedup vs baseline: 4.0376x; 1.0597x over previous
#include <cuda_runtime.h>
#include <cuda_bf16.h>
#include <cuda_fp16.h>
#include <stdint.h>
#include <math.h>

#define T_SEQ   1024
#define D_MODEL 1024
#define NLAYER  4
#define FF_DIM  4096
#define VOCAB   32000
#define BT      2048
#define ATT_SCALE 0.125f

// ---------------- fp32 scratch ----------------------------------------------
__device__ float g_h   [BT * D_MODEL];
__device__ float g_n   [BT * D_MODEL];
__device__ float g_pred[BT * D_MODEL];
__device__ float g_corr[BT * D_MODEL];

// ---------------- activation scratch ----------------------------------------
__device__ __align__(16) __nv_bfloat16 g_qkvh[BT * 3 * D_MODEL];
__device__ __align__(16) __nv_bfloat16 g_qkvl[BT * 3 * D_MODEL];
__device__ __align__(16) __half g_a16[BT * D_MODEL];
__device__ __align__(16) __half g_d16[BT * D_MODEL];
__device__ __align__(16) __half g_p16[BT * D_MODEL];
__device__ __align__(16) __half g_c16[BT * D_MODEL];
__device__ __align__(16) __half g_g16[BT * D_MODEL];
__device__ __align__(16) __half g_f16[BT * FF_DIM];

// ---------------- weights (all fp16 hi/lo; embed fp16 single) ----------------
#define SZ_WQKV (NLAYER * 2 * 3 * D_MODEL * D_MODEL)
#define SZ_WO   (NLAYER * D_MODEL * D_MODEL)
#define SZ_WG   (NLAYER * D_MODEL * 2 * D_MODEL)
#define SZ_W1   (NLAYER * FF_DIM * D_MODEL)
#define SZ_W2   (NLAYER * D_MODEL * FF_DIM)
#define SZ_EMB  (VOCAB * D_MODEL)
__device__ __align__(16) __half g_wqkv_h[SZ_WQKV], g_wqkv_l[SZ_WQKV];
__device__ __align__(16) __half g_wo_h  [SZ_WO],   g_wo_l  [SZ_WO];
__device__ __align__(16) __half g_wg_h  [SZ_WG],   g_wg_l  [SZ_WG];
__device__ __align__(16) __half g_w1_h  [SZ_W1],   g_w1_l  [SZ_W1];
__device__ __align__(16) __half g_w2_h  [SZ_W2],   g_w2_l  [SZ_W2];
__device__ __align__(16) __half g_embf  [SZ_EMB];

// ---------------- helpers ----------------------------------------------------
__device__ __forceinline__ void splt(float x, __nv_bfloat16& h, __nv_bfloat16& l) {
    h = __float2bfloat16_rn(x);
    l = __float2bfloat16_rn(x - __bfloat162float(h));
}
__device__ __forceinline__ void pack_hl(float x, float y, uint32_t& h, uint32_t& l) {
    __nv_bfloat16 h0 = __float2bfloat16_rn(x), h1 = __float2bfloat16_rn(y);
    __nv_bfloat16 l0 = __float2bfloat16_rn(x - __bfloat162float(h0));
    __nv_bfloat16 l1 = __float2bfloat16_rn(y - __bfloat162float(h1));
    h = (uint32_t)__bfloat16_as_ushort(h0) | ((uint32_t)__bfloat16_as_ushort(h1) << 16);
    l = (uint32_t)__bfloat16_as_ushort(l0) | ((uint32_t)__bfloat16_as_ushort(l1) << 16);
}
__device__ __forceinline__ uint32_t smem_u32(const void* p) {
    uint32_t a;
    asm("{ .reg .u64 t; cvta.to.shared.u64 t, %1; cvt.u32.u64 %0, t; }" : "=r"(a) : "l"(p));
    return a;
}
__device__ __forceinline__ void cp16(uint32_t s, const void* g) {
    asm volatile("cp.async.cg.shared.global [%0], [%1], 16;" :: "r"(s), "l"(g));
}
#define CP_COMMIT() asm volatile("cp.async.commit_group;" ::: "memory")
#define CP_WAIT0()  asm volatile("cp.async.wait_group 0;" ::: "memory")

__device__ __forceinline__ void ldmx4(uint32_t a, uint32_t& r0, uint32_t& r1,
                                      uint32_t& r2, uint32_t& r3) {
    asm volatile("ldmatrix.sync.aligned.m8n8.x4.shared.b16 {%0,%1,%2,%3}, [%4];"
                 : "=r"(r0), "=r"(r1), "=r"(r2), "=r"(r3) : "r"(a));
}
__device__ __forceinline__ void ldmx4t(uint32_t a, uint32_t& r0, uint32_t& r1,
                                       uint32_t& r2, uint32_t& r3) {
    asm volatile("ldmatrix.sync.aligned.m8n8.x4.trans.shared.b16 {%0,%1,%2,%3}, [%4];"
                 : "=r"(r0), "=r"(r1), "=r"(r2), "=r"(r3) : "r"(a));
}
__device__ __forceinline__ void mma16816(float* d, const uint32_t* a, const uint32_t* b) {
    asm volatile("mma.sync.aligned.m16n8k16.row.col.f32.bf16.bf16.f32 "
                 "{%0,%1,%2,%3}, {%4,%5,%6,%7}, {%8,%9}, {%0,%1,%2,%3};"
                 : "+f"(d[0]), "+f"(d[1]), "+f"(d[2]), "+f"(d[3])
                 : "r"(a[0]), "r"(a[1]), "r"(a[2]), "r"(a[3]), "r"(b[0]), "r"(b[1]));
}
__device__ __forceinline__ void mma16816h(float* d, const uint32_t* a, const uint32_t* b) {
    asm volatile("mma.sync.aligned.m16n8k16.row.col.f32.f16.f16.f32 "
                 "{%0,%1,%2,%3}, {%4,%5,%6,%7}, {%8,%9}, {%0,%1,%2,%3};"
                 : "+f"(d[0]), "+f"(d[1]), "+f"(d[2]), "+f"(d[3])
                 : "r"(a[0]), "r"(a[1]), "r"(a[2]), "r"(a[3]), "r"(b[0]), "r"(b[1]));
}

// ---------------- one-shot weight split (fp16 hi/lo; embed fp16) -------------
#define Q0 (SZ_WQKV/4)
#define Q1 (Q0 + SZ_WO/4)
#define Q2 (Q1 + SZ_WG/4)
#define Q3 (Q2 + SZ_W1/4)
#define Q4 (Q3 + SZ_W2/4)
#define Q5 (Q4 + SZ_EMB/4)
__global__ void split_all(
    const float4* w0, const float4* w1, const float4* w2,
    const float4* w3, const float4* w4, const float4* w5,
    uint2* h0, uint2* l0, uint2* h1, uint2* l1, uint2* h2, uint2* l2,
    uint2* h3, uint2* l3, uint2* h4, uint2* l4, uint2* f5)
{
    long i = (long)blockIdx.x * 256 + threadIdx.x;
    if (i >= Q5) return;
    const float4* src; uint2 *hi, *lo; long off; int single;
    if      (i < Q0) { src = w0; hi = h0; lo = l0; off = i;      single = 0; }
    else if (i < Q1) { src = w1; hi = h1; lo = l1; off = i - Q0; single = 0; }
    else if (i < Q2) { src = w2; hi = h2; lo = l2; off = i - Q1; single = 0; }
    else if (i < Q3) { src = w3; hi = h3; lo = l3; off = i - Q2; single = 0; }
    else if (i < Q4) { src = w4; hi = h4; lo = l4; off = i - Q3; single = 0; }
    else             { src = w5; hi = f5; lo = f5; off = i - Q4; single = 1; }
    float4 v = src[off];
    float vv[4] = {v.x, v.y, v.z, v.w};
    uint32_t Hw[2] = {0, 0}, Lw[2] = {0, 0};
    #pragma unroll
    for (int k = 0; k < 4; k++) {
        __half a = __float2half_rn(vv[k]);
        Hw[k >> 1] |= (uint32_t)__half_as_ushort(a) << ((k & 1) * 16);
        if (!single) {
            __half b = __float2half_rn(vv[k] - __half2float(a));
            Lw[k >> 1] |= (uint32_t)__half_as_ushort(b) << ((k & 1) * 16);
        }
    }
    hi[off] = make_uint2(Hw[0], Hw[1]);
    if (!single) lo[off] = make_uint2(Lw[0], Lw[1]);
}

#define SROW 80

// ---------------- fp16 2-mma GEMM (all layer GEMMs), single-sync -------------
// Dual-A concat at kSplit. epi: 0 none, 1 +res, 2 gelu, 3 gated.
template<int BN>
__global__ __launch_bounds__(256, 2) void gemm_h(
    const __half* __restrict__ A16, const __half* __restrict__ A16b,
    int kSplit, int lda1, int lda2,
    const __half* __restrict__ Wh, const __half* __restrict__ Wl,
    const float* __restrict__ bias, const float* __restrict__ res,
    const float* __restrict__ corr,
    float* __restrict__ Cf, __nv_bfloat16* __restrict__ Ch, __nv_bfloat16* __restrict__ Cl,
    __half* __restrict__ C16,
    int M, int N, int K, int epi)
{
    constexpr int ASZ  = 128 * SROW;
    constexpr int BSZ  = BN * SROW;
    constexpr int BOFF = ASZ;
    constexpr int STGB = ASZ + 2 * BSZ;
    constexpr int NG   = BN / 32;
    constexpr int NB16 = 128 * 4 + BN * 8;
    extern __shared__ char smem[];
    uint32_t sb = smem_u32(smem);
    int tid = threadIdx.x, lane = tid & 31, w = tid >> 5;
    int wm = w & 3, wn = w >> 2;
    int bm = blockIdx.y * 128, bn = blockIdx.x * BN;

    float acc[2][NG * 2][4];
    #pragma unroll
    for (int i = 0; i < 2; i++)
        #pragma unroll
        for (int j = 0; j < NG * 2; j++)
            #pragma unroll
            for (int e = 0; e < 4; e++) acc[i][j][e] = 0.f;

    int nk = K / 32;

    auto load_chunk = [&](int kc, uint32_t s) {
        int kb = kc * 32;
        const __half* sA; int lda, koff;
        if (kb < kSplit) { sA = A16;  lda = lda1; koff = kb; }
        else             { sA = A16b; lda = lda2; koff = kb - kSplit; }
        #pragma unroll
        for (int it = 0; it < NB16 / 256; it++) {
            int i = tid + it * 256;
            if (i < 512) {
                int row = i >> 2, c = i & 3;
                size_t go = (size_t)(bm + row) * lda + koff + c * 8;
                cp16(s + row * SROW + c * 16, sA + go);
            } else {
                int ii = i - 512;
                int hf = ii >= BN * 4;
                int ww = ii & (BN * 4 - 1);
                int row = ww >> 2, c = ww & 3;
                size_t go = (size_t)(bn + row) * K + kb + c * 8;
                cp16(s + BOFF + (hf ? BSZ : 0) + row * SROW + c * 16, (hf ? Wl : Wh) + go);
            }
        }
    };

    load_chunk(0, sb);
    CP_COMMIT();

    for (int kc = 0; kc < nk; kc++) {
        CP_WAIT0();
        __syncthreads();
        if (kc + 1 < nk) { load_chunk(kc + 1, sb + ((kc + 1) & 1) * STGB); CP_COMMIT(); }

        uint32_t s = sb + (kc & 1) * STGB;
        #pragma unroll
        for (int t = 0; t < 2; t++) {
            uint32_t arow = wm * 32 + (lane & 15);
            uint32_t ak = (t * 16 + (lane >> 4) * 8) * 2;
            uint32_t ar[2][4];
            #pragma unroll
            for (int mg = 0; mg < 2; mg++) {
                uint32_t aoff = (arow + mg * 16) * SROW + ak;
                ldmx4(s + aoff, ar[mg][0], ar[mg][1], ar[mg][2], ar[mg][3]);
            }
            #pragma unroll
            for (int ng = 0; ng < NG; ng++) {
                uint32_t brow = wn * (BN / 2) + ng * 16 + (lane & 7) + ((lane >> 4) << 3);
                uint32_t boff = brow * SROW + (t * 16 + ((lane >> 3) & 1) * 8) * 2;
                uint32_t bh[4], bl[4];
                ldmx4(s + BOFF + boff,       bh[0], bh[1], bh[2], bh[3]);
                ldmx4(s + BOFF + BSZ + boff, bl[0], bl[1], bl[2], bl[3]);
                #pragma unroll
                for (int mg = 0; mg < 2; mg++) {
                    mma16816h(acc[mg][ng*2+0], ar[mg], &bh[0]);
                    mma16816h(acc[mg][ng*2+1], ar[mg], &bh[2]);
                    mma16816h(acc[mg][ng*2+0], ar[mg], &bl[0]);
                    mma16816h(acc[mg][ng*2+1], ar[mg], &bl[2]);
                }
            }
        }
    }

    #pragma unroll
    for (int mg = 0; mg < 2; mg++) {
        #pragma unroll
        for (int j = 0; j < NG * 2; j++) {
            int m0 = bm + wm * 32 + mg * 16 + (lane >> 2);
            int n0 = bn + wn * (BN / 2) + j * 8 + (lane & 3) * 2;
            #pragma unroll
            for (int e = 0; e < 4; e++) {
                int m = m0 + (e >> 1) * 8;
                int n = n0 + (e & 1);
                size_t idx = (size_t)m * N + n;
                float v = acc[mg][j][e];
                if (bias) v += bias[n];
                if (epi == 1)      v += res[idx];
                else if (epi == 2) v = 0.5f * v * (1.f + erff(v * 0.70710678118f));
                else if (epi == 3) v = res[idx] + corr[idx] / (1.f + __expf(-v));
                if (Cf) Cf[idx] = v;
                if (Ch) {
                    __nv_bfloat16 hh, ll;
                    splt(v, hh, ll);
                    Ch[idx] = hh; Cl[idx] = ll;
                }
                if (C16) C16[idx] = __float2half_rn(v);
            }
        }
    }
}

// ---------------- logits GEMM (fp16 1-mma, 128x64, KC=64, single-sync) -------
#define FROW  144
#define FB    18432
#define FSTG  27648
#define FSMEM (2 * FSTG)

__global__ __launch_bounds__(256, 3) void gemm_f16(
    const __half* __restrict__ Ah, const __half* __restrict__ Wh,
    float* __restrict__ Cf, int M, int N, int K)
{
    extern __shared__ char smem[];
    uint32_t sb = smem_u32(smem);
    int tid = threadIdx.x, lane = tid & 31, w = tid >> 5;
    int wm = w & 3, wn = w >> 2;
    int bm = blockIdx.y * 128, bn = blockIdx.x * 64;

    float acc[2][4][4];
    #pragma unroll
    for (int i = 0; i < 2; i++)
        #pragma unroll
        for (int j = 0; j < 4; j++)
            #pragma unroll
            for (int e = 0; e < 4; e++) acc[i][j][e] = 0.f;

    int nk = K / 64;

    auto load_chunk = [&](int kc, uint32_t s) {
        int kb = kc * 64;
        #pragma unroll
        for (int it = 0; it < 6; it++) {
            int i = tid + it * 256;
            if (i < 1024) {
                int row = i >> 3, c = i & 7;
                size_t go = (size_t)(bm + row) * K + kb + c * 8;
                cp16(s + row * FROW + c * 16, Ah + go);
            } else {
                int ii = i - 1024;
                int row = ii >> 3, c = ii & 7;
                size_t go = (size_t)(bn + row) * K + kb + c * 8;
                cp16(s + FB + row * FROW + c * 16, Wh + go);
            }
        }
    };

    load_chunk(0, sb);
    CP_COMMIT();

    for (int kc = 0; kc < nk; kc++) {
        CP_WAIT0();
        __syncthreads();
        if (kc + 1 < nk) { load_chunk(kc + 1, sb + ((kc + 1) & 1) * FSTG); CP_COMMIT(); }

        uint32_t s = sb + (kc & 1) * FSTG;
        #pragma unroll
        for (int t = 0; t < 4; t++) {
            uint32_t arow = wm * 32 + (lane & 15);
            uint32_t ak = (t * 16 + (lane >> 4) * 8) * 2;
            uint32_t ahr[2][4];
            #pragma unroll
            for (int mg = 0; mg < 2; mg++) {
                uint32_t aoff = (arow + mg * 16) * FROW + ak;
                ldmx4(s + aoff, ahr[mg][0], ahr[mg][1], ahr[mg][2], ahr[mg][3]);
            }
            #pragma unroll
            for (int ng = 0; ng < 2; ng++) {
                uint32_t brow = wn * 32 + ng * 16 + (lane & 7) + ((lane >> 4) << 3);
                uint32_t boff = brow * FROW + (t * 16 + ((lane >> 3) & 1) * 8) * 2;
                uint32_t bw[4];
                ldmx4(s + FB + boff, bw[0], bw[1], bw[2], bw[3]);
                #pragma unroll
                for (int mg = 0; mg < 2; mg++) {
                    mma16816h(acc[mg][ng*2+0], ahr[mg], &bw[0]);
                    mma16816h(acc[mg][ng*2+1], ahr[mg], &bw[2]);
                }
            }
        }
    }

    #pragma unroll
    for (int mg = 0; mg < 2; mg++) {
        #pragma unroll
        for (int j = 0; j < 4; j++) {
            int m0 = bm + wm * 32 + mg * 16 + (lane >> 2);
            int n0 = bn + wn * 32 + j * 8 + (lane & 3) * 2;
            #pragma unroll
            for (int e = 0; e < 4; e++) {
                int m = m0 + (e >> 1) * 8;
                int n = n0 + (e & 1);
                Cf[(size_t)m * N + n] = acc[mg][j][e];
            }
        }
    }
}

// ---------------- embedding ------------------------------------------------
__global__ void embed_kernel(const int* __restrict__ x, const float* __restrict__ emb,
                             const float* __restrict__ pos, float* __restrict__ h) {
    int row = blockIdx.x;
    int t   = row & (T_SEQ - 1);
    int tok = x[row];
    const float* e = emb + (size_t)tok * D_MODEL;
    const float* p = pos + (size_t)t   * D_MODEL;
    float* o = h + (size_t)row * D_MODEL;
    for (int d = threadIdx.x; d < D_MODEL; d += blockDim.x)
        o[d] = e[d] + p[d];
}

// ---------------- layernorm -------------------------------------------------
__global__ void ln_kernel(const float* __restrict__ in, const float* __restrict__ g,
                          const float* __restrict__ b, float* __restrict__ of,
                          __half* __restrict__ o16) {
    int row = blockIdx.x;
    const float* x = in + (size_t)row * D_MODEL;
    int tid = threadIdx.x;
    float s = 0.f, ss = 0.f;
    for (int d = tid; d < D_MODEL; d += 256) { float v = x[d]; s += v; ss += v * v; }
    #pragma unroll
    for (int off = 16; off; off >>= 1) {
        s  += __shfl_xor_sync(0xffffffffu, s,  off);
        ss += __shfl_xor_sync(0xffffffffu, ss, off);
    }
    __shared__ float shs[8], shss[8];
    if ((tid & 31) == 0) { shs[tid >> 5] = s; shss[tid >> 5] = ss; }
    __syncthreads();
    float tots = 0.f, totss = 0.f;
    #pragma unroll
    for (int i = 0; i < 8; i++) { tots += shs[i]; totss += shss[i]; }
    float mean = tots * (1.f / D_MODEL);
    float var  = totss * (1.f / D_MODEL) - mean * mean;
    float rstd = rsqrtf(var + 1e-5f);
    for (int d = tid; d < D_MODEL; d += 256) {
        float v = (x[d] - mean) * rstd * g[d] + b[d];
        size_t idx = (size_t)row * D_MODEL + d;
        if (of) of[idx] = v;
        o16[idx] = __float2half_rn(v);
    }
}

// ---------------- HMMA flash attention (fp16/fp32 outputs) -------------------
#define AT_ROWB   144
#define AT_QH     0
#define AT_QL     9216
#define AT_STAGE0 18432
#define AT_STGSZ  36864
#define AT_KH     0
#define AT_KL     9216
#define AT_VH     18432
#define AT_VL     27648
#define AT_SMEM   (18432 + 2 * 36864)

__global__ __launch_bounds__(128, 2) void attn_mma(
    const __nv_bfloat16* __restrict__ qkvh, const __nv_bfloat16* __restrict__ qkvl,
    const float* __restrict__ nIn,
    float* __restrict__ outF, __half* __restrict__ o16, __half* __restrict__ d16)
{
    extern __shared__ char sm[];
    uint32_t sb = smem_u32(sm);
    int qt = blockIdx.x, hh = blockIdx.y, b = blockIdx.z;
    int tid = threadIdx.x, lane = tid & 31, wq = tid >> 5;
    int qb = wq * 16;

    #pragma unroll
    for (int it = 0; it < 8; it++) {
        int i = tid + it * 128;
        int tensor = i >> 9, ww = i & 511, row = ww >> 3, c = ww & 7;
        size_t ge = (size_t)(b * T_SEQ + qt * 64 + row) * 3072 + hh * 64 + c * 8;
        const __nv_bfloat16* src = tensor ? qkvl : qkvh;
        uint32_t dst = sb + (tensor ? AT_QL : AT_QH) + row * AT_ROWB + c * 16;
        cp16(dst, src + ge);
    }

    auto load_kv = [&](int kt, int stage) {
        uint32_t stb = sb + AT_STAGE0 + stage * AT_STGSZ;
        #pragma unroll
        for (int it = 0; it < 16; it++) {
            int i = tid + it * 128;
            int tensor = i >> 9, ww = i & 511, row = ww >> 3, c = ww & 7;
            int kvoff = (tensor >= 2) ? 2048 : 1024;
            size_t ge = (size_t)(b * T_SEQ + kt * 64 + row) * 3072 + kvoff + hh * 64 + c * 8;
            const __nv_bfloat16* src = (tensor & 1) ? qkvl : qkvh;
            uint32_t toff = (tensor == 0) ? AT_KH : (tensor == 1) ? AT_KL
                          : (tensor == 2) ? AT_VH : AT_VL;
            cp16(stb + toff + row * AT_ROWB + c * 16, src + ge);
        }
    };
    load_kv(0, 0);
    CP_COMMIT();

    float O[8][4];
    #pragma unroll
    for (int j = 0; j < 8; j++)
        #pragma unroll
        for (int e = 0; e < 4; e++) O[j][e] = 0.f;
    float m0 = -1e30f, m1 = -1e30f, l0 = 0.f, l1 = 0.f;

    int r0 = qt * 64 + qb + (lane >> 2);
    int r1 = r0 + 8;

    for (int kt = 0; kt <= qt; kt++) {
        CP_WAIT0();
        __syncthreads();
        if (kt < qt) { load_kv(kt + 1, (kt + 1) & 1); CP_COMMIT(); }

        uint32_t stb = sb + AT_STAGE0 + (kt & 1) * AT_STGSZ;

        float S[8][4];
        #pragma unroll
        for (int j = 0; j < 8; j++)
            #pragma unroll
            for (int e = 0; e < 4; e++) S[j][e] = 0.f;

        #pragma unroll
        for (int t = 0; t < 4; t++) {
            uint32_t qa = sb + (qb + (lane & 15)) * AT_ROWB + (t * 16 + (lane >> 4) * 8) * 2;
            uint32_t qh[4], ql[4];
            ldmx4(qa + AT_QH, qh[0], qh[1], qh[2], qh[3]);
            ldmx4(qa + AT_QL, ql[0], ql[1], ql[2], ql[3]);
            #pragma unroll
            for (int jj = 0; jj < 4; jj++) {
                uint32_t ka = stb + (jj * 16 + (lane & 7) + ((lane >> 4) << 3)) * AT_ROWB
                            + (t * 16 + ((lane >> 3) & 1) * 8) * 2;
                uint32_t kh[4], kl[4];
                ldmx4(ka + AT_KH, kh[0], kh[1], kh[2], kh[3]);
                ldmx4(ka + AT_KL, kl[0], kl[1], kl[2], kl[3]);
                mma16816(S[jj*2+0], qh, &kh[0]); mma16816(S[jj*2+1], qh, &kh[2]);
                mma16816(S[jj*2+0], qh, &kl[0]); mma16816(S[jj*2+1], qh, &kl[2]);
                mma16816(S[jj*2+0], ql, &kh[0]); mma16816(S[jj*2+1], ql, &kh[2]);
            }
        }

        int cb = kt * 64 + ((lane & 3) << 1);
        float mx0 = -1e30f, mx1 = -1e30f;
        #pragma unroll
        for (int j = 0; j < 8; j++) {
            int c0 = cb + j * 8, c1 = c0 + 1;
            float v;
            v = (c0 <= r0) ? S[j][0] * ATT_SCALE : -1e30f; S[j][0] = v; mx0 = fmaxf(mx0, v);
            v = (c1 <= r0) ? S[j][1] * ATT_SCALE : -1e30f; S[j][1] = v; mx0 = fmaxf(mx0, v);
            v = (c0 <= r1) ? S[j][2] * ATT_SCALE : -1e30f; S[j][2] = v; mx1 = fmaxf(mx1, v);
            v = (c1 <= r1) ? S[j][3] * ATT_SCALE : -1e30f; S[j][3] = v; mx1 = fmaxf(mx1, v);
        }
        mx0 = fmaxf(mx0, __shfl_xor_sync(0xffffffffu, mx0, 1));
        mx0 = fmaxf(mx0, __shfl_xor_sync(0xffffffffu, mx0, 2));
        mx1 = fmaxf(mx1, __shfl_xor_sync(0xffffffffu, mx1, 1));
        mx1 = fmaxf(mx1, __shfl_xor_sync(0xffffffffu, mx1, 2));
        float mn0 = fmaxf(m0, mx0), mn1 = fmaxf(m1, mx1);
        float a0 = __expf(m0 - mn0), a1 = __expf(m1 - mn1);
        m0 = mn0; m1 = mn1;
        float s0 = 0.f, s1 = 0.f;
        #pragma unroll
        for (int j = 0; j < 8; j++) {
            S[j][0] = __expf(S[j][0] - m0); s0 += S[j][0];
            S[j][1] = __expf(S[j][1] - m0); s0 += S[j][1];
            S[j][2] = __expf(S[j][2] - m1); s1 += S[j][2];
            S[j][3] = __expf(S[j][3] - m1); s1 += S[j][3];
        }
        s0 += __shfl_xor_sync(0xffffffffu, s0, 1);
        s0 += __shfl_xor_sync(0xffffffffu, s0, 2);
        s1 += __shfl_xor_sync(0xffffffffu, s1, 1);
        s1 += __shfl_xor_sync(0xffffffffu, s1, 2);
        l0 = l0 * a0 + s0; l1 = l1 * a1 + s1;
        #pragma unroll
        for (int j = 0; j < 8; j++) {
            O[j][0] *= a0; O[j][1] *= a0; O[j][2] *= a1; O[j][3] *= a1;
        }

        #pragma unroll
        for (int t = 0; t < 4; t++) {
            uint32_t pah[4], pal[4];
            pack_hl(S[2*t  ][0], S[2*t  ][1], pah[0], pal[0]);
            pack_hl(S[2*t  ][2], S[2*t  ][3], pah[1], pal[1]);
            pack_hl(S[2*t+1][0], S[2*t+1][1], pah[2], pal[2]);
            pack_hl(S[2*t+1][2], S[2*t+1][3], pah[3], pal[3]);
            #pragma unroll
            for (int dd = 0; dd < 4; dd++) {
                uint32_t va = stb + (t * 16 + (lane & 7) + ((lane >> 3) & 1) * 8) * AT_ROWB
                            + (dd * 16 + (lane >> 4) * 8) * 2;
                uint32_t vh[4], vl[4];
                ldmx4t(va + AT_VH, vh[0], vh[1], vh[2], vh[3]);
                ldmx4t(va + AT_VL, vl[0], vl[1], vl[2], vl[3]);
                mma16816(O[dd*2+0], pah, &vh[0]); mma16816(O[dd*2+1], pah, &vh[2]);
                mma16816(O[dd*2+0], pah, &vl[0]); mma16816(O[dd*2+1], pah, &vl[2]);
                mma16816(O[dd*2+0], pal, &vh[0]); mma16816(O[dd*2+1], pal, &vh[2]);
            }
        }
    }

    float i0 = 1.f / l0, i1 = 1.f / l1;
    int tok0 = b * T_SEQ + r0, tok1 = b * T_SEQ + r1;
    #pragma unroll
    for (int j = 0; j < 8; j++) {
        int d = hh * 64 + j * 8 + ((lane & 3) << 1);
        size_t idx0 = (size_t)tok0 * D_MODEL + d;
        size_t idx1 = (size_t)tok1 * D_MODEL + d;
        float v00 = O[j][0] * i0, v01 = O[j][1] * i0;
        float v10 = O[j][2] * i1, v11 = O[j][3] * i1;
        outF[idx0] = v00; outF[idx0 + 1] = v01;
        outF[idx1] = v10; outF[idx1 + 1] = v11;
        o16[idx0]     = __float2half_rn(v00);
        o16[idx0 + 1] = __float2half_rn(v01);
        o16[idx1]     = __float2half_rn(v10);
        o16[idx1 + 1] = __float2half_rn(v11);
        if (d16) {
            d16[idx0]     = __float2half_rn(nIn[idx0]     - v00);
            d16[idx0 + 1] = __float2half_rn(nIn[idx0 + 1] - v01);
            d16[idx1]     = __float2half_rn(nIn[idx1]     - v10);
            d16[idx1 + 1] = __float2half_rn(nIn[idx1 + 1] - v11);
        }
    }
}

// ---------------- driver ----------------------------------------------------
#define GH128 (2 * (128 * SROW + 2 * 128 * SROW))
#define GH64  (2 * (128 * SROW + 2 * 64 * SROW))

extern "C" void kernel_launch(void* const* d_in, const int* in_sizes, int n_in,
                              void* d_out, int out_size) {
    const int*   x      = (const int*)  d_in[0];
    const float* embed  = (const float*)d_in[1];
    const float* pos    = (const float*)d_in[2];
    const float* Wqkv   = (const float*)d_in[3];
    const float* bqkv   = (const float*)d_in[4];
    const float* Wo     = (const float*)d_in[5];
    const float* bo     = (const float*)d_in[6];
    const float* Wg     = (const float*)d_in[7];
    const float* bg     = (const float*)d_in[8];
    const float* ln1_g  = (const float*)d_in[9];
    const float* ln1_b  = (const float*)d_in[10];
    const float* W1     = (const float*)d_in[11];
    const float* b1     = (const float*)d_in[12];
    const float* W2     = (const float*)d_in[13];
    const float* b2     = (const float*)d_in[14];
    const float* ln2_g  = (const float*)d_in[15];
    const float* ln2_b  = (const float*)d_in[16];
    const float* lnf_g  = (const float*)d_in[17];
    const float* lnf_b  = (const float*)d_in[18];
    float* out = (float*)d_out;

    cudaFuncSetAttribute(gemm_h<128>, cudaFuncAttributeMaxDynamicSharedMemorySize, GH128);
    cudaFuncSetAttribute(gemm_h<64>,  cudaFuncAttributeMaxDynamicSharedMemorySize, GH64);
    cudaFuncSetAttribute(gemm_f16,    cudaFuncAttributeMaxDynamicSharedMemorySize, FSMEM);
    cudaFuncSetAttribute(attn_mma,    cudaFuncAttributeMaxDynamicSharedMemorySize, AT_SMEM);

    float *h, *n, *pred, *corr;
    cudaGetSymbolAddress((void**)&h,    g_h);
    cudaGetSymbolAddress((void**)&n,    g_n);
    cudaGetSymbolAddress((void**)&pred, g_pred);
    cudaGetSymbolAddress((void**)&corr, g_corr);
    __nv_bfloat16 *qh, *ql;
    cudaGetSymbolAddress((void**)&qh, g_qkvh);
    cudaGetSymbolAddress((void**)&ql, g_qkvl);
    __half *a16, *d16, *p16, *c16, *gg16, *f16, *embf;
    cudaGetSymbolAddress((void**)&a16,  g_a16);
    cudaGetSymbolAddress((void**)&d16,  g_d16);
    cudaGetSymbolAddress((void**)&p16,  g_p16);
    cudaGetSymbolAddress((void**)&c16,  g_c16);
    cudaGetSymbolAddress((void**)&gg16, g_g16);
    cudaGetSymbolAddress((void**)&f16,  g_f16);
    cudaGetSymbolAddress((void**)&embf, g_embf);
    __half *wqkv_h, *wqkv_l, *wo_h, *wo_l, *wg_h, *wg_l, *w1_h, *w1_l, *w2_h, *w2_l;
    cudaGetSymbolAddress((void**)&wqkv_h, g_wqkv_h); cudaGetSymbolAddress((void**)&wqkv_l, g_wqkv_l);
    cudaGetSymbolAddress((void**)&wo_h,   g_wo_h);   cudaGetSymbolAddress((void**)&wo_l,   g_wo_l);
    cudaGetSymbolAddress((void**)&wg_h,   g_wg_h);   cudaGetSymbolAddress((void**)&wg_l,   g_wg_l);
    cudaGetSymbolAddress((void**)&w1_h,   g_w1_h);   cudaGetSymbolAddress((void**)&w1_l,   g_w1_l);
    cudaGetSymbolAddress((void**)&w2_h,   g_w2_h);   cudaGetSymbolAddress((void**)&w2_l,   g_w2_l);

    split_all<<<(int)((Q5 + 255) / 256), 256>>>(
        (const float4*)Wqkv, (const float4*)Wo, (const float4*)Wg,
        (const float4*)W1, (const float4*)W2, (const float4*)embed,
        (uint2*)wqkv_h, (uint2*)wqkv_l, (uint2*)wo_h, (uint2*)wo_l,
        (uint2*)wg_h, (uint2*)wg_l, (uint2*)w1_h, (uint2*)w1_l,
        (uint2*)w2_h, (uint2*)w2_l, (uint2*)embf);

    dim3 attng(T_SEQ / 64, 16, 2);

    embed_kernel<<<BT, 256>>>(x, embed, pos, h);

    for (int l = 0; l < NLAYER; l++) {
        // n1 = ln(h): fp32 n (for diff) + fp16 a16 (qkv1 A)
        ln_kernel<<<BT, 256>>>(h, ln1_g + l * D_MODEL, ln1_b + l * D_MODEL, n, a16);
        // qkv1 -> bf16 hi/lo (for attention)
        gemm_h<128><<<dim3(3072/128, BT/128), 256, GH128>>>(
            a16, nullptr, 1 << 30, D_MODEL, 0,
            wqkv_h + (size_t)(l*2+0)*3072*D_MODEL, wqkv_l + (size_t)(l*2+0)*3072*D_MODEL,
            bqkv + (l*2+0)*3072, nullptr, nullptr,
            nullptr, qh, ql, nullptr, BT, 3072, D_MODEL, 0);
        // attn1 -> pred fp32 + p16; diff = n - pred as d16
        attn_mma<<<attng, 128, AT_SMEM>>>(qh, ql, n, pred, p16, d16);
        // qkv2 (A = d16)
        gemm_h<128><<<dim3(3072/128, BT/128), 256, GH128>>>(
            d16, nullptr, 1 << 30, D_MODEL, 0,
            wqkv_h + (size_t)(l*2+1)*3072*D_MODEL, wqkv_l + (size_t)(l*2+1)*3072*D_MODEL,
            bqkv + (l*2+1)*3072, nullptr, nullptr,
            nullptr, qh, ql, nullptr, BT, 3072, D_MODEL, 0);
        // attn2 -> corr fp32 + c16
        attn_mma<<<attng, 128, AT_SMEM>>>(qh, ql, nullptr, corr, c16, nullptr);
        // gated = pred + sigmoid([p16|c16]@Wg^T + bg)*corr -> g16
        gemm_h<64><<<dim3(D_MODEL/64, BT/128), 256, GH64>>>(
            p16, c16, D_MODEL, D_MODEL, D_MODEL,
            wg_h + (size_t)l*D_MODEL*2*D_MODEL, wg_l + (size_t)l*D_MODEL*2*D_MODEL,
            bg + l*D_MODEL, pred, corr,
            nullptr, nullptr, nullptr, gg16, BT, D_MODEL, 2*D_MODEL, 3);
        // h += g16 @ Wo^T + bo
        gemm_h<64><<<dim3(D_MODEL/64, BT/128), 256, GH64>>>(
            gg16, nullptr, 1 << 30, D_MODEL, 0,
            wo_h + (size_t)l*D_MODEL*D_MODEL, wo_l + (size_t)l*D_MODEL*D_MODEL,
            bo + l*D_MODEL, h, nullptr,
            h, nullptr, nullptr, nullptr, BT, D_MODEL, D_MODEL, 1);
        // FF
        ln_kernel<<<BT, 256>>>(h, ln2_g + l * D_MODEL, ln2_b + l * D_MODEL, nullptr, a16);
        gemm_h<128><<<dim3(FF_DIM/128, BT/128), 256, GH128>>>(
            a16, nullptr, 1 << 30, D_MODEL, 0,
            w1_h + (size_t)l*FF_DIM*D_MODEL, w1_l + (size_t)l*FF_DIM*D_MODEL,
            b1 + l*FF_DIM, nullptr, nullptr,
            nullptr, nullptr, nullptr, f16, BT, FF_DIM, D_MODEL, 2);
        gemm_h<64><<<dim3(D_MODEL/64, BT/128), 256, GH64>>>(
            f16, nullptr, 1 << 30, FF_DIM, 0,
            w2_h + (size_t)l*D_MODEL*FF_DIM, w2_l + (size_t)l*D_MODEL*FF_DIM,
            b2 + l*D_MODEL, h, nullptr,
            h, nullptr, nullptr, nullptr, BT, D_MODEL, FF_DIM, 1);
    }

    ln_kernel<<<BT, 256>>>(h, lnf_g, lnf_b, nullptr, a16);
    gemm_f16<<<dim3(VOCAB/64, BT/128), 256, FSMEM>>>(
        a16, embf, out, BT, VOCAB, D_MODEL);
}